// round 7
// baseline (speedup 1.0000x reference)
#include <cuda_runtime.h>
#include <cstdint>

#define BB 64
#define FF 256
#define JJ 25
#define FILT 64
#define C1 128
#define NNODES (BB * FF * JJ)              // 409600
#define NE (NNODES * FILT)                 // 26214400
#define MTOT (BB * FF)                     // 16384
#define NW 384
#define KCI 1600
#define EPSV 1e-5f

// ---------------------------------------------------------------------------
// Scratch
// ---------------------------------------------------------------------------
__device__ float g_z2[NE];                 // GCN2 pre-BN output [node][c]
__device__ float g_y[MTOT * NW];           // conv1 GEMM output (pre shift-add)
__device__ float g_wwhi[NW * KCI];         // tap-split conv1 weights, tf32 hi
__device__ float g_wwlo[NW * KCI];         // tf32 lo residual
__device__ float g_w2hi[FILT * FILT];      // W2 split, [n_out][k_in]
__device__ float g_w2lo[FILT * FILT];
__device__ float g_w1out[BB * C1 * FF];    // conv1 raw output (pre-BN)
__device__ float g_v[BB * FILT * FF];      // conv2 raw output (pre-BN)
__device__ float g_p1[2 * 64 * 1024];
__device__ float g_p2[2 * 64 * 6400];
__device__ float g_pC1[2 * 128 * 256];
__device__ float g_pC2[2 * 64 * 256];
__device__ float g_scale1[64], g_shift1[64];
__device__ float g_scale2[64], g_shift2[64];
__device__ float g_scaleC1[128], g_shiftC1[128];
__device__ float g_scaleC2[64], g_shiftC2[64];

__device__ __forceinline__ float dinvf(int j) {
    return (j == 0 || j == JJ - 1) ? 0.70710678118654752f : 0.57735026918962576f;
}
__device__ __forceinline__ float lrelu(float v) { return v >= 0.f ? v : 0.2f * v; }
__device__ __forceinline__ float totf32(float x) {
    uint32_t u; asm("cvt.rna.tf32.f32 %0, %1;" : "=r"(u) : "f"(x));
    return __uint_as_float(u);
}

#define MMA_TF32(d, av, b0, b1) \
    asm volatile("mma.sync.aligned.m16n8k8.row.col.f32.tf32.tf32.f32 " \
        "{%0,%1,%2,%3}, {%4,%5,%6,%7}, {%8,%9}, {%0,%1,%2,%3};" \
        : "+f"((d)[0]), "+f"((d)[1]), "+f"((d)[2]), "+f"((d)[3]) \
        : "r"((av)[0]), "r"((av)[1]), "r"((av)[2]), "r"((av)[3]), \
          "r"(b0), "r"(b1))

__device__ __forceinline__ void cp_async16(uint32_t saddr, const void* g) {
    asm volatile("cp.async.cg.shared.global [%0], [%1], 16;" :: "r"(saddr), "l"(g) : "memory");
}

// ---------------------------------------------------------------------------
// K0a: W2 prep — split tf32, transposed: w2hi/lo[n*64+k] = split(W2[k*64+n])
// ---------------------------------------------------------------------------
__global__ __launch_bounds__(256) void w2prep(
    const float* __restrict__ W2, float* __restrict__ whi,
    float* __restrict__ wlo) {
    int i = blockIdx.x * 256 + threadIdx.x;       // < 4096
    int n = i >> 6, k = i & 63;
    float w = W2[k * 64 + n];
    float hi = totf32(w);
    whi[i] = hi;
    wlo[i] = totf32(w - hi);
}

// ---------------------------------------------------------------------------
// K0b: conv1 weight prep — split tf32: wwhi/wwlo[k*128+o][ci] from cw1[o][ci][k]
// ---------------------------------------------------------------------------
__global__ __launch_bounds__(256) void wprep(
    const float* __restrict__ cw1, float* __restrict__ whi,
    float* __restrict__ wlo) {
    int idx = blockIdx.x * 256 + threadIdx.x;     // < 614400 exactly
    int n = idx / KCI, ci = idx - n * KCI;
    int k = n >> 7, o = n & 127;
    float w = cw1[(size_t)o * 4800 + ci * 3 + k];
    float hi = totf32(w);
    whi[idx] = hi;
    wlo[idx] = totf32(w - hi);
}

// ---------------------------------------------------------------------------
// K1: GCN1 stats only (z1 recomputed, never stored). Block = 16 graphs.
// ---------------------------------------------------------------------------
__global__ __launch_bounds__(256) void gcn1_stats(
    const float* __restrict__ x, const float* __restrict__ W1,
    const float* __restrict__ b1, float* __restrict__ part) {
    __shared__ float xs[1200], W1s[192], b1s[64], ss[256], qq[256];
    int tid = threadIdx.x;
    if (tid < 192) W1s[tid] = W1[tid];
    if (tid < 64) b1s[tid] = b1[tid];
    int base = blockIdx.x * 1200;
    for (int i = tid; i < 1200; i += 256) xs[i] = x[base + i];
    __syncthreads();

    int c = tid & 63, sub = tid >> 6;
    float w0 = W1s[c], w1 = W1s[64 + c], w2 = W1s[128 + c], bb = b1s[c];
    float s = 0.f, q = 0.f;
    for (int it = 0; it < 100; it++) {
        int nl = it * 4 + sub;
        int j = nl % 25;
        const float* xb = xs + nl * 3;
        float acc = dinvf(j) * (xb[0] * w0 + xb[1] * w1 + xb[2] * w2);
        if (j > 0)      acc += dinvf(j - 1) * (xb[-3] * w0 + xb[-2] * w1 + xb[-1] * w2);
        if (j < JJ - 1) acc += dinvf(j + 1) * (xb[3] * w0 + xb[4] * w1 + xb[5] * w2);
        float z = dinvf(j) * acc + bb;
        s += z; q += z * z;
    }
    ss[tid] = s; qq[tid] = q;
    __syncthreads();
    if (tid < 64) {
        s = ss[tid] + ss[tid + 64] + ss[tid + 128] + ss[tid + 192];
        q = qq[tid] + qq[tid + 64] + qq[tid + 128] + qq[tid + 192];
        part[tid * 1024 + blockIdx.x] = s;
        part[65536 + tid * 1024 + blockIdx.x] = q;
    }
}

// ---------------------------------------------------------------------------
// BN finalize: part layout S at [c*R + r], Q at [C*R + c*R + r].
// ---------------------------------------------------------------------------
__global__ __launch_bounds__(256) void bn_final(
    const float* __restrict__ part, int R, int C,
    const float* __restrict__ g, const float* __restrict__ be, float invN,
    float* __restrict__ scale, float* __restrict__ shift) {
    int c = blockIdx.x, tid = threadIdx.x;
    __shared__ float ss[256], qq[256];
    const float* pS = part + (size_t)c * R;
    const float* pQ = part + (size_t)C * R + (size_t)c * R;
    float s = 0.f, q = 0.f;
    for (int r = tid; r < R; r += 256) { s += pS[r]; q += pQ[r]; }
    ss[tid] = s; qq[tid] = q;
    __syncthreads();
    for (int o = 128; o > 0; o >>= 1) {
        if (tid < o) { ss[tid] += ss[tid + o]; qq[tid] += qq[tid + o]; }
        __syncthreads();
    }
    if (tid == 0) {
        float m = ss[0] * invN;
        float var = qq[0] * invN - m * m;
        float rstd = rsqrtf(var + EPSV);
        float sc = g[c] * rstd;
        scale[c] = sc;
        shift[c] = be[c] - m * sc;
    }
}

// ---------------------------------------------------------------------------
// K2: gcn2 via 3xTF32 MMA. Block = 64 nodes.
// A = stencil(lrelu(bn1(gcn1(x)))) [64 x 64], B = W2^T split [64 x 64].
// z2 = A @ W2 + b2, with per-channel partial stats from fragments.
// ---------------------------------------------------------------------------
#define G2_HBE 0                // 66*66 = 4356, pad 4368
#define G2_AHI 4368             // 64*68 = 4352
#define G2_ALO 8720
#define G2_BHI 13072
#define G2_BLO 17424
#define G2_TOTF 21776
#define G2_BYTES (G2_TOTF * 4)  // 87104

__global__ __launch_bounds__(256) void gcn2_mma(
    const float* __restrict__ x, const float* __restrict__ W1,
    const float* __restrict__ b1, const float* __restrict__ sc1,
    const float* __restrict__ sh1, const float* __restrict__ w2hi,
    const float* __restrict__ w2lo, const float* __restrict__ b2,
    float* __restrict__ part, float* __restrict__ z2b) {
    extern __shared__ __align__(16) float dyn[];
    __shared__ float xs[204], W1s[192], b1s[64], sc1s[64], sh1s[64], b2s[64];
    __shared__ float redS[256], redQ[256];
    float* hbe = dyn + G2_HBE;
    float* Ahi = dyn + G2_AHI;
    float* Alo = dyn + G2_ALO;
    float* Bhi = dyn + G2_BHI;
    float* Blo = dyn + G2_BLO;
    int tid = threadIdx.x, lane = tid & 31, wid = tid >> 5;
    int n0 = blockIdx.x * 64;

    if (tid < 192) W1s[tid] = W1[tid];
    if (tid < 64) {
        b1s[tid] = b1[tid]; sc1s[tid] = sc1[tid];
        sh1s[tid] = sh1[tid]; b2s[tid] = b2[tid];
    }
    if (tid < 204) {
        int gi = (n0 - 2) * 3 + tid;
        xs[tid] = (gi >= 0 && gi < NNODES * 3) ? x[gi] : 0.f;
    }
    for (int i = tid; i < 1024; i += 256) {       // B tiles (float4 rows)
        int n = i >> 4, k4 = i & 15;
        float4 vh = *reinterpret_cast<const float4*>(w2hi + n * 64 + k4 * 4);
        float4 vl = *reinterpret_cast<const float4*>(w2lo + n * 64 + k4 * 4);
        *reinterpret_cast<float4*>(Bhi + n * 68 + k4 * 4) = vh;
        *reinterpret_cast<float4*>(Blo + n * 68 + k4 * 4) = vl;
    }
    __syncthreads();

    // Phase A: h for 66 local nodes (l = 0..65, node m = n0-1+l)
    for (int i = tid; i < 66 * 64; i += 256) {
        int c = i & 63, l = i >> 6;
        int m = n0 - 1 + l;
        float hv = 0.f;
        if (m >= 0 && m < NNODES) {
            int j = m % 25;
            const float* xb = xs + (l + 1) * 3;
            float w0 = W1s[c], w1 = W1s[64 + c], w2v = W1s[128 + c];
            float acc = dinvf(j) * (xb[0] * w0 + xb[1] * w1 + xb[2] * w2v);
            if (j > 0)  acc += dinvf(j - 1) * (xb[-3] * w0 + xb[-2] * w1 + xb[-1] * w2v);
            if (j < 24) acc += dinvf(j + 1) * (xb[3] * w0 + xb[4] * w1 + xb[5] * w2v);
            float z = dinvf(j) * acc + b1s[c];
            hv = lrelu(fmaf(z, sc1s[c], sh1s[c]));
        }
        hbe[l * 66 + c] = hv;
    }
    __syncthreads();

    // Phase B: stencil + tf32 split -> A tiles
    for (int i = tid; i < 4096; i += 256) {
        int c = i & 63, nl = i >> 6;
        int m = n0 + nl, j = m % 25, l = nl + 1;
        float acc = dinvf(j) * hbe[l * 66 + c];
        if (j > 0)  acc += dinvf(j - 1) * hbe[(l - 1) * 66 + c];
        if (j < 24) acc += dinvf(j + 1) * hbe[(l + 1) * 66 + c];
        float val = dinvf(j) * acc;
        float hi = totf32(val);
        Ahi[nl * 68 + c] = hi;
        Alo[nl * 68 + c] = totf32(val - hi);
    }
    __syncthreads();

    // MMA: 8 warps = 4M (16 rows) x 2N (32 cols); K=64 in 8 kt steps.
    int wm = wid & 3, wn = wid >> 2;
    float acc[4][4];
#pragma unroll
    for (int nt = 0; nt < 4; nt++)
#pragma unroll
        for (int u = 0; u < 4; u++) acc[nt][u] = 0.f;

#pragma unroll
    for (int kt = 0; kt < 8; kt++) {
        int aoff = (wm * 16 + (lane >> 2)) * 68 + kt * 8 + (lane & 3);
        uint32_t ah[4], al[4];
        ah[0] = __float_as_uint(Ahi[aoff]);
        ah[1] = __float_as_uint(Ahi[aoff + 544]);
        ah[2] = __float_as_uint(Ahi[aoff + 4]);
        ah[3] = __float_as_uint(Ahi[aoff + 548]);
        al[0] = __float_as_uint(Alo[aoff]);
        al[1] = __float_as_uint(Alo[aoff + 544]);
        al[2] = __float_as_uint(Alo[aoff + 4]);
        al[3] = __float_as_uint(Alo[aoff + 548]);
        int boff = (wn * 32 + (lane >> 2)) * 68 + kt * 8 + (lane & 3);
        uint32_t bh[4][2], bl[4][2];
#pragma unroll
        for (int nt = 0; nt < 4; nt++) {
            bh[nt][0] = __float_as_uint(Bhi[boff + nt * 544]);
            bh[nt][1] = __float_as_uint(Bhi[boff + nt * 544 + 4]);
            bl[nt][0] = __float_as_uint(Blo[boff + nt * 544]);
            bl[nt][1] = __float_as_uint(Blo[boff + nt * 544 + 4]);
        }
#pragma unroll
        for (int nt = 0; nt < 4; nt++) MMA_TF32(acc[nt], ah, bh[nt][0], bh[nt][1]);
#pragma unroll
        for (int nt = 0; nt < 4; nt++) MMA_TF32(acc[nt], ah, bl[nt][0], bl[nt][1]);
#pragma unroll
        for (int nt = 0; nt < 4; nt++) MMA_TF32(acc[nt], al, bh[nt][0], bh[nt][1]);
    }

    // Epilogue: bias + z2 store + per-channel partial stats
    int r0 = n0 + wm * 16 + (lane >> 2);
#pragma unroll
    for (int nt = 0; nt < 4; nt++) {
        int c0 = wn * 32 + nt * 8 + ((lane & 3) << 1);
        float bb0 = b2s[c0], bb1 = b2s[c0 + 1];
        float u0 = acc[nt][0] + bb0, u1 = acc[nt][1] + bb1;
        float u2 = acc[nt][2] + bb0, u3 = acc[nt][3] + bb1;
        *reinterpret_cast<float2*>(z2b + (size_t)r0 * 64 + c0) = make_float2(u0, u1);
        *reinterpret_cast<float2*>(z2b + (size_t)(r0 + 8) * 64 + c0) = make_float2(u2, u3);
        float s0 = u0 + u2, q0 = u0 * u0 + u2 * u2;
        float s1 = u1 + u3, q1 = u1 * u1 + u3 * u3;
#pragma unroll
        for (int o = 4; o < 32; o <<= 1) {
            s0 += __shfl_xor_sync(0xffffffffu, s0, o);
            q0 += __shfl_xor_sync(0xffffffffu, q0, o);
            s1 += __shfl_xor_sync(0xffffffffu, s1, o);
            q1 += __shfl_xor_sync(0xffffffffu, q1, o);
        }
        if (lane < 4) {
            redS[c0 * 4 + wm] = s0; redS[(c0 + 1) * 4 + wm] = s1;
            redQ[c0 * 4 + wm] = q0; redQ[(c0 + 1) * 4 + wm] = q1;
        }
    }
    __syncthreads();
    if (tid < 64) {
        float S = redS[tid * 4] + redS[tid * 4 + 1] + redS[tid * 4 + 2] + redS[tid * 4 + 3];
        float Q = redQ[tid * 4] + redQ[tid * 4 + 1] + redQ[tid * 4 + 2] + redQ[tid * 4 + 3];
        part[tid * 6400 + blockIdx.x] = S;
        part[409600 + tid * 6400 + blockIdx.x] = Q;
    }
}

// ---------------------------------------------------------------------------
// K3: conv1 as 3xTF32 mma.sync GEMM (unchanged from passing round).
// ---------------------------------------------------------------------------
#define SA_STRIDE 36
#define TILE_FLTS (128 * SA_STRIDE)                  // 4608
#define CM_BYTES (8 * TILE_FLTS * 4)                 // 147456

__global__ __launch_bounds__(256) void conv1_mma(
    const float* __restrict__ z2b, const float* __restrict__ wwhi,
    const float* __restrict__ wwlo, const float* __restrict__ sc,
    const float* __restrict__ sh, float* __restrict__ y) {
    extern __shared__ __align__(16) float smem[];
    __shared__ float scs[64], shs[64];
    int tid = threadIdx.x, lane = tid & 31, wid = tid >> 5;
    int wm = wid & 3, wn = wid >> 2;
    int m0 = blockIdx.y * 128, n0 = blockIdx.x * 128;
    if (tid < 64) { scs[tid] = sc[tid]; shs[tid] = sh[tid]; }
    __syncthreads();

    float acc[2][8][4];
#pragma unroll
    for (int mt = 0; mt < 2; mt++)
#pragma unroll
        for (int nt = 0; nt < 8; nt++)
#pragma unroll
            for (int u = 0; u < 4; u++) acc[mt][nt][u] = 0.f;

    float4 aReg[4];

#define LOADA(step) do { \
        int ci0_ = (step) * 32; \
        _Pragma("unroll") \
        for (int u = 0; u < 4; u++) { \
            int fi = u * 256 + tid; \
            int row = fi >> 3, c4 = fi & 7; \
            aReg[u] = *reinterpret_cast<const float4*>( \
                z2b + (size_t)(m0 + row) * KCI + ci0_ + c4 * 4); \
        } \
    } while (0)

#define STOREA(bufi, step) do { \
        int ci0_ = (step) * 32; \
        float* Ahi_ = smem + (bufi) * 4 * TILE_FLTS; \
        float* Alo_ = Ahi_ + TILE_FLTS; \
        _Pragma("unroll") \
        for (int u = 0; u < 4; u++) { \
            int fi = u * 256 + tid; \
            int row = fi >> 3, c4 = fi & 7; \
            int cb = (ci0_ + c4 * 4) & 63; \
            float4 v = aReg[u]; \
            v.x = lrelu(fmaf(v.x, scs[cb],     shs[cb])); \
            v.y = lrelu(fmaf(v.y, scs[cb + 1], shs[cb + 1])); \
            v.z = lrelu(fmaf(v.z, scs[cb + 2], shs[cb + 2])); \
            v.w = lrelu(fmaf(v.w, scs[cb + 3], shs[cb + 3])); \
            float4 hv, lv; \
            hv.x = totf32(v.x); lv.x = totf32(v.x - hv.x); \
            hv.y = totf32(v.y); lv.y = totf32(v.y - hv.y); \
            hv.z = totf32(v.z); lv.z = totf32(v.z - hv.z); \
            hv.w = totf32(v.w); lv.w = totf32(v.w - hv.w); \
            *reinterpret_cast<float4*>(Ahi_ + row * SA_STRIDE + c4 * 4) = hv; \
            *reinterpret_cast<float4*>(Alo_ + row * SA_STRIDE + c4 * 4) = lv; \
        } \
    } while (0)

#define LOADB(bufi, step) do { \
        int ci0_ = (step) * 32; \
        float* Bhi_ = smem + (bufi) * 4 * TILE_FLTS + 2 * TILE_FLTS; \
        float* Blo_ = Bhi_ + TILE_FLTS; \
        _Pragma("unroll") \
        for (int u = 0; u < 4; u++) { \
            int fi = u * 256 + tid; \
            int row = fi >> 3, c4 = fi & 7; \
            size_t goff = (size_t)(n0 + row) * KCI + ci0_ + c4 * 4; \
            uint32_t sh_ = (uint32_t)__cvta_generic_to_shared(Bhi_ + row * SA_STRIDE + c4 * 4); \
            uint32_t sl_ = (uint32_t)__cvta_generic_to_shared(Blo_ + row * SA_STRIDE + c4 * 4); \
            cp_async16(sh_, wwhi + goff); \
            cp_async16(sl_, wwlo + goff); \
        } \
        asm volatile("cp.async.commit_group;" ::: "memory"); \
    } while (0)

    LOADA(0);
    STOREA(0, 0);
    LOADB(0, 0);

    for (int i = 0; i < 50; i++) {
        int buf = i & 1;
        if (i < 49) LOADA(i + 1);
        asm volatile("cp.async.wait_group 0;" ::: "memory");
        __syncthreads();
        if (i < 49) LOADB(buf ^ 1, i + 1);

        const float* Ahi = smem + buf * 4 * TILE_FLTS;
        const float* Alo = Ahi + TILE_FLTS;
        const float* Bhi = Ahi + 2 * TILE_FLTS;
        const float* Blo = Ahi + 3 * TILE_FLTS;
#pragma unroll
        for (int kt = 0; kt < 4; kt++) {
            uint32_t ahi[2][4], alo[2][4], bhi[8][2], blo[8][2];
            int aoff = (wm * 32 + (lane >> 2)) * SA_STRIDE + kt * 8 + (lane & 3);
#pragma unroll
            for (int mt = 0; mt < 2; mt++) {
                const float* ph = Ahi + aoff + mt * 576;
                const float* pl = Alo + aoff + mt * 576;
                ahi[mt][0] = __float_as_uint(ph[0]);
                ahi[mt][1] = __float_as_uint(ph[288]);
                ahi[mt][2] = __float_as_uint(ph[4]);
                ahi[mt][3] = __float_as_uint(ph[292]);
                alo[mt][0] = __float_as_uint(pl[0]);
                alo[mt][1] = __float_as_uint(pl[288]);
                alo[mt][2] = __float_as_uint(pl[4]);
                alo[mt][3] = __float_as_uint(pl[292]);
            }
            int boff = (wn * 64 + (lane >> 2)) * SA_STRIDE + kt * 8 + (lane & 3);
#pragma unroll
            for (int nt = 0; nt < 8; nt++) {
                bhi[nt][0] = __float_as_uint(Bhi[boff + nt * 288]);
                bhi[nt][1] = __float_as_uint(Bhi[boff + nt * 288 + 4]);
                blo[nt][0] = __float_as_uint(Blo[boff + nt * 288]);
                blo[nt][1] = __float_as_uint(Blo[boff + nt * 288 + 4]);
            }
#pragma unroll
            for (int nt = 0; nt < 8; nt++) {
                MMA_TF32(acc[0][nt], ahi[0], bhi[nt][0], bhi[nt][1]);
                MMA_TF32(acc[1][nt], ahi[1], bhi[nt][0], bhi[nt][1]);
            }
#pragma unroll
            for (int nt = 0; nt < 8; nt++) {
                MMA_TF32(acc[0][nt], ahi[0], blo[nt][0], blo[nt][1]);
                MMA_TF32(acc[1][nt], ahi[1], blo[nt][0], blo[nt][1]);
            }
#pragma unroll
            for (int nt = 0; nt < 8; nt++) {
                MMA_TF32(acc[0][nt], alo[0], bhi[nt][0], bhi[nt][1]);
                MMA_TF32(acc[1][nt], alo[1], bhi[nt][0], bhi[nt][1]);
            }
        }
        if (i < 49) STOREA(buf ^ 1, i + 1);
    }

#pragma unroll
    for (int mt = 0; mt < 2; mt++) {
#pragma unroll
        for (int nt = 0; nt < 8; nt++) {
            int row = m0 + wm * 32 + mt * 16 + (lane >> 2);
            int col = n0 + wn * 64 + nt * 8 + ((lane & 3) << 1);
            float2 v0 = make_float2(acc[mt][nt][0], acc[mt][nt][1]);
            float2 v1 = make_float2(acc[mt][nt][2], acc[mt][nt][3]);
            *reinterpret_cast<float2*>(y + (size_t)row * NW + col) = v0;
            *reinterpret_cast<float2*>(y + (size_t)(row + 8) * NW + col) = v1;
        }
    }
#undef LOADA
#undef STOREA
#undef LOADB
}

// ---------------------------------------------------------------------------
// K4: shift-add epilogue + fused per-channel stats.
// w1out[b][o][f] = Y[f-1][o] + Y[f][128+o] + Y[f+1][256+o] + cb1[o]
// ---------------------------------------------------------------------------
__global__ __launch_bounds__(256) void shiftadd(
    const float* __restrict__ y, const float* __restrict__ cb1,
    float* __restrict__ w1o, float* __restrict__ part) {
    __shared__ float t[128 * 65];
    int tid = threadIdx.x;
    int b = blockIdx.y;
    int f0 = blockIdx.x * 64;
    for (int i = tid; i < 8192; i += 256) {
        int o = i & 127, ff = i >> 7;
        int f = f0 + ff, m = b * 256 + f;
        float val = __ldg(cb1 + o) + y[(size_t)m * NW + 128 + o];
        if (f > 0)   val += y[(size_t)(m - 1) * NW + o];
        if (f < 255) val += y[(size_t)(m + 1) * NW + 256 + o];
        t[o * 65 + ff] = val;
    }
    __syncthreads();
    for (int i = tid; i < 8192; i += 256) {
        int ff = i & 63, o = i >> 6;
        w1o[(size_t)(b * 128 + o) * 256 + f0 + ff] = t[o * 65 + ff];
    }
    // fused stats: per-o sums over this 64-frame tile
    if (tid < 128) {
        float S = 0.f, Q = 0.f;
#pragma unroll 8
        for (int k = 0; k < 64; k++) {
            float v = t[tid * 65 + k];
            S += v; Q += v * v;
        }
        int blk = blockIdx.y * 4 + blockIdx.x;
        part[tid * 256 + blk] = S;
        part[32768 + tid * 256 + blk] = Q;
    }
}

// ---------------------------------------------------------------------------
// K6: Conv2 (1x1, 128->64) with bnC1+lrelu fused at load + partial stats.
// ---------------------------------------------------------------------------
__global__ __launch_bounds__(256) void conv2_kernel(
    const float* __restrict__ w1o, const float* __restrict__ cw2,
    const float* __restrict__ cb2, const float* __restrict__ sc,
    const float* __restrict__ sh, float* __restrict__ vout,
    float* __restrict__ part) {
    __shared__ __align__(16) float Us[64 * 64];
    __shared__ __align__(16) float Ws2[64 * 64];
    int tid = threadIdx.x;
    int b = blockIdx.y;
    int f0 = blockIdx.x * 64;
    int fth = tid & 15, oth = tid >> 4;
    float acc[4][4] = {};

    for (int ci0 = 0; ci0 < 128; ci0 += 64) {
        for (int i = tid; i < 4096; i += 256) {
            int cc = i >> 6, ffi = i & 63;
            float raw = w1o[(size_t)(b * 128 + ci0 + cc) * 256 + f0 + ffi];
            float v = fmaf(raw, __ldg(sc + ci0 + cc), __ldg(sh + ci0 + cc));
            Us[i] = lrelu(v);
        }
        for (int i = tid; i < 4096; i += 256) {
            int o = i & 63, cc = i >> 6;
            Ws2[cc * 64 + o] = cw2[o * 128 + ci0 + cc];
        }
        __syncthreads();
#pragma unroll 8
        for (int cc = 0; cc < 64; cc++) {
            float4 iv = *reinterpret_cast<const float4*>(Us + cc * 64 + fth * 4);
            float4 wv = *reinterpret_cast<const float4*>(Ws2 + cc * 64 + oth * 4);
            acc[0][0] = fmaf(wv.x, iv.x, acc[0][0]); acc[0][1] = fmaf(wv.x, iv.y, acc[0][1]);
            acc[0][2] = fmaf(wv.x, iv.z, acc[0][2]); acc[0][3] = fmaf(wv.x, iv.w, acc[0][3]);
            acc[1][0] = fmaf(wv.y, iv.x, acc[1][0]); acc[1][1] = fmaf(wv.y, iv.y, acc[1][1]);
            acc[1][2] = fmaf(wv.y, iv.z, acc[1][2]); acc[1][3] = fmaf(wv.y, iv.w, acc[1][3]);
            acc[2][0] = fmaf(wv.z, iv.x, acc[2][0]); acc[2][1] = fmaf(wv.z, iv.y, acc[2][1]);
            acc[2][2] = fmaf(wv.z, iv.z, acc[2][2]); acc[2][3] = fmaf(wv.z, iv.w, acc[2][3]);
            acc[3][0] = fmaf(wv.w, iv.x, acc[3][0]); acc[3][1] = fmaf(wv.w, iv.y, acc[3][1]);
            acc[3][2] = fmaf(wv.w, iv.z, acc[3][2]); acc[3][3] = fmaf(wv.w, iv.w, acc[3][3]);
        }
        __syncthreads();
    }

    float* reds = Us;
    float* redq = Ws2;
#pragma unroll
    for (int i = 0; i < 4; i++) {
        int o = oth * 4 + i;
        float bias = __ldg(cb2 + o);
        float s = 0.f, q = 0.f;
#pragma unroll
        for (int j2 = 0; j2 < 4; j2++) {
            float r = acc[i][j2] + bias;
            vout[(size_t)(b * 64 + o) * 256 + f0 + fth * 4 + j2] = r;
            s += r; q += r * r;
        }
        reds[o * 17 + fth] = s;
        redq[o * 17 + fth] = q;
    }
    __syncthreads();
    if (tid < 64) {
        float S = 0.f, Q = 0.f;
#pragma unroll
        for (int t = 0; t < 16; t++) { S += reds[tid * 17 + t]; Q += redq[tid * 17 + t]; }
        int blk = blockIdx.y * 4 + blockIdx.x;
        part[tid * 256 + blk] = S;
        part[16384 + tid * 256 + blk] = Q;
    }
}

// ---------------------------------------------------------------------------
// K7: final BN + LReLU + transpose (B,64,256) -> (B,256,64)
// ---------------------------------------------------------------------------
__global__ __launch_bounds__(256) void final_kernel(
    const float* __restrict__ v, const float* __restrict__ sc,
    const float* __restrict__ sh, float* __restrict__ out) {
    __shared__ float s[64 * 65];
    int tid = threadIdx.x;
    int b = blockIdx.y;
    int f0 = blockIdx.x * 64;
    for (int i = tid; i < 4096; i += 256) {
        int o = i >> 6, ffi = i & 63;
        s[o * 65 + ffi] = v[(size_t)(b * 64 + o) * 256 + f0 + ffi];
    }
    __syncthreads();
    for (int i = tid; i < 4096; i += 256) {
        int ffi = i >> 6, o = i & 63;
        float val = fmaf(s[o * 65 + ffi], __ldg(sc + o), __ldg(sh + o));
        out[(size_t)(b * 256 + f0 + ffi) * 64 + o] = lrelu(val);
    }
}

// ---------------------------------------------------------------------------
// Launch
// ---------------------------------------------------------------------------
extern "C" void kernel_launch(void* const* d_in, const int* in_sizes, int n_in,
                              void* d_out, int out_size) {
    const float* x   = (const float*)d_in[0];
    const float* W1  = (const float*)d_in[4];
    const float* b1  = (const float*)d_in[5];
    const float* g1  = (const float*)d_in[6];
    const float* be1 = (const float*)d_in[7];
    const float* W2  = (const float*)d_in[8];
    const float* b2  = (const float*)d_in[9];
    const float* g2  = (const float*)d_in[10];
    const float* be2 = (const float*)d_in[11];
    const float* cw1 = (const float*)d_in[12];
    const float* cb1 = (const float*)d_in[13];
    const float* cg1 = (const float*)d_in[14];
    const float* cbe1= (const float*)d_in[15];
    const float* cw2 = (const float*)d_in[16];
    const float* cb2 = (const float*)d_in[17];
    const float* cg2 = (const float*)d_in[18];
    const float* cbe2= (const float*)d_in[19];
    float* out = (float*)d_out;

    float *z2, *y, *whi, *wlo, *w2h, *w2l, *w1o, *v, *p1, *p2, *pC1, *pC2;
    float *s1, *h1, *s2, *h2, *sC1, *hC1, *sC2, *hC2;
    cudaGetSymbolAddress((void**)&z2,  g_z2);
    cudaGetSymbolAddress((void**)&y,   g_y);
    cudaGetSymbolAddress((void**)&whi, g_wwhi);
    cudaGetSymbolAddress((void**)&wlo, g_wwlo);
    cudaGetSymbolAddress((void**)&w2h, g_w2hi);
    cudaGetSymbolAddress((void**)&w2l, g_w2lo);
    cudaGetSymbolAddress((void**)&w1o, g_w1out);
    cudaGetSymbolAddress((void**)&v,   g_v);
    cudaGetSymbolAddress((void**)&p1,  g_p1);
    cudaGetSymbolAddress((void**)&p2,  g_p2);
    cudaGetSymbolAddress((void**)&pC1, g_pC1);
    cudaGetSymbolAddress((void**)&pC2, g_pC2);
    cudaGetSymbolAddress((void**)&s1,  g_scale1);
    cudaGetSymbolAddress((void**)&h1,  g_shift1);
    cudaGetSymbolAddress((void**)&s2,  g_scale2);
    cudaGetSymbolAddress((void**)&h2,  g_shift2);
    cudaGetSymbolAddress((void**)&sC1, g_scaleC1);
    cudaGetSymbolAddress((void**)&hC1, g_shiftC1);
    cudaGetSymbolAddress((void**)&sC2, g_scaleC2);
    cudaGetSymbolAddress((void**)&hC2, g_shiftC2);

    cudaFuncSetAttribute(conv1_mma, cudaFuncAttributeMaxDynamicSharedMemorySize, CM_BYTES);
    cudaFuncSetAttribute(gcn2_mma,  cudaFuncAttributeMaxDynamicSharedMemorySize, G2_BYTES);

    const float invN_nodes = 1.f / (float)NNODES;
    const float invN_bf    = 1.f / (float)(BB * FF);

    wprep<<<2400, 256>>>(cw1, whi, wlo);                                      // 0
    w2prep<<<16, 256>>>(W2, w2h, w2l);                                        // 1
    gcn1_stats<<<1024, 256>>>(x, W1, b1, p1);                                 // 2
    bn_final<<<64, 256>>>(p1, 1024, 64, g1, be1, invN_nodes, s1, h1);         // 3
    gcn2_mma<<<6400, 256, G2_BYTES>>>(x, W1, b1, s1, h1, w2h, w2l, b2, p2, z2); // 4
    bn_final<<<64, 256>>>(p2, 6400, 64, g2, be2, invN_nodes, s2, h2);         // 5
    conv1_mma<<<dim3(3, 128), 256, CM_BYTES>>>(z2, whi, wlo, s2, h2, y);      // 6
    shiftadd<<<dim3(4, BB), 256>>>(y, cb1, w1o, pC1);                         // 7
    bn_final<<<128, 256>>>(pC1, 256, 128, cg1, cbe1, invN_bf, sC1, hC1);      // 8
    conv2_kernel<<<dim3(4, BB), 256>>>(w1o, cw2, cb2, sC1, hC1, v, pC2);      // 9
    bn_final<<<64, 256>>>(pC2, 256, 64, cg2, cbe2, invN_bf, sC2, hC2);        // 10
    final_kernel<<<dim3(4, BB), 256>>>(v, sC2, hC2, out);                     // 11
}

// round 8
// speedup vs baseline: 1.2539x; 1.2539x over previous
#include <cuda_runtime.h>
#include <cuda_bf16.h>
#include <cstdint>

#define BB 64
#define FF 256
#define JJ 25
#define FILT 64
#define C1 128
#define NNODES (BB * FF * JJ)              // 409600
#define NE (NNODES * FILT)                 // 26214400
#define MTOT (BB * FF)                     // 16384
#define NW 384
#define KCI 1600
#define EPSV 1e-5f

// ---------------------------------------------------------------------------
// Scratch
// ---------------------------------------------------------------------------
__device__ float g_z2[NE];                 // GCN2 pre-BN output [node][c]
__device__ float g_y[MTOT * NW];           // conv1 GEMM output (pre shift-add)
__device__ __nv_bfloat16 g_wwhi[NW * KCI]; // tap-split conv1 weights, bf16 hi
__device__ __nv_bfloat16 g_wwlo[NW * KCI]; // bf16 lo residual
__device__ float g_w2hi[FILT * FILT];      // W2 split (tf32), [n_out][k_in]
__device__ float g_w2lo[FILT * FILT];
__device__ float g_w1out[BB * C1 * FF];    // conv1 raw output (pre-BN)
__device__ float g_v[BB * FILT * FF];      // conv2 raw output (pre-BN)
__device__ float g_p1[2 * 64 * 1024];
__device__ float g_p2[2 * 64 * 6400];
__device__ float g_pC1[2 * 128 * 256];
__device__ float g_pC2[2 * 64 * 256];
__device__ float g_scale1[64], g_shift1[64];
__device__ float g_scale2[64], g_shift2[64];
__device__ float g_scaleC1[128], g_shiftC1[128];
__device__ float g_scaleC2[64], g_shiftC2[64];

__device__ __forceinline__ float dinvf(int j) {
    return (j == 0 || j == JJ - 1) ? 0.70710678118654752f : 0.57735026918962576f;
}
__device__ __forceinline__ float lrelu(float v) { return v >= 0.f ? v : 0.2f * v; }
__device__ __forceinline__ float totf32(float x) {
    uint32_t u; asm("cvt.rna.tf32.f32 %0, %1;" : "=r"(u) : "f"(x));
    return __uint_as_float(u);
}

#define MMA_TF32(d, av, b0, b1) \
    asm volatile("mma.sync.aligned.m16n8k8.row.col.f32.tf32.tf32.f32 " \
        "{%0,%1,%2,%3}, {%4,%5,%6,%7}, {%8,%9}, {%0,%1,%2,%3};" \
        : "+f"((d)[0]), "+f"((d)[1]), "+f"((d)[2]), "+f"((d)[3]) \
        : "r"((av)[0]), "r"((av)[1]), "r"((av)[2]), "r"((av)[3]), \
          "r"(b0), "r"(b1))

#define MMA_BF16(d, av, b0, b1) \
    asm volatile("mma.sync.aligned.m16n8k16.row.col.f32.bf16.bf16.f32 " \
        "{%0,%1,%2,%3}, {%4,%5,%6,%7}, {%8,%9}, {%0,%1,%2,%3};" \
        : "+f"((d)[0]), "+f"((d)[1]), "+f"((d)[2]), "+f"((d)[3]) \
        : "r"((av)[0]), "r"((av)[1]), "r"((av)[2]), "r"((av)[3]), \
          "r"(b0), "r"(b1))

__device__ __forceinline__ void cp_async16(uint32_t saddr, const void* g) {
    asm volatile("cp.async.cg.shared.global [%0], [%1], 16;" :: "r"(saddr), "l"(g) : "memory");
}

// ---------------------------------------------------------------------------
// K0: merged prep.
//  blocks [0,2400): conv1 weights bf16-split, wwhi/lo[k*128+o][ci] from cw1[o][ci][k]
//  blocks [2400,2416): W2 tf32-split transposed, w2hi/lo[n*64+k] = split(W2[k*64+n])
// ---------------------------------------------------------------------------
__global__ __launch_bounds__(256) void prep(
    const float* __restrict__ cw1, const float* __restrict__ W2,
    __nv_bfloat16* __restrict__ whi, __nv_bfloat16* __restrict__ wlo,
    float* __restrict__ w2h, float* __restrict__ w2l) {
    int bid = blockIdx.x;
    if (bid < 2400) {
        int idx = bid * 256 + threadIdx.x;        // < 614400 exactly
        int n = idx / KCI, ci = idx - n * KCI;
        int k = n >> 7, o = n & 127;
        float w = cw1[(size_t)o * 4800 + ci * 3 + k];
        __nv_bfloat16 hb = __float2bfloat16(w);
        whi[idx] = hb;
        wlo[idx] = __float2bfloat16(w - __bfloat162float(hb));
    } else {
        int i = (bid - 2400) * 256 + threadIdx.x; // < 4096
        int n = i >> 6, k = i & 63;
        float w = W2[k * 64 + n];
        float hi = totf32(w);
        w2h[i] = hi;
        w2l[i] = totf32(w - hi);
    }
}

// ---------------------------------------------------------------------------
// K1: GCN1 stats only (z1 recomputed, never stored). Block = 16 graphs.
// ---------------------------------------------------------------------------
__global__ __launch_bounds__(256) void gcn1_stats(
    const float* __restrict__ x, const float* __restrict__ W1,
    const float* __restrict__ b1, float* __restrict__ part) {
    __shared__ float xs[1200], W1s[192], b1s[64], ss[256], qq[256];
    int tid = threadIdx.x;
    if (tid < 192) W1s[tid] = W1[tid];
    if (tid < 64) b1s[tid] = b1[tid];
    int base = blockIdx.x * 1200;
    for (int i = tid; i < 1200; i += 256) xs[i] = x[base + i];
    __syncthreads();

    int c = tid & 63, sub = tid >> 6;
    float w0 = W1s[c], w1 = W1s[64 + c], w2 = W1s[128 + c], bb = b1s[c];
    float s = 0.f, q = 0.f;
    for (int it = 0; it < 100; it++) {
        int nl = it * 4 + sub;
        int j = nl % 25;
        const float* xb = xs + nl * 3;
        float acc = dinvf(j) * (xb[0] * w0 + xb[1] * w1 + xb[2] * w2);
        if (j > 0)      acc += dinvf(j - 1) * (xb[-3] * w0 + xb[-2] * w1 + xb[-1] * w2);
        if (j < JJ - 1) acc += dinvf(j + 1) * (xb[3] * w0 + xb[4] * w1 + xb[5] * w2);
        float z = dinvf(j) * acc + bb;
        s += z; q += z * z;
    }
    ss[tid] = s; qq[tid] = q;
    __syncthreads();
    if (tid < 64) {
        s = ss[tid] + ss[tid + 64] + ss[tid + 128] + ss[tid + 192];
        q = qq[tid] + qq[tid + 64] + qq[tid + 128] + qq[tid + 192];
        part[tid * 1024 + blockIdx.x] = s;
        part[65536 + tid * 1024 + blockIdx.x] = q;
    }
}

// ---------------------------------------------------------------------------
// BN finalize: part layout S at [c*R + r], Q at [C*R + c*R + r].
// ---------------------------------------------------------------------------
__global__ __launch_bounds__(256) void bn_final(
    const float* __restrict__ part, int R, int C,
    const float* __restrict__ g, const float* __restrict__ be, float invN,
    float* __restrict__ scale, float* __restrict__ shift) {
    int c = blockIdx.x, tid = threadIdx.x;
    __shared__ float ss[256], qq[256];
    const float* pS = part + (size_t)c * R;
    const float* pQ = part + (size_t)C * R + (size_t)c * R;
    float s = 0.f, q = 0.f;
    for (int r = tid; r < R; r += 256) { s += pS[r]; q += pQ[r]; }
    ss[tid] = s; qq[tid] = q;
    __syncthreads();
    for (int o = 128; o > 0; o >>= 1) {
        if (tid < o) { ss[tid] += ss[tid + o]; qq[tid] += qq[tid + o]; }
        __syncthreads();
    }
    if (tid == 0) {
        float m = ss[0] * invN;
        float var = qq[0] * invN - m * m;
        float rstd = rsqrtf(var + EPSV);
        float sc = g[c] * rstd;
        scale[c] = sc;
        shift[c] = be[c] - m * sc;
    }
}

// ---------------------------------------------------------------------------
// K2: gcn2 via 3xTF32 MMA. Block = 64 nodes. (unchanged)
// ---------------------------------------------------------------------------
#define G2_HBE 0                // 66*66 = 4356, pad 4368
#define G2_AHI 4368             // 64*68 = 4352
#define G2_ALO 8720
#define G2_BHI 13072
#define G2_BLO 17424
#define G2_TOTF 21776
#define G2_BYTES (G2_TOTF * 4)  // 87104

__global__ __launch_bounds__(256) void gcn2_mma(
    const float* __restrict__ x, const float* __restrict__ W1,
    const float* __restrict__ b1, const float* __restrict__ sc1,
    const float* __restrict__ sh1, const float* __restrict__ w2hi,
    const float* __restrict__ w2lo, const float* __restrict__ b2,
    float* __restrict__ part, float* __restrict__ z2b) {
    extern __shared__ __align__(16) char dynraw[];
    float* dyn = reinterpret_cast<float*>(dynraw);
    __shared__ float xs[204], W1s[192], b1s[64], sc1s[64], sh1s[64], b2s[64];
    __shared__ float redS[256], redQ[256];
    float* hbe = dyn + G2_HBE;
    float* Ahi = dyn + G2_AHI;
    float* Alo = dyn + G2_ALO;
    float* Bhi = dyn + G2_BHI;
    float* Blo = dyn + G2_BLO;
    int tid = threadIdx.x, lane = tid & 31, wid = tid >> 5;
    int n0 = blockIdx.x * 64;

    if (tid < 192) W1s[tid] = W1[tid];
    if (tid < 64) {
        b1s[tid] = b1[tid]; sc1s[tid] = sc1[tid];
        sh1s[tid] = sh1[tid]; b2s[tid] = b2[tid];
    }
    if (tid < 204) {
        int gi = (n0 - 2) * 3 + tid;
        xs[tid] = (gi >= 0 && gi < NNODES * 3) ? x[gi] : 0.f;
    }
    for (int i = tid; i < 1024; i += 256) {
        int n = i >> 4, k4 = i & 15;
        float4 vh = *reinterpret_cast<const float4*>(w2hi + n * 64 + k4 * 4);
        float4 vl = *reinterpret_cast<const float4*>(w2lo + n * 64 + k4 * 4);
        *reinterpret_cast<float4*>(Bhi + n * 68 + k4 * 4) = vh;
        *reinterpret_cast<float4*>(Blo + n * 68 + k4 * 4) = vl;
    }
    __syncthreads();

    for (int i = tid; i < 66 * 64; i += 256) {
        int c = i & 63, l = i >> 6;
        int m = n0 - 1 + l;
        float hv = 0.f;
        if (m >= 0 && m < NNODES) {
            int j = m % 25;
            const float* xb = xs + (l + 1) * 3;
            float w0 = W1s[c], w1 = W1s[64 + c], w2v = W1s[128 + c];
            float acc = dinvf(j) * (xb[0] * w0 + xb[1] * w1 + xb[2] * w2v);
            if (j > 0)  acc += dinvf(j - 1) * (xb[-3] * w0 + xb[-2] * w1 + xb[-1] * w2v);
            if (j < 24) acc += dinvf(j + 1) * (xb[3] * w0 + xb[4] * w1 + xb[5] * w2v);
            float z = dinvf(j) * acc + b1s[c];
            hv = lrelu(fmaf(z, sc1s[c], sh1s[c]));
        }
        hbe[l * 66 + c] = hv;
    }
    __syncthreads();

    for (int i = tid; i < 4096; i += 256) {
        int c = i & 63, nl = i >> 6;
        int m = n0 + nl, j = m % 25, l = nl + 1;
        float acc = dinvf(j) * hbe[l * 66 + c];
        if (j > 0)  acc += dinvf(j - 1) * hbe[(l - 1) * 66 + c];
        if (j < 24) acc += dinvf(j + 1) * hbe[(l + 1) * 66 + c];
        float val = dinvf(j) * acc;
        float hi = totf32(val);
        Ahi[nl * 68 + c] = hi;
        Alo[nl * 68 + c] = totf32(val - hi);
    }
    __syncthreads();

    int wm = wid & 3, wn = wid >> 2;
    float acc[4][4];
#pragma unroll
    for (int nt = 0; nt < 4; nt++)
#pragma unroll
        for (int u = 0; u < 4; u++) acc[nt][u] = 0.f;

#pragma unroll
    for (int kt = 0; kt < 8; kt++) {
        int aoff = (wm * 16 + (lane >> 2)) * 68 + kt * 8 + (lane & 3);
        uint32_t ah[4], al[4];
        ah[0] = __float_as_uint(Ahi[aoff]);
        ah[1] = __float_as_uint(Ahi[aoff + 544]);
        ah[2] = __float_as_uint(Ahi[aoff + 4]);
        ah[3] = __float_as_uint(Ahi[aoff + 548]);
        al[0] = __float_as_uint(Alo[aoff]);
        al[1] = __float_as_uint(Alo[aoff + 544]);
        al[2] = __float_as_uint(Alo[aoff + 4]);
        al[3] = __float_as_uint(Alo[aoff + 548]);
        int boff = (wn * 32 + (lane >> 2)) * 68 + kt * 8 + (lane & 3);
        uint32_t bh[4][2], bl[4][2];
#pragma unroll
        for (int nt = 0; nt < 4; nt++) {
            bh[nt][0] = __float_as_uint(Bhi[boff + nt * 544]);
            bh[nt][1] = __float_as_uint(Bhi[boff + nt * 544 + 4]);
            bl[nt][0] = __float_as_uint(Blo[boff + nt * 544]);
            bl[nt][1] = __float_as_uint(Blo[boff + nt * 544 + 4]);
        }
#pragma unroll
        for (int nt = 0; nt < 4; nt++) MMA_TF32(acc[nt], ah, bh[nt][0], bh[nt][1]);
#pragma unroll
        for (int nt = 0; nt < 4; nt++) MMA_TF32(acc[nt], ah, bl[nt][0], bl[nt][1]);
#pragma unroll
        for (int nt = 0; nt < 4; nt++) MMA_TF32(acc[nt], al, bh[nt][0], bh[nt][1]);
    }

    int r0 = n0 + wm * 16 + (lane >> 2);
#pragma unroll
    for (int nt = 0; nt < 4; nt++) {
        int c0 = wn * 32 + nt * 8 + ((lane & 3) << 1);
        float bb0 = b2s[c0], bb1 = b2s[c0 + 1];
        float u0 = acc[nt][0] + bb0, u1 = acc[nt][1] + bb1;
        float u2 = acc[nt][2] + bb0, u3 = acc[nt][3] + bb1;
        *reinterpret_cast<float2*>(z2b + (size_t)r0 * 64 + c0) = make_float2(u0, u1);
        *reinterpret_cast<float2*>(z2b + (size_t)(r0 + 8) * 64 + c0) = make_float2(u2, u3);
        float s0 = u0 + u2, q0 = u0 * u0 + u2 * u2;
        float s1 = u1 + u3, q1 = u1 * u1 + u3 * u3;
#pragma unroll
        for (int o = 4; o < 32; o <<= 1) {
            s0 += __shfl_xor_sync(0xffffffffu, s0, o);
            q0 += __shfl_xor_sync(0xffffffffu, q0, o);
            s1 += __shfl_xor_sync(0xffffffffu, s1, o);
            q1 += __shfl_xor_sync(0xffffffffu, q1, o);
        }
        if (lane < 4) {
            redS[c0 * 4 + wm] = s0; redS[(c0 + 1) * 4 + wm] = s1;
            redQ[c0 * 4 + wm] = q0; redQ[(c0 + 1) * 4 + wm] = q1;
        }
    }
    __syncthreads();
    if (tid < 64) {
        float S = redS[tid * 4] + redS[tid * 4 + 1] + redS[tid * 4 + 2] + redS[tid * 4 + 3];
        float Q = redQ[tid * 4] + redQ[tid * 4 + 1] + redQ[tid * 4 + 2] + redQ[tid * 4 + 3];
        part[tid * 6400 + blockIdx.x] = S;
        part[409600 + tid * 6400 + blockIdx.x] = Q;
    }
}

// ---------------------------------------------------------------------------
// K3: conv1 as bf16x3 mma.sync GEMM (m16n8k16).
// Y[16384][384] = act(z2)[16384][1600] x ww[384][1600]^T.
// Block 128M x 128N x 32K; 8 warps (4M x 2N); warp tile 32x64.
// bf16 smem rows padded to 40 elems (80B) -> all 32-bit frag loads conflict-free.
// Buffers: {Ahi, Alo, Bhi, Blo} x 2 stages = 81920 B.
// ---------------------------------------------------------------------------
#define TILEB 5120                                   // 128*40 bf16
#define CM_BYTES (8 * TILEB * 2)                     // 81920

__global__ __launch_bounds__(256) void conv1_mma(
    const float* __restrict__ z2b, const __nv_bfloat16* __restrict__ wwhi,
    const __nv_bfloat16* __restrict__ wwlo, const float* __restrict__ sc,
    const float* __restrict__ sh, float* __restrict__ y) {
    extern __shared__ __align__(16) char dynraw[];
    __nv_bfloat16* sm = reinterpret_cast<__nv_bfloat16*>(dynraw);
    __shared__ float scs[64], shs[64];
    int tid = threadIdx.x, lane = tid & 31, wid = tid >> 5;
    int wm = wid & 3, wn = wid >> 2;
    int m0 = blockIdx.y * 128, n0 = blockIdx.x * 128;
    if (tid < 64) { scs[tid] = sc[tid]; shs[tid] = sh[tid]; }
    __syncthreads();

    float acc[2][8][4];
#pragma unroll
    for (int mt = 0; mt < 2; mt++)
#pragma unroll
        for (int nt = 0; nt < 8; nt++)
#pragma unroll
            for (int u = 0; u < 4; u++) acc[mt][nt][u] = 0.f;

    float4 aReg[4];

#define LOADA(step) do { \
        int ci0_ = (step) * 32; \
        _Pragma("unroll") \
        for (int u = 0; u < 4; u++) { \
            int fi = u * 256 + tid; \
            int row = fi >> 3, c4 = fi & 7; \
            aReg[u] = *reinterpret_cast<const float4*>( \
                z2b + (size_t)(m0 + row) * KCI + ci0_ + c4 * 4); \
        } \
    } while (0)

#define STOREA(bufi, step) do { \
        int ci0_ = (step) * 32; \
        __nv_bfloat16* Ah_ = sm + (bufi) * 4 * TILEB; \
        __nv_bfloat16* Al_ = Ah_ + TILEB; \
        _Pragma("unroll") \
        for (int u = 0; u < 4; u++) { \
            int fi = u * 256 + tid; \
            int row = fi >> 3, c4 = fi & 7; \
            int cb = (ci0_ + c4 * 4) & 63; \
            float4 v = aReg[u]; \
            v.x = lrelu(fmaf(v.x, scs[cb],     shs[cb])); \
            v.y = lrelu(fmaf(v.y, scs[cb + 1], shs[cb + 1])); \
            v.z = lrelu(fmaf(v.z, scs[cb + 2], shs[cb + 2])); \
            v.w = lrelu(fmaf(v.w, scs[cb + 3], shs[cb + 3])); \
            __nv_bfloat16 hx = __float2bfloat16(v.x); \
            __nv_bfloat16 hy = __float2bfloat16(v.y); \
            __nv_bfloat16 hz = __float2bfloat16(v.z); \
            __nv_bfloat16 hw = __float2bfloat16(v.w); \
            __nv_bfloat16 lx = __float2bfloat16(v.x - __bfloat162float(hx)); \
            __nv_bfloat16 ly = __float2bfloat16(v.y - __bfloat162float(hy)); \
            __nv_bfloat16 lz = __float2bfloat16(v.z - __bfloat162float(hz)); \
            __nv_bfloat16 lw = __float2bfloat16(v.w - __bfloat162float(hw)); \
            int di = row * 40 + c4 * 4; \
            *reinterpret_cast<__nv_bfloat162*>(Ah_ + di)     = __halves2bfloat162(hx, hy); \
            *reinterpret_cast<__nv_bfloat162*>(Ah_ + di + 2) = __halves2bfloat162(hz, hw); \
            *reinterpret_cast<__nv_bfloat162*>(Al_ + di)     = __halves2bfloat162(lx, ly); \
            *reinterpret_cast<__nv_bfloat162*>(Al_ + di + 2) = __halves2bfloat162(lz, lw); \
        } \
    } while (0)

#define LOADB(bufi, step) do { \
        int ci0_ = (step) * 32; \
        __nv_bfloat16* Bh_ = sm + (bufi) * 4 * TILEB + 2 * TILEB; \
        __nv_bfloat16* Bl_ = Bh_ + TILEB; \
        _Pragma("unroll") \
        for (int u = 0; u < 4; u++) { \
            int fi = u * 256 + tid; \
            int bsel = fi >> 9; \
            int rem = fi & 511; \
            int row = rem >> 2, gg = rem & 3; \
            const __nv_bfloat16* src = (bsel ? wwlo : wwhi) + \
                (size_t)(n0 + row) * KCI + ci0_ + gg * 8; \
            __nv_bfloat16* dstp = (bsel ? Bl_ : Bh_) + row * 40 + gg * 8; \
            cp_async16((uint32_t)__cvta_generic_to_shared(dstp), src); \
        } \
        asm volatile("cp.async.commit_group;" ::: "memory"); \
    } while (0)

    LOADA(0);
    STOREA(0, 0);
    LOADB(0, 0);

    for (int i = 0; i < 50; i++) {
        int buf = i & 1;
        if (i < 49) LOADA(i + 1);
        asm volatile("cp.async.wait_group 0;" ::: "memory");
        __syncthreads();
        if (i < 49) LOADB(buf ^ 1, i + 1);

        const __nv_bfloat16* Ahi = sm + buf * 4 * TILEB;
        const __nv_bfloat16* Alo = Ahi + TILEB;
        const __nv_bfloat16* Bhi = Ahi + 2 * TILEB;
        const __nv_bfloat16* Blo = Ahi + 3 * TILEB;
#pragma unroll
        for (int kt = 0; kt < 2; kt++) {
            uint32_t ahi[2][4], alo[2][4], bhi[8][2], blo[8][2];
            int abase = (wm * 32 + (lane >> 2)) * 40 + (lane & 3) * 2 + kt * 16;
#pragma unroll
            for (int mt = 0; mt < 2; mt++) {
                int o = abase + mt * 640;            // mt*16 rows * 40
                ahi[mt][0] = *reinterpret_cast<const uint32_t*>(Ahi + o);
                ahi[mt][1] = *reinterpret_cast<const uint32_t*>(Ahi + o + 320);
                ahi[mt][2] = *reinterpret_cast<const uint32_t*>(Ahi + o + 8);
                ahi[mt][3] = *reinterpret_cast<const uint32_t*>(Ahi + o + 328);
                alo[mt][0] = *reinterpret_cast<const uint32_t*>(Alo + o);
                alo[mt][1] = *reinterpret_cast<const uint32_t*>(Alo + o + 320);
                alo[mt][2] = *reinterpret_cast<const uint32_t*>(Alo + o + 8);
                alo[mt][3] = *reinterpret_cast<const uint32_t*>(Alo + o + 328);
            }
            int bbase = (wn * 64 + (lane >> 2)) * 40 + (lane & 3) * 2 + kt * 16;
#pragma unroll
            for (int nt = 0; nt < 8; nt++) {
                int o = bbase + nt * 320;            // nt*8 rows * 40
                bhi[nt][0] = *reinterpret_cast<const uint32_t*>(Bhi + o);
                bhi[nt][1] = *reinterpret_cast<const uint32_t*>(Bhi + o + 8);
                blo[nt][0] = *reinterpret_cast<const uint32_t*>(Blo + o);
                blo[nt][1] = *reinterpret_cast<const uint32_t*>(Blo + o + 8);
            }
#pragma unroll
            for (int nt = 0; nt < 8; nt++) {
                MMA_BF16(acc[0][nt], ahi[0], bhi[nt][0], bhi[nt][1]);
                MMA_BF16(acc[1][nt], ahi[1], bhi[nt][0], bhi[nt][1]);
            }
#pragma unroll
            for (int nt = 0; nt < 8; nt++) {
                MMA_BF16(acc[0][nt], ahi[0], blo[nt][0], blo[nt][1]);
                MMA_BF16(acc[1][nt], ahi[1], blo[nt][0], blo[nt][1]);
            }
#pragma unroll
            for (int nt = 0; nt < 8; nt++) {
                MMA_BF16(acc[0][nt], alo[0], bhi[nt][0], bhi[nt][1]);
                MMA_BF16(acc[1][nt], alo[1], bhi[nt][0], bhi[nt][1]);
            }
        }
        if (i < 49) STOREA(buf ^ 1, i + 1);
    }

#pragma unroll
    for (int mt = 0; mt < 2; mt++) {
#pragma unroll
        for (int nt = 0; nt < 8; nt++) {
            int row = m0 + wm * 32 + mt * 16 + (lane >> 2);
            int col = n0 + wn * 64 + nt * 8 + ((lane & 3) << 1);
            float2 v0 = make_float2(acc[mt][nt][0], acc[mt][nt][1]);
            float2 v1 = make_float2(acc[mt][nt][2], acc[mt][nt][3]);
            *reinterpret_cast<float2*>(y + (size_t)row * NW + col) = v0;
            *reinterpret_cast<float2*>(y + (size_t)(row + 8) * NW + col) = v1;
        }
    }
#undef LOADA
#undef STOREA
#undef LOADB
}

// ---------------------------------------------------------------------------
// K4: shift-add epilogue + fused per-channel stats.
// ---------------------------------------------------------------------------
__global__ __launch_bounds__(256) void shiftadd(
    const float* __restrict__ y, const float* __restrict__ cb1,
    float* __restrict__ w1o, float* __restrict__ part) {
    __shared__ float t[128 * 65];
    int tid = threadIdx.x;
    int b = blockIdx.y;
    int f0 = blockIdx.x * 64;
    for (int i = tid; i < 8192; i += 256) {
        int o = i & 127, ff = i >> 7;
        int f = f0 + ff, m = b * 256 + f;
        float val = __ldg(cb1 + o) + y[(size_t)m * NW + 128 + o];
        if (f > 0)   val += y[(size_t)(m - 1) * NW + o];
        if (f < 255) val += y[(size_t)(m + 1) * NW + 256 + o];
        t[o * 65 + ff] = val;
    }
    __syncthreads();
    for (int i = tid; i < 8192; i += 256) {
        int ff = i & 63, o = i >> 6;
        w1o[(size_t)(b * 128 + o) * 256 + f0 + ff] = t[o * 65 + ff];
    }
    if (tid < 128) {
        float S = 0.f, Q = 0.f;
#pragma unroll 8
        for (int k = 0; k < 64; k++) {
            float v = t[tid * 65 + k];
            S += v; Q += v * v;
        }
        int blk = blockIdx.y * 4 + blockIdx.x;
        part[tid * 256 + blk] = S;
        part[32768 + tid * 256 + blk] = Q;
    }
}

// ---------------------------------------------------------------------------
// K6: Conv2 (1x1, 128->64) with bnC1+lrelu fused at load + partial stats.
// ---------------------------------------------------------------------------
__global__ __launch_bounds__(256) void conv2_kernel(
    const float* __restrict__ w1o, const float* __restrict__ cw2,
    const float* __restrict__ cb2, const float* __restrict__ sc,
    const float* __restrict__ sh, float* __restrict__ vout,
    float* __restrict__ part) {
    __shared__ __align__(16) float Us[64 * 64];
    __shared__ __align__(16) float Ws2[64 * 64];
    int tid = threadIdx.x;
    int b = blockIdx.y;
    int f0 = blockIdx.x * 64;
    int fth = tid & 15, oth = tid >> 4;
    float acc[4][4] = {};

    for (int ci0 = 0; ci0 < 128; ci0 += 64) {
        for (int i = tid; i < 4096; i += 256) {
            int cc = i >> 6, ffi = i & 63;
            float raw = w1o[(size_t)(b * 128 + ci0 + cc) * 256 + f0 + ffi];
            float v = fmaf(raw, __ldg(sc + ci0 + cc), __ldg(sh + ci0 + cc));
            Us[i] = lrelu(v);
        }
        for (int i = tid; i < 4096; i += 256) {
            int o = i & 63, cc = i >> 6;
            Ws2[cc * 64 + o] = cw2[o * 128 + ci0 + cc];
        }
        __syncthreads();
#pragma unroll 8
        for (int cc = 0; cc < 64; cc++) {
            float4 iv = *reinterpret_cast<const float4*>(Us + cc * 64 + fth * 4);
            float4 wv = *reinterpret_cast<const float4*>(Ws2 + cc * 64 + oth * 4);
            acc[0][0] = fmaf(wv.x, iv.x, acc[0][0]); acc[0][1] = fmaf(wv.x, iv.y, acc[0][1]);
            acc[0][2] = fmaf(wv.x, iv.z, acc[0][2]); acc[0][3] = fmaf(wv.x, iv.w, acc[0][3]);
            acc[1][0] = fmaf(wv.y, iv.x, acc[1][0]); acc[1][1] = fmaf(wv.y, iv.y, acc[1][1]);
            acc[1][2] = fmaf(wv.y, iv.z, acc[1][2]); acc[1][3] = fmaf(wv.y, iv.w, acc[1][3]);
            acc[2][0] = fmaf(wv.z, iv.x, acc[2][0]); acc[2][1] = fmaf(wv.z, iv.y, acc[2][1]);
            acc[2][2] = fmaf(wv.z, iv.z, acc[2][2]); acc[2][3] = fmaf(wv.z, iv.w, acc[2][3]);
            acc[3][0] = fmaf(wv.w, iv.x, acc[3][0]); acc[3][1] = fmaf(wv.w, iv.y, acc[3][1]);
            acc[3][2] = fmaf(wv.w, iv.z, acc[3][2]); acc[3][3] = fmaf(wv.w, iv.w, acc[3][3]);
        }
        __syncthreads();
    }

    float* reds = Us;
    float* redq = Ws2;
#pragma unroll
    for (int i = 0; i < 4; i++) {
        int o = oth * 4 + i;
        float bias = __ldg(cb2 + o);
        float s = 0.f, q = 0.f;
#pragma unroll
        for (int j2 = 0; j2 < 4; j2++) {
            float r = acc[i][j2] + bias;
            vout[(size_t)(b * 64 + o) * 256 + f0 + fth * 4 + j2] = r;
            s += r; q += r * r;
        }
        reds[o * 17 + fth] = s;
        redq[o * 17 + fth] = q;
    }
    __syncthreads();
    if (tid < 64) {
        float S = 0.f, Q = 0.f;
#pragma unroll
        for (int t = 0; t < 16; t++) { S += reds[tid * 17 + t]; Q += redq[tid * 17 + t]; }
        int blk = blockIdx.y * 4 + blockIdx.x;
        part[tid * 256 + blk] = S;
        part[16384 + tid * 256 + blk] = Q;
    }
}

// ---------------------------------------------------------------------------
// K7: final BN + LReLU + transpose (B,64,256) -> (B,256,64)
// ---------------------------------------------------------------------------
__global__ __launch_bounds__(256) void final_kernel(
    const float* __restrict__ v, const float* __restrict__ sc,
    const float* __restrict__ sh, float* __restrict__ out) {
    __shared__ float s[64 * 65];
    int tid = threadIdx.x;
    int b = blockIdx.y;
    int f0 = blockIdx.x * 64;
    for (int i = tid; i < 4096; i += 256) {
        int o = i >> 6, ffi = i & 63;
        s[o * 65 + ffi] = v[(size_t)(b * 64 + o) * 256 + f0 + ffi];
    }
    __syncthreads();
    for (int i = tid; i < 4096; i += 256) {
        int ffi = i >> 6, o = i & 63;
        float val = fmaf(s[o * 65 + ffi], __ldg(sc + o), __ldg(sh + o));
        out[(size_t)(b * 256 + f0 + ffi) * 64 + o] = lrelu(val);
    }
}

// ---------------------------------------------------------------------------
// Launch
// ---------------------------------------------------------------------------
extern "C" void kernel_launch(void* const* d_in, const int* in_sizes, int n_in,
                              void* d_out, int out_size) {
    const float* x   = (const float*)d_in[0];
    const float* W1  = (const float*)d_in[4];
    const float* b1  = (const float*)d_in[5];
    const float* g1  = (const float*)d_in[6];
    const float* be1 = (const float*)d_in[7];
    const float* W2  = (const float*)d_in[8];
    const float* b2  = (const float*)d_in[9];
    const float* g2  = (const float*)d_in[10];
    const float* be2 = (const float*)d_in[11];
    const float* cw1 = (const float*)d_in[12];
    const float* cb1 = (const float*)d_in[13];
    const float* cg1 = (const float*)d_in[14];
    const float* cbe1= (const float*)d_in[15];
    const float* cw2 = (const float*)d_in[16];
    const float* cb2 = (const float*)d_in[17];
    const float* cg2 = (const float*)d_in[18];
    const float* cbe2= (const float*)d_in[19];
    float* out = (float*)d_out;

    float *z2, *y, *w2h, *w2l, *w1o, *v, *p1, *p2, *pC1, *pC2;
    __nv_bfloat16 *whi, *wlo;
    float *s1, *h1, *s2, *h2, *sC1, *hC1, *sC2, *hC2;
    cudaGetSymbolAddress((void**)&z2,  g_z2);
    cudaGetSymbolAddress((void**)&y,   g_y);
    cudaGetSymbolAddress((void**)&whi, g_wwhi);
    cudaGetSymbolAddress((void**)&wlo, g_wwlo);
    cudaGetSymbolAddress((void**)&w2h, g_w2hi);
    cudaGetSymbolAddress((void**)&w2l, g_w2lo);
    cudaGetSymbolAddress((void**)&w1o, g_w1out);
    cudaGetSymbolAddress((void**)&v,   g_v);
    cudaGetSymbolAddress((void**)&p1,  g_p1);
    cudaGetSymbolAddress((void**)&p2,  g_p2);
    cudaGetSymbolAddress((void**)&pC1, g_pC1);
    cudaGetSymbolAddress((void**)&pC2, g_pC2);
    cudaGetSymbolAddress((void**)&s1,  g_scale1);
    cudaGetSymbolAddress((void**)&h1,  g_shift1);
    cudaGetSymbolAddress((void**)&s2,  g_scale2);
    cudaGetSymbolAddress((void**)&h2,  g_shift2);
    cudaGetSymbolAddress((void**)&sC1, g_scaleC1);
    cudaGetSymbolAddress((void**)&hC1, g_shiftC1);
    cudaGetSymbolAddress((void**)&sC2, g_scaleC2);
    cudaGetSymbolAddress((void**)&hC2, g_shiftC2);

    cudaFuncSetAttribute(conv1_mma, cudaFuncAttributeMaxDynamicSharedMemorySize, CM_BYTES);
    cudaFuncSetAttribute(gcn2_mma,  cudaFuncAttributeMaxDynamicSharedMemorySize, G2_BYTES);

    const float invN_nodes = 1.f / (float)NNODES;
    const float invN_bf    = 1.f / (float)(BB * FF);

    prep<<<2416, 256>>>(cw1, W2, whi, wlo, w2h, w2l);                          // 0
    gcn1_stats<<<1024, 256>>>(x, W1, b1, p1);                                  // 1
    bn_final<<<64, 256>>>(p1, 1024, 64, g1, be1, invN_nodes, s1, h1);          // 2
    gcn2_mma<<<6400, 256, G2_BYTES>>>(x, W1, b1, s1, h1, w2h, w2l, b2, p2, z2);// 3
    bn_final<<<64, 256>>>(p2, 6400, 64, g2, be2, invN_nodes, s2, h2);          // 4
    conv1_mma<<<dim3(3, 128), 256, CM_BYTES>>>(z2, whi, wlo, s2, h2, y);       // 5  <- ncu
    shiftadd<<<dim3(4, BB), 256>>>(y, cb1, w1o, pC1);                          // 6
    bn_final<<<128, 256>>>(pC1, 256, 128, cg1, cbe1, invN_bf, sC1, hC1);       // 7
    conv2_kernel<<<dim3(4, BB), 256>>>(w1o, cw2, cb2, sC1, hC1, v, pC2);       // 8
    bn_final<<<64, 256>>>(pC2, 256, 64, cg2, cbe2, invN_bf, sC2, hC2);         // 9
    final_kernel<<<dim3(4, BB), 256>>>(v, sC2, hC2, out);                      // 10
}

// round 12
// speedup vs baseline: 1.7038x; 1.3588x over previous
#include <cuda_runtime.h>
#include <cuda_bf16.h>
#include <cstdint>

#define BB 64
#define FF 256
#define JJ 25
#define FILT 64
#define C1 128
#define NNODES (BB * FF * JJ)              // 409600
#define NE (NNODES * FILT)                 // 26214400
#define MTOT (BB * FF)                     // 16384
#define NW 384
#define KCI 1600
#define EPSV 1e-5f

// ---------------------------------------------------------------------------
// Scratch
// ---------------------------------------------------------------------------
__device__ float g_z2[NE];                 // GCN2 pre-BN output [node][c]
__device__ float g_y[MTOT * NW];           // conv1 GEMM output (pre shift-add)
__device__ __nv_bfloat16 g_wwhi[NW * KCI]; // tap-split conv1 weights, bf16 hi
__device__ __nv_bfloat16 g_wwlo[NW * KCI]; // bf16 lo residual
__device__ __nv_bfloat16 g_w2hb[FILT * FILT]; // W2 split bf16, [n_out][k_in]
__device__ __nv_bfloat16 g_w2lb[FILT * FILT];
__device__ float g_w1out[BB * C1 * FF];    // conv1 raw output (pre-BN)
__device__ float g_v[BB * FILT * FF];      // conv2 raw output (pre-BN)
__device__ float g_p1[2 * 64 * 1024];
__device__ float g_p2[2 * 64 * 3200];
__device__ float g_pC1[2 * 128 * 256];
__device__ float g_pC2[2 * 64 * 256];
__device__ float g_scale1[64], g_shift1[64];
__device__ float g_scale2[64], g_shift2[64];
__device__ float g_scaleC1[128], g_shiftC1[128];
__device__ float g_scaleC2[64], g_shiftC2[64];

__device__ __forceinline__ float dinvf(int j) {
    return (j == 0 || j == JJ - 1) ? 0.70710678118654752f : 0.57735026918962576f;
}
__device__ __forceinline__ float lrelu(float v) { return v >= 0.f ? v : 0.2f * v; }

#define MMA_BF16(d, av, b0, b1) \
    asm volatile("mma.sync.aligned.m16n8k16.row.col.f32.bf16.bf16.f32 " \
        "{%0,%1,%2,%3}, {%4,%5,%6,%7}, {%8,%9}, {%0,%1,%2,%3};" \
        : "+f"((d)[0]), "+f"((d)[1]), "+f"((d)[2]), "+f"((d)[3]) \
        : "r"((av)[0]), "r"((av)[1]), "r"((av)[2]), "r"((av)[3]), \
          "r"(b0), "r"(b1))

__device__ __forceinline__ void cp_async16(uint32_t saddr, const void* g) {
    asm volatile("cp.async.cg.shared.global [%0], [%1], 16;" :: "r"(saddr), "l"(g) : "memory");
}

// ---------------------------------------------------------------------------
// K0: merged prep.
//  blocks [0,2400): conv1 weights bf16-split
//  blocks [2400,2416): W2 bf16-split transposed: w2hb/lb[n*64+k] from W2[k*64+n]
// ---------------------------------------------------------------------------
__global__ __launch_bounds__(256) void prep(
    const float* __restrict__ cw1, const float* __restrict__ W2,
    __nv_bfloat16* __restrict__ whi, __nv_bfloat16* __restrict__ wlo,
    __nv_bfloat16* __restrict__ w2h, __nv_bfloat16* __restrict__ w2l) {
    int bid = blockIdx.x;
    if (bid < 2400) {
        int idx = bid * 256 + threadIdx.x;        // < 614400 exactly
        int n = idx / KCI, ci = idx - n * KCI;
        int k = n >> 7, o = n & 127;
        float w = cw1[(size_t)o * 4800 + ci * 3 + k];
        __nv_bfloat16 hb = __float2bfloat16(w);
        whi[idx] = hb;
        wlo[idx] = __float2bfloat16(w - __bfloat162float(hb));
    } else {
        int i = (bid - 2400) * 256 + threadIdx.x; // < 4096
        int n = i >> 6, k = i & 63;
        float w = W2[k * 64 + n];
        __nv_bfloat16 hb = __float2bfloat16(w);
        w2h[i] = hb;
        w2l[i] = __float2bfloat16(w - __bfloat162float(hb));
    }
}

// ---------------------------------------------------------------------------
// K1: GCN1 stats only, with xeff precompute. Block = 16 graphs (400 nodes).
// ---------------------------------------------------------------------------
__global__ __launch_bounds__(256) void gcn1_stats(
    const float* __restrict__ x, const float* __restrict__ W1,
    const float* __restrict__ b1, float* __restrict__ part) {
    __shared__ float xs[1200], xef[1200], W1s[192], b1s[64], ss[256], qq[256];
    int tid = threadIdx.x;
    if (tid < 192) W1s[tid] = W1[tid];
    if (tid < 64) b1s[tid] = b1[tid];
    int base = blockIdx.x * 1200;
    for (int i = tid; i < 1200; i += 256) xs[i] = x[base + i];
    __syncthreads();
    for (int i = tid; i < 400; i += 256) {
        int j = i % 25;
        float dj = dinvf(j);
        float cm = (j > 0) ? dinvf(j - 1) : 0.f;
        float cp = (j < 24) ? dinvf(j + 1) : 0.f;
        int im = (i > 0) ? i - 1 : 0, ip = (i < 399) ? i + 1 : 399;
#pragma unroll
        for (int d = 0; d < 3; d++)
            xef[i * 3 + d] = dj * (dj * xs[i * 3 + d] + cm * xs[im * 3 + d] + cp * xs[ip * 3 + d]);
    }
    __syncthreads();

    int c = tid & 63, sub = tid >> 6;
    float w0 = W1s[c], w1 = W1s[64 + c], w2 = W1s[128 + c], bb = b1s[c];
    float s = 0.f, q = 0.f;
    for (int it = 0; it < 100; it++) {
        int nl = it * 4 + sub;
        float z = xef[nl * 3] * w0 + xef[nl * 3 + 1] * w1 + xef[nl * 3 + 2] * w2 + bb;
        s += z; q += z * z;
    }
    ss[tid] = s; qq[tid] = q;
    __syncthreads();
    if (tid < 64) {
        s = ss[tid] + ss[tid + 64] + ss[tid + 128] + ss[tid + 192];
        q = qq[tid] + qq[tid + 64] + qq[tid + 128] + qq[tid + 192];
        part[tid * 1024 + blockIdx.x] = s;
        part[65536 + tid * 1024 + blockIdx.x] = q;
    }
}

// ---------------------------------------------------------------------------
// BN finalize: part layout S at [c*R + r], Q at [C*R + c*R + r].
// ---------------------------------------------------------------------------
__global__ __launch_bounds__(256) void bn_final(
    const float* __restrict__ part, int R, int C,
    const float* __restrict__ g, const float* __restrict__ be, float invN,
    float* __restrict__ scale, float* __restrict__ shift) {
    int c = blockIdx.x, tid = threadIdx.x;
    __shared__ float ss[256], qq[256];
    const float* pS = part + (size_t)c * R;
    const float* pQ = part + (size_t)C * R + (size_t)c * R;
    float s = 0.f, q = 0.f;
    for (int r = tid; r < R; r += 256) { s += pS[r]; q += pQ[r]; }
    ss[tid] = s; qq[tid] = q;
    __syncthreads();
    for (int o = 128; o > 0; o >>= 1) {
        if (tid < o) { ss[tid] += ss[tid + o]; qq[tid] += qq[tid + o]; }
        __syncthreads();
    }
    if (tid == 0) {
        float m = ss[0] * invN;
        float var = qq[0] * invN - m * m;
        float rstd = rsqrtf(var + EPSV);
        float sc = g[c] * rstd;
        scale[c] = sc;
        shift[c] = be[c] - m * sc;
    }
}

// ---------------------------------------------------------------------------
// K2: gcn2 via bf16x3 MMA. Block = 128 nodes (3200 blocks).
// A/B tiles hold full K=64 -> bf16 row stride 72 (64 + 8 pad, conflict-free).
// Dynamic smem layout (bytes):
//   HBE @ 0     : 130*68*4 = 35360 (fp32 h, stride 68)
//   AHI @ 35360 : 128*72*2 = 18432
//   ALO @ 53792 : 18432
//   BHI @ 72224 : 64*72*2  = 9216
//   BLO @ 81440 : 9216      -> total 90656
// ---------------------------------------------------------------------------
#define G2S 72
#define G2_BYTES 90656

__global__ __launch_bounds__(256) void gcn2_mma(
    const float* __restrict__ x, const float* __restrict__ W1,
    const float* __restrict__ b1, const float* __restrict__ sc1,
    const float* __restrict__ sh1, const __nv_bfloat16* __restrict__ w2hb,
    const __nv_bfloat16* __restrict__ w2lb, const float* __restrict__ b2,
    float* __restrict__ part, float* __restrict__ z2b) {
    extern __shared__ __align__(16) char dynraw[];
    float* hbe = reinterpret_cast<float*>(dynraw);
    __nv_bfloat16* Ahi = reinterpret_cast<__nv_bfloat16*>(dynraw + 35360);
    __nv_bfloat16* Alo = reinterpret_cast<__nv_bfloat16*>(dynraw + 53792);
    __nv_bfloat16* Bhi = reinterpret_cast<__nv_bfloat16*>(dynraw + 72224);
    __nv_bfloat16* Blo = reinterpret_cast<__nv_bfloat16*>(dynraw + 81440);
    __shared__ __align__(16) float xs[396], xef[520];
    __shared__ __align__(16) float W1s[192], b1s[64], sc1s[64], sh1s[64], b2s[64];
    __shared__ float redS[256], redQ[256];

    int tid = threadIdx.x, lane = tid & 31, wid = tid >> 5;
    int n0 = blockIdx.x * 128;

    if (tid < 192) W1s[tid] = W1[tid];
    if (tid < 64) {
        b1s[tid] = b1[tid]; sc1s[tid] = sc1[tid];
        sh1s[tid] = sh1[tid]; b2s[tid] = b2[tid];
    }
    // Load 396 floats (132 nodes: n0-2 .. n0+129). The l=129 xeff read
    // touches xs[393..395]; a 393 bound would leave them uninitialized.
    for (int i = tid; i < 396; i += 256) {
        int gi = (n0 - 2) * 3 + i;
        xs[i] = (gi >= 0 && gi < NNODES * 3) ? x[gi] : 0.f;
    }
    // B tiles: 64 rows x 64 k, bf16 pairs, stride 72
    for (int i = tid; i < 2048; i += 256) {
        int n = i >> 5, kk = i & 31;
        *reinterpret_cast<uint32_t*>(Bhi + n * G2S + kk * 2) =
            *reinterpret_cast<const uint32_t*>(w2hb + n * 64 + kk * 2);
        *reinterpret_cast<uint32_t*>(Blo + n * G2S + kk * 2) =
            *reinterpret_cast<const uint32_t*>(w2lb + n * 64 + kk * 2);
    }
    __syncthreads();

    // Phase 0: xeff[l] for l in 0..129 (node m = n0-1+l); xs row = l+1
    for (int i = tid; i < 130; i += 256) {
        int m = n0 - 1 + i;
        float e0 = 0.f, e1 = 0.f, e2 = 0.f;
        if (m >= 0 && m < NNODES) {
            int j = m % 25;
            float dj = dinvf(j);
            float cm = (j > 0) ? dinvf(j - 1) : 0.f;
            float cp = (j < 24) ? dinvf(j + 1) : 0.f;
            const float* xc = xs + (i + 1) * 3;
            e0 = dj * (dj * xc[0] + cm * xc[-3] + cp * xc[3]);
            e1 = dj * (dj * xc[1] + cm * xc[-2] + cp * xc[4]);
            e2 = dj * (dj * xc[2] + cm * xc[-1] + cp * xc[5]);
        }
        xef[i * 4] = e0; xef[i * 4 + 1] = e1; xef[i * 4 + 2] = e2;
    }
    __syncthreads();

    // Phase A: h[130][68] = lrelu(bn1(xeff . W1 + b1)), float4 channels
    {
        const float4* W1s4 = reinterpret_cast<const float4*>(W1s);
        const float4* b4 = reinterpret_cast<const float4*>(b1s);
        const float4* sc4 = reinterpret_cast<const float4*>(sc1s);
        const float4* sh4 = reinterpret_cast<const float4*>(sh1s);
        for (int i = tid; i < 2080; i += 256) {
            int cg = i & 15, l = i >> 4;
            float e0 = xef[l * 4], e1 = xef[l * 4 + 1], e2 = xef[l * 4 + 2];
            float4 w0 = W1s4[cg], w1 = W1s4[16 + cg], w2 = W1s4[32 + cg];
            float4 bb = b4[cg], sv = sc4[cg], hv = sh4[cg];
            float4 z;
            z.x = e0 * w0.x + e1 * w1.x + e2 * w2.x + bb.x;
            z.y = e0 * w0.y + e1 * w1.y + e2 * w2.y + bb.y;
            z.z = e0 * w0.z + e1 * w1.z + e2 * w2.z + bb.z;
            z.w = e0 * w0.w + e1 * w1.w + e2 * w2.w + bb.w;
            z.x = lrelu(fmaf(z.x, sv.x, hv.x));
            z.y = lrelu(fmaf(z.y, sv.y, hv.y));
            z.z = lrelu(fmaf(z.z, sv.z, hv.z));
            z.w = lrelu(fmaf(z.w, sv.w, hv.w));
            *reinterpret_cast<float4*>(hbe + l * 68 + cg * 4) = z;
        }
    }
    __syncthreads();

    // Phase B: stencil over h + bf16 split -> A tiles (rows 0..127, l = nl+1)
    for (int i = tid; i < 2048; i += 256) {
        int cg = i & 15, nl = i >> 4;
        int m = n0 + nl, j = m % 25, l = nl + 1;
        float dj = dinvf(j);
        float cm = (j > 0) ? dinvf(j - 1) : 0.f;
        float cp = (j < 24) ? dinvf(j + 1) : 0.f;
        float4 hc = *reinterpret_cast<const float4*>(hbe + l * 68 + cg * 4);
        float4 hm = *reinterpret_cast<const float4*>(hbe + (l - 1) * 68 + cg * 4);
        float4 hp = *reinterpret_cast<const float4*>(hbe + (l + 1) * 68 + cg * 4);
        float4 v;
        v.x = dj * (dj * hc.x + cm * hm.x + cp * hp.x);
        v.y = dj * (dj * hc.y + cm * hm.y + cp * hp.y);
        v.z = dj * (dj * hc.z + cm * hm.z + cp * hp.z);
        v.w = dj * (dj * hc.w + cm * hm.w + cp * hp.w);
        __nv_bfloat16 hx = __float2bfloat16(v.x), hy = __float2bfloat16(v.y);
        __nv_bfloat16 hz = __float2bfloat16(v.z), hw = __float2bfloat16(v.w);
        __nv_bfloat16 lx = __float2bfloat16(v.x - __bfloat162float(hx));
        __nv_bfloat16 ly = __float2bfloat16(v.y - __bfloat162float(hy));
        __nv_bfloat16 lz = __float2bfloat16(v.z - __bfloat162float(hz));
        __nv_bfloat16 lw = __float2bfloat16(v.w - __bfloat162float(hw));
        int di = nl * G2S + cg * 4;
        *reinterpret_cast<__nv_bfloat162*>(Ahi + di)     = __halves2bfloat162(hx, hy);
        *reinterpret_cast<__nv_bfloat162*>(Ahi + di + 2) = __halves2bfloat162(hz, hw);
        *reinterpret_cast<__nv_bfloat162*>(Alo + di)     = __halves2bfloat162(lx, ly);
        *reinterpret_cast<__nv_bfloat162*>(Alo + di + 2) = __halves2bfloat162(lz, lw);
    }
    __syncthreads();

    // MMA: 8 warps = 4M x 2N; warp tile 32 rows x 32 cols; K=64 (4 kt).
    int wm = wid & 3, wn = wid >> 2;
    float acc[2][4][4];
#pragma unroll
    for (int mt = 0; mt < 2; mt++)
#pragma unroll
        for (int nt = 0; nt < 4; nt++)
#pragma unroll
            for (int u = 0; u < 4; u++) acc[mt][nt][u] = 0.f;

#pragma unroll
    for (int kt = 0; kt < 4; kt++) {
        uint32_t ahi[2][4], alo[2][4], bhi[4][2], blo[4][2];
        int abase = (wm * 32 + (lane >> 2)) * G2S + (lane & 3) * 2 + kt * 16;
#pragma unroll
        for (int mt = 0; mt < 2; mt++) {
            int o = abase + mt * 16 * G2S;
            ahi[mt][0] = *reinterpret_cast<const uint32_t*>(Ahi + o);
            ahi[mt][1] = *reinterpret_cast<const uint32_t*>(Ahi + o + 8 * G2S);
            ahi[mt][2] = *reinterpret_cast<const uint32_t*>(Ahi + o + 8);
            ahi[mt][3] = *reinterpret_cast<const uint32_t*>(Ahi + o + 8 * G2S + 8);
            alo[mt][0] = *reinterpret_cast<const uint32_t*>(Alo + o);
            alo[mt][1] = *reinterpret_cast<const uint32_t*>(Alo + o + 8 * G2S);
            alo[mt][2] = *reinterpret_cast<const uint32_t*>(Alo + o + 8);
            alo[mt][3] = *reinterpret_cast<const uint32_t*>(Alo + o + 8 * G2S + 8);
        }
        int bbase = (wn * 32 + (lane >> 2)) * G2S + (lane & 3) * 2 + kt * 16;
#pragma unroll
        for (int nt = 0; nt < 4; nt++) {
            int o = bbase + nt * 8 * G2S;
            bhi[nt][0] = *reinterpret_cast<const uint32_t*>(Bhi + o);
            bhi[nt][1] = *reinterpret_cast<const uint32_t*>(Bhi + o + 8);
            blo[nt][0] = *reinterpret_cast<const uint32_t*>(Blo + o);
            blo[nt][1] = *reinterpret_cast<const uint32_t*>(Blo + o + 8);
        }
#pragma unroll
        for (int nt = 0; nt < 4; nt++) {
            MMA_BF16(acc[0][nt], ahi[0], bhi[nt][0], bhi[nt][1]);
            MMA_BF16(acc[1][nt], ahi[1], bhi[nt][0], bhi[nt][1]);
        }
#pragma unroll
        for (int nt = 0; nt < 4; nt++) {
            MMA_BF16(acc[0][nt], ahi[0], blo[nt][0], blo[nt][1]);
            MMA_BF16(acc[1][nt], ahi[1], blo[nt][0], blo[nt][1]);
        }
#pragma unroll
        for (int nt = 0; nt < 4; nt++) {
            MMA_BF16(acc[0][nt], alo[0], bhi[nt][0], bhi[nt][1]);
            MMA_BF16(acc[1][nt], alo[1], bhi[nt][0], bhi[nt][1]);
        }
    }

    // Epilogue: bias + z2 store + per-channel partial stats
#pragma unroll
    for (int nt = 0; nt < 4; nt++) {
        int c0 = wn * 32 + nt * 8 + ((lane & 3) << 1);
        float bb0 = b2s[c0], bb1 = b2s[c0 + 1];
        float s0 = 0.f, q0 = 0.f, s1 = 0.f, q1 = 0.f;
#pragma unroll
        for (int mt = 0; mt < 2; mt++) {
            int row = n0 + wm * 32 + mt * 16 + (lane >> 2);
            float u0 = acc[mt][nt][0] + bb0, u1 = acc[mt][nt][1] + bb1;
            float u2 = acc[mt][nt][2] + bb0, u3 = acc[mt][nt][3] + bb1;
            *reinterpret_cast<float2*>(z2b + (size_t)row * 64 + c0) = make_float2(u0, u1);
            *reinterpret_cast<float2*>(z2b + (size_t)(row + 8) * 64 + c0) = make_float2(u2, u3);
            s0 += u0 + u2; q0 += u0 * u0 + u2 * u2;
            s1 += u1 + u3; q1 += u1 * u1 + u3 * u3;
        }
#pragma unroll
        for (int o = 4; o < 32; o <<= 1) {
            s0 += __shfl_xor_sync(0xffffffffu, s0, o);
            q0 += __shfl_xor_sync(0xffffffffu, q0, o);
            s1 += __shfl_xor_sync(0xffffffffu, s1, o);
            q1 += __shfl_xor_sync(0xffffffffu, q1, o);
        }
        if (lane < 4) {
            redS[c0 * 4 + wm] = s0; redS[(c0 + 1) * 4 + wm] = s1;
            redQ[c0 * 4 + wm] = q0; redQ[(c0 + 1) * 4 + wm] = q1;
        }
    }
    __syncthreads();
    if (tid < 64) {
        float S = redS[tid * 4] + redS[tid * 4 + 1] + redS[tid * 4 + 2] + redS[tid * 4 + 3];
        float Q = redQ[tid * 4] + redQ[tid * 4 + 1] + redQ[tid * 4 + 2] + redQ[tid * 4 + 3];
        part[tid * 3200 + blockIdx.x] = S;
        part[204800 + tid * 3200 + blockIdx.x] = Q;
    }
}

// ---------------------------------------------------------------------------
// K3: conv1 as bf16x3 mma.sync GEMM (m16n8k16). (unchanged, passing; K-slice
// is 32 so stride 40 is correct here.)
// ---------------------------------------------------------------------------
#define TILEB 5120                                   // 128*40 bf16
#define CM_BYTES (8 * TILEB * 2)                     // 81920

__global__ __launch_bounds__(256) void conv1_mma(
    const float* __restrict__ z2b, const __nv_bfloat16* __restrict__ wwhi,
    const __nv_bfloat16* __restrict__ wwlo, const float* __restrict__ sc,
    const float* __restrict__ sh, float* __restrict__ y) {
    extern __shared__ __align__(16) char dynraw[];
    __nv_bfloat16* sm = reinterpret_cast<__nv_bfloat16*>(dynraw);
    __shared__ float scs[64], shs[64];
    int tid = threadIdx.x, lane = tid & 31, wid = tid >> 5;
    int wm = wid & 3, wn = wid >> 2;
    int m0 = blockIdx.y * 128, n0 = blockIdx.x * 128;
    if (tid < 64) { scs[tid] = sc[tid]; shs[tid] = sh[tid]; }
    __syncthreads();

    float acc[2][8][4];
#pragma unroll
    for (int mt = 0; mt < 2; mt++)
#pragma unroll
        for (int nt = 0; nt < 8; nt++)
#pragma unroll
            for (int u = 0; u < 4; u++) acc[mt][nt][u] = 0.f;

    float4 aReg[4];

#define LOADA(step) do { \
        int ci0_ = (step) * 32; \
        _Pragma("unroll") \
        for (int u = 0; u < 4; u++) { \
            int fi = u * 256 + tid; \
            int row = fi >> 3, c4 = fi & 7; \
            aReg[u] = *reinterpret_cast<const float4*>( \
                z2b + (size_t)(m0 + row) * KCI + ci0_ + c4 * 4); \
        } \
    } while (0)

#define STOREA(bufi, step) do { \
        int ci0_ = (step) * 32; \
        __nv_bfloat16* Ah_ = sm + (bufi) * 4 * TILEB; \
        __nv_bfloat16* Al_ = Ah_ + TILEB; \
        _Pragma("unroll") \
        for (int u = 0; u < 4; u++) { \
            int fi = u * 256 + tid; \
            int row = fi >> 3, c4 = fi & 7; \
            int cb = (ci0_ + c4 * 4) & 63; \
            float4 v = aReg[u]; \
            v.x = lrelu(fmaf(v.x, scs[cb],     shs[cb])); \
            v.y = lrelu(fmaf(v.y, scs[cb + 1], shs[cb + 1])); \
            v.z = lrelu(fmaf(v.z, scs[cb + 2], shs[cb + 2])); \
            v.w = lrelu(fmaf(v.w, scs[cb + 3], shs[cb + 3])); \
            __nv_bfloat16 hx = __float2bfloat16(v.x); \
            __nv_bfloat16 hy = __float2bfloat16(v.y); \
            __nv_bfloat16 hz = __float2bfloat16(v.z); \
            __nv_bfloat16 hw = __float2bfloat16(v.w); \
            __nv_bfloat16 lx = __float2bfloat16(v.x - __bfloat162float(hx)); \
            __nv_bfloat16 ly = __float2bfloat16(v.y - __bfloat162float(hy)); \
            __nv_bfloat16 lz = __float2bfloat16(v.z - __bfloat162float(hz)); \
            __nv_bfloat16 lw = __float2bfloat16(v.w - __bfloat162float(hw)); \
            int di = row * 40 + c4 * 4; \
            *reinterpret_cast<__nv_bfloat162*>(Ah_ + di)     = __halves2bfloat162(hx, hy); \
            *reinterpret_cast<__nv_bfloat162*>(Ah_ + di + 2) = __halves2bfloat162(hz, hw); \
            *reinterpret_cast<__nv_bfloat162*>(Al_ + di)     = __halves2bfloat162(lx, ly); \
            *reinterpret_cast<__nv_bfloat162*>(Al_ + di + 2) = __halves2bfloat162(lz, lw); \
        } \
    } while (0)

#define LOADB(bufi, step) do { \
        int ci0_ = (step) * 32; \
        __nv_bfloat16* Bh_ = sm + (bufi) * 4 * TILEB + 2 * TILEB; \
        __nv_bfloat16* Bl_ = Bh_ + TILEB; \
        _Pragma("unroll") \
        for (int u = 0; u < 4; u++) { \
            int fi = u * 256 + tid; \
            int bsel = fi >> 9; \
            int rem = fi & 511; \
            int row = rem >> 2, gg = rem & 3; \
            const __nv_bfloat16* src = (bsel ? wwlo : wwhi) + \
                (size_t)(n0 + row) * KCI + ci0_ + gg * 8; \
            __nv_bfloat16* dstp = (bsel ? Bl_ : Bh_) + row * 40 + gg * 8; \
            cp_async16((uint32_t)__cvta_generic_to_shared(dstp), src); \
        } \
        asm volatile("cp.async.commit_group;" ::: "memory"); \
    } while (0)

    LOADA(0);
    STOREA(0, 0);
    LOADB(0, 0);

    for (int i = 0; i < 50; i++) {
        int buf = i & 1;
        if (i < 49) LOADA(i + 1);
        asm volatile("cp.async.wait_group 0;" ::: "memory");
        __syncthreads();
        if (i < 49) LOADB(buf ^ 1, i + 1);

        const __nv_bfloat16* Ahi = sm + buf * 4 * TILEB;
        const __nv_bfloat16* Alo = Ahi + TILEB;
        const __nv_bfloat16* Bhi = Ahi + 2 * TILEB;
        const __nv_bfloat16* Blo = Ahi + 3 * TILEB;
#pragma unroll
        for (int kt = 0; kt < 2; kt++) {
            uint32_t ahi[2][4], alo[2][4], bhi[8][2], blo[8][2];
            int abase = (wm * 32 + (lane >> 2)) * 40 + (lane & 3) * 2 + kt * 16;
#pragma unroll
            for (int mt = 0; mt < 2; mt++) {
                int o = abase + mt * 640;
                ahi[mt][0] = *reinterpret_cast<const uint32_t*>(Ahi + o);
                ahi[mt][1] = *reinterpret_cast<const uint32_t*>(Ahi + o + 320);
                ahi[mt][2] = *reinterpret_cast<const uint32_t*>(Ahi + o + 8);
                ahi[mt][3] = *reinterpret_cast<const uint32_t*>(Ahi + o + 328);
                alo[mt][0] = *reinterpret_cast<const uint32_t*>(Alo + o);
                alo[mt][1] = *reinterpret_cast<const uint32_t*>(Alo + o + 320);
                alo[mt][2] = *reinterpret_cast<const uint32_t*>(Alo + o + 8);
                alo[mt][3] = *reinterpret_cast<const uint32_t*>(Alo + o + 328);
            }
            int bbase = (wn * 64 + (lane >> 2)) * 40 + (lane & 3) * 2 + kt * 16;
#pragma unroll
            for (int nt = 0; nt < 8; nt++) {
                int o = bbase + nt * 320;
                bhi[nt][0] = *reinterpret_cast<const uint32_t*>(Bhi + o);
                bhi[nt][1] = *reinterpret_cast<const uint32_t*>(Bhi + o + 8);
                blo[nt][0] = *reinterpret_cast<const uint32_t*>(Blo + o);
                blo[nt][1] = *reinterpret_cast<const uint32_t*>(Blo + o + 8);
            }
#pragma unroll
            for (int nt = 0; nt < 8; nt++) {
                MMA_BF16(acc[0][nt], ahi[0], bhi[nt][0], bhi[nt][1]);
                MMA_BF16(acc[1][nt], ahi[1], bhi[nt][0], bhi[nt][1]);
            }
#pragma unroll
            for (int nt = 0; nt < 8; nt++) {
                MMA_BF16(acc[0][nt], ahi[0], blo[nt][0], blo[nt][1]);
                MMA_BF16(acc[1][nt], ahi[1], blo[nt][0], blo[nt][1]);
            }
#pragma unroll
            for (int nt = 0; nt < 8; nt++) {
                MMA_BF16(acc[0][nt], alo[0], bhi[nt][0], bhi[nt][1]);
                MMA_BF16(acc[1][nt], alo[1], bhi[nt][0], bhi[nt][1]);
            }
        }
        if (i < 49) STOREA(buf ^ 1, i + 1);
    }

#pragma unroll
    for (int mt = 0; mt < 2; mt++) {
#pragma unroll
        for (int nt = 0; nt < 8; nt++) {
            int row = m0 + wm * 32 + mt * 16 + (lane >> 2);
            int col = n0 + wn * 64 + nt * 8 + ((lane & 3) << 1);
            float2 v0 = make_float2(acc[mt][nt][0], acc[mt][nt][1]);
            float2 v1 = make_float2(acc[mt][nt][2], acc[mt][nt][3]);
            *reinterpret_cast<float2*>(y + (size_t)row * NW + col) = v0;
            *reinterpret_cast<float2*>(y + (size_t)(row + 8) * NW + col) = v1;
        }
    }
#undef LOADA
#undef STOREA
#undef LOADB
}

// ---------------------------------------------------------------------------
// K4: shift-add epilogue + fused per-channel stats.
// ---------------------------------------------------------------------------
__global__ __launch_bounds__(256) void shiftadd(
    const float* __restrict__ y, const float* __restrict__ cb1,
    float* __restrict__ w1o, float* __restrict__ part) {
    __shared__ float t[128 * 65];
    int tid = threadIdx.x;
    int b = blockIdx.y;
    int f0 = blockIdx.x * 64;
    for (int i = tid; i < 8192; i += 256) {
        int o = i & 127, ff = i >> 7;
        int f = f0 + ff, m = b * 256 + f;
        float val = __ldg(cb1 + o) + y[(size_t)m * NW + 128 + o];
        if (f > 0)   val += y[(size_t)(m - 1) * NW + o];
        if (f < 255) val += y[(size_t)(m + 1) * NW + 256 + o];
        t[o * 65 + ff] = val;
    }
    __syncthreads();
    for (int i = tid; i < 8192; i += 256) {
        int ff = i & 63, o = i >> 6;
        w1o[(size_t)(b * 128 + o) * 256 + f0 + ff] = t[o * 65 + ff];
    }
    if (tid < 128) {
        float S = 0.f, Q = 0.f;
#pragma unroll 8
        for (int k = 0; k < 64; k++) {
            float v = t[tid * 65 + k];
            S += v; Q += v * v;
        }
        int blk = blockIdx.y * 4 + blockIdx.x;
        part[tid * 256 + blk] = S;
        part[32768 + tid * 256 + blk] = Q;
    }
}

// ---------------------------------------------------------------------------
// K6: Conv2 (1x1, 128->64) with bnC1+lrelu fused at load + partial stats.
// ---------------------------------------------------------------------------
__global__ __launch_bounds__(256) void conv2_kernel(
    const float* __restrict__ w1o, const float* __restrict__ cw2,
    const float* __restrict__ cb2, const float* __restrict__ sc,
    const float* __restrict__ sh, float* __restrict__ vout,
    float* __restrict__ part) {
    __shared__ __align__(16) float Us[64 * 64];
    __shared__ __align__(16) float Ws2[64 * 64];
    int tid = threadIdx.x;
    int b = blockIdx.y;
    int f0 = blockIdx.x * 64;
    int fth = tid & 15, oth = tid >> 4;
    float acc[4][4] = {};

    for (int ci0 = 0; ci0 < 128; ci0 += 64) {
        for (int i = tid; i < 4096; i += 256) {
            int cc = i >> 6, ffi = i & 63;
            float raw = w1o[(size_t)(b * 128 + ci0 + cc) * 256 + f0 + ffi];
            float v = fmaf(raw, __ldg(sc + ci0 + cc), __ldg(sh + ci0 + cc));
            Us[i] = lrelu(v);
        }
        for (int i = tid; i < 4096; i += 256) {
            int o = i & 63, cc = i >> 6;
            Ws2[cc * 64 + o] = cw2[o * 128 + ci0 + cc];
        }
        __syncthreads();
#pragma unroll 8
        for (int cc = 0; cc < 64; cc++) {
            float4 iv = *reinterpret_cast<const float4*>(Us + cc * 64 + fth * 4);
            float4 wv = *reinterpret_cast<const float4*>(Ws2 + cc * 64 + oth * 4);
            acc[0][0] = fmaf(wv.x, iv.x, acc[0][0]); acc[0][1] = fmaf(wv.x, iv.y, acc[0][1]);
            acc[0][2] = fmaf(wv.x, iv.z, acc[0][2]); acc[0][3] = fmaf(wv.x, iv.w, acc[0][3]);
            acc[1][0] = fmaf(wv.y, iv.x, acc[1][0]); acc[1][1] = fmaf(wv.y, iv.y, acc[1][1]);
            acc[1][2] = fmaf(wv.y, iv.z, acc[1][2]); acc[1][3] = fmaf(wv.y, iv.w, acc[1][3]);
            acc[2][0] = fmaf(wv.z, iv.x, acc[2][0]); acc[2][1] = fmaf(wv.z, iv.y, acc[2][1]);
            acc[2][2] = fmaf(wv.z, iv.z, acc[2][2]); acc[2][3] = fmaf(wv.z, iv.w, acc[2][3]);
            acc[3][0] = fmaf(wv.w, iv.x, acc[3][0]); acc[3][1] = fmaf(wv.w, iv.y, acc[3][1]);
            acc[3][2] = fmaf(wv.w, iv.z, acc[3][2]); acc[3][3] = fmaf(wv.w, iv.w, acc[3][3]);
        }
        __syncthreads();
    }

    float* reds = Us;
    float* redq = Ws2;
#pragma unroll
    for (int i = 0; i < 4; i++) {
        int o = oth * 4 + i;
        float bias = __ldg(cb2 + o);
        float s = 0.f, q = 0.f;
#pragma unroll
        for (int j2 = 0; j2 < 4; j2++) {
            float r = acc[i][j2] + bias;
            vout[(size_t)(b * 64 + o) * 256 + f0 + fth * 4 + j2] = r;
            s += r; q += r * r;
        }
        reds[o * 17 + fth] = s;
        redq[o * 17 + fth] = q;
    }
    __syncthreads();
    if (tid < 64) {
        float S = 0.f, Q = 0.f;
#pragma unroll
        for (int t = 0; t < 16; t++) { S += reds[tid * 17 + t]; Q += redq[tid * 17 + t]; }
        int blk = blockIdx.y * 4 + blockIdx.x;
        part[tid * 256 + blk] = S;
        part[16384 + tid * 256 + blk] = Q;
    }
}

// ---------------------------------------------------------------------------
// K7: final BN + LReLU + transpose (B,64,256) -> (B,256,64)
// ---------------------------------------------------------------------------
__global__ __launch_bounds__(256) void final_kernel(
    const float* __restrict__ v, const float* __restrict__ sc,
    const float* __restrict__ sh, float* __restrict__ out) {
    __shared__ float s[64 * 65];
    int tid = threadIdx.x;
    int b = blockIdx.y;
    int f0 = blockIdx.x * 64;
    for (int i = tid; i < 4096; i += 256) {
        int o = i >> 6, ffi = i & 63;
        s[o * 65 + ffi] = v[(size_t)(b * 64 + o) * 256 + f0 + ffi];
    }
    __syncthreads();
    for (int i = tid; i < 4096; i += 256) {
        int ffi = i >> 6, o = i & 63;
        float val = fmaf(s[o * 65 + ffi], __ldg(sc + o), __ldg(sh + o));
        out[(size_t)(b * 256 + f0 + ffi) * 64 + o] = lrelu(val);
    }
}

// ---------------------------------------------------------------------------
// Launch
// ---------------------------------------------------------------------------
extern "C" void kernel_launch(void* const* d_in, const int* in_sizes, int n_in,
                              void* d_out, int out_size) {
    const float* x   = (const float*)d_in[0];
    const float* W1  = (const float*)d_in[4];
    const float* b1  = (const float*)d_in[5];
    const float* g1  = (const float*)d_in[6];
    const float* be1 = (const float*)d_in[7];
    const float* W2  = (const float*)d_in[8];
    const float* b2  = (const float*)d_in[9];
    const float* g2  = (const float*)d_in[10];
    const float* be2 = (const float*)d_in[11];
    const float* cw1 = (const float*)d_in[12];
    const float* cb1 = (const float*)d_in[13];
    const float* cg1 = (const float*)d_in[14];
    const float* cbe1= (const float*)d_in[15];
    const float* cw2 = (const float*)d_in[16];
    const float* cb2 = (const float*)d_in[17];
    const float* cg2 = (const float*)d_in[18];
    const float* cbe2= (const float*)d_in[19];
    float* out = (float*)d_out;

    float *z2, *y, *w1o, *v, *p1, *p2, *pC1, *pC2;
    __nv_bfloat16 *whi, *wlo, *w2h, *w2l;
    float *s1, *h1, *s2, *h2, *sC1, *hC1, *sC2, *hC2;
    cudaGetSymbolAddress((void**)&z2,  g_z2);
    cudaGetSymbolAddress((void**)&y,   g_y);
    cudaGetSymbolAddress((void**)&whi, g_wwhi);
    cudaGetSymbolAddress((void**)&wlo, g_wwlo);
    cudaGetSymbolAddress((void**)&w2h, g_w2hb);
    cudaGetSymbolAddress((void**)&w2l, g_w2lb);
    cudaGetSymbolAddress((void**)&w1o, g_w1out);
    cudaGetSymbolAddress((void**)&v,   g_v);
    cudaGetSymbolAddress((void**)&p1,  g_p1);
    cudaGetSymbolAddress((void**)&p2,  g_p2);
    cudaGetSymbolAddress((void**)&pC1, g_pC1);
    cudaGetSymbolAddress((void**)&pC2, g_pC2);
    cudaGetSymbolAddress((void**)&s1,  g_scale1);
    cudaGetSymbolAddress((void**)&h1,  g_shift1);
    cudaGetSymbolAddress((void**)&s2,  g_scale2);
    cudaGetSymbolAddress((void**)&h2,  g_shift2);
    cudaGetSymbolAddress((void**)&sC1, g_scaleC1);
    cudaGetSymbolAddress((void**)&hC1, g_shiftC1);
    cudaGetSymbolAddress((void**)&sC2, g_scaleC2);
    cudaGetSymbolAddress((void**)&hC2, g_shiftC2);

    cudaFuncSetAttribute(conv1_mma, cudaFuncAttributeMaxDynamicSharedMemorySize, CM_BYTES);
    cudaFuncSetAttribute(gcn2_mma,  cudaFuncAttributeMaxDynamicSharedMemorySize, G2_BYTES);

    const float invN_nodes = 1.f / (float)NNODES;
    const float invN_bf    = 1.f / (float)(BB * FF);

    prep<<<2416, 256>>>(cw1, W2, whi, wlo, w2h, w2l);                          // 0
    gcn1_stats<<<1024, 256>>>(x, W1, b1, p1);                                  // 1
    bn_final<<<64, 256>>>(p1, 1024, 64, g1, be1, invN_nodes, s1, h1);          // 2
    gcn2_mma<<<3200, 256, G2_BYTES>>>(x, W1, b1, s1, h1, w2h, w2l, b2, p2, z2);// 3
    bn_final<<<64, 256>>>(p2, 3200, 64, g2, be2, invN_nodes, s2, h2);          // 4
    conv1_mma<<<dim3(3, 128), 256, CM_BYTES>>>(z2, whi, wlo, s2, h2, y);       // 5
    shiftadd<<<dim3(4, BB), 256>>>(y, cb1, w1o, pC1);                          // 6
    bn_final<<<128, 256>>>(pC1, 256, 128, cg1, cbe1, invN_bf, sC1, hC1);       // 7
    conv2_kernel<<<dim3(4, BB), 256>>>(w1o, cw2, cb2, sC1, hC1, v, pC2);       // 8
    bn_final<<<64, 256>>>(pC2, 256, 64, cg2, cbe2, invN_bf, sC2, hC2);         // 9
    final_kernel<<<dim3(4, BB), 256>>>(v, sC2, hC2, out);                      // 10
}

// round 13
// speedup vs baseline: 1.7349x; 1.0183x over previous
#include <cuda_runtime.h>
#include <cuda_bf16.h>
#include <cstdint>

#define BB 64
#define FF 256
#define JJ 25
#define FILT 64
#define C1 128
#define NNODES (BB * FF * JJ)              // 409600
#define NE (NNODES * FILT)                 // 26214400
#define MTOT (BB * FF)                     // 16384
#define NW 384
#define KCI 1600
#define EPSV 1e-5f

// ---------------------------------------------------------------------------
// Scratch
// ---------------------------------------------------------------------------
__device__ float g_z2[NE];                 // GCN2 pre-BN output [node][c]
__device__ float g_y[MTOT * NW];           // conv1 GEMM output (pre shift-add)
__device__ __nv_bfloat16 g_wwhi[NW * KCI]; // tap-split conv1 weights, bf16 hi
__device__ __nv_bfloat16 g_wwlo[NW * KCI]; // bf16 lo residual
__device__ __nv_bfloat16 g_w2hb[FILT * FILT]; // W2 split bf16, [n_out][k_in]
__device__ __nv_bfloat16 g_w2lb[FILT * FILT];
__device__ float g_w1out[BB * C1 * FF];    // conv1 raw output (pre-BN)
__device__ float g_v[BB * FILT * FF];      // conv2 raw output (pre-BN)
__device__ float g_p1[2 * 64 * 1024];
__device__ float g_p2[2 * 64 * 3200];
__device__ float g_pC1[2 * 128 * 256];
__device__ float g_pC2[2 * 64 * 256];
__device__ float g_scale1[64], g_shift1[64];
__device__ float g_scale2[64], g_shift2[64];
__device__ float g_scaleC1[128], g_shiftC1[128];
__device__ float g_scaleC2[64], g_shiftC2[64];

__device__ __forceinline__ float dinvf(int j) {
    return (j == 0 || j == JJ - 1) ? 0.70710678118654752f : 0.57735026918962576f;
}
__device__ __forceinline__ float lrelu(float v) { return v >= 0.f ? v : 0.2f * v; }

#define MMA_BF16(d, av, b0, b1) \
    asm volatile("mma.sync.aligned.m16n8k16.row.col.f32.bf16.bf16.f32 " \
        "{%0,%1,%2,%3}, {%4,%5,%6,%7}, {%8,%9}, {%0,%1,%2,%3};" \
        : "+f"((d)[0]), "+f"((d)[1]), "+f"((d)[2]), "+f"((d)[3]) \
        : "r"((av)[0]), "r"((av)[1]), "r"((av)[2]), "r"((av)[3]), \
          "r"(b0), "r"(b1))

__device__ __forceinline__ void cp_async16(uint32_t saddr, const void* g) {
    asm volatile("cp.async.cg.shared.global [%0], [%1], 16;" :: "r"(saddr), "l"(g) : "memory");
}

// ---------------------------------------------------------------------------
// K0: merged prep + gcn1 stats.
//  blocks [0,2400): conv1 weights bf16-split
//  blocks [2400,2416): W2 bf16-split transposed
//  blocks [2416,3440): GCN1 stats (z1 recomputed on the fly, 16 graphs/block)
// ---------------------------------------------------------------------------
__global__ __launch_bounds__(256) void prep_stats(
    const float* __restrict__ cw1, const float* __restrict__ W2,
    const float* __restrict__ x, const float* __restrict__ W1,
    const float* __restrict__ b1,
    __nv_bfloat16* __restrict__ whi, __nv_bfloat16* __restrict__ wlo,
    __nv_bfloat16* __restrict__ w2h, __nv_bfloat16* __restrict__ w2l,
    float* __restrict__ part) {
    int bid = blockIdx.x;
    int tid = threadIdx.x;
    if (bid < 2400) {
        int idx = bid * 256 + tid;                // < 614400 exactly
        int n = idx / KCI, ci = idx - n * KCI;
        int k = n >> 7, o = n & 127;
        float w = cw1[(size_t)o * 4800 + ci * 3 + k];
        __nv_bfloat16 hb = __float2bfloat16(w);
        whi[idx] = hb;
        wlo[idx] = __float2bfloat16(w - __bfloat162float(hb));
        return;
    }
    if (bid < 2416) {
        int i = (bid - 2400) * 256 + tid;         // < 4096
        int n = i >> 6, k = i & 63;
        float w = W2[k * 64 + n];
        __nv_bfloat16 hb = __float2bfloat16(w);
        w2h[i] = hb;
        w2l[i] = __float2bfloat16(w - __bfloat162float(hb));
        return;
    }
    // ---- gcn1 stats ----
    int sb = bid - 2416;                          // 0..1023
    __shared__ float xs[1200], xef[1200], W1s[192], b1s[64], ss[256], qq[256];
    if (tid < 192) W1s[tid] = W1[tid];
    if (tid < 64) b1s[tid] = b1[tid];
    int base = sb * 1200;
    for (int i = tid; i < 1200; i += 256) xs[i] = x[base + i];
    __syncthreads();
    for (int i = tid; i < 400; i += 256) {
        int j = i % 25;
        float dj = dinvf(j);
        float cm = (j > 0) ? dinvf(j - 1) : 0.f;
        float cp = (j < 24) ? dinvf(j + 1) : 0.f;
        int im = (i > 0) ? i - 1 : 0, ip = (i < 399) ? i + 1 : 399;
#pragma unroll
        for (int d = 0; d < 3; d++)
            xef[i * 3 + d] = dj * (dj * xs[i * 3 + d] + cm * xs[im * 3 + d] + cp * xs[ip * 3 + d]);
    }
    __syncthreads();

    int c = tid & 63, sub = tid >> 6;
    float w0 = W1s[c], w1 = W1s[64 + c], w2 = W1s[128 + c], bb = b1s[c];
    float s = 0.f, q = 0.f;
    for (int it = 0; it < 100; it++) {
        int nl = it * 4 + sub;
        float z = xef[nl * 3] * w0 + xef[nl * 3 + 1] * w1 + xef[nl * 3 + 2] * w2 + bb;
        s += z; q += z * z;
    }
    ss[tid] = s; qq[tid] = q;
    __syncthreads();
    if (tid < 64) {
        s = ss[tid] + ss[tid + 64] + ss[tid + 128] + ss[tid + 192];
        q = qq[tid] + qq[tid + 64] + qq[tid + 128] + qq[tid + 192];
        part[tid * 1024 + sb] = s;
        part[65536 + tid * 1024 + sb] = q;
    }
}

// ---------------------------------------------------------------------------
// BN finalize: part layout S at [c*R + r], Q at [C*R + c*R + r].
// ---------------------------------------------------------------------------
__global__ __launch_bounds__(256) void bn_final(
    const float* __restrict__ part, int R, int C,
    const float* __restrict__ g, const float* __restrict__ be, float invN,
    float* __restrict__ scale, float* __restrict__ shift) {
    int c = blockIdx.x, tid = threadIdx.x;
    __shared__ float ss[256], qq[256];
    const float* pS = part + (size_t)c * R;
    const float* pQ = part + (size_t)C * R + (size_t)c * R;
    float s = 0.f, q = 0.f;
    for (int r = tid; r < R; r += 256) { s += pS[r]; q += pQ[r]; }
    ss[tid] = s; qq[tid] = q;
    __syncthreads();
    for (int o = 128; o > 0; o >>= 1) {
        if (tid < o) { ss[tid] += ss[tid + o]; qq[tid] += qq[tid + o]; }
        __syncthreads();
    }
    if (tid == 0) {
        float m = ss[0] * invN;
        float var = qq[0] * invN - m * m;
        float rstd = rsqrtf(var + EPSV);
        float sc = g[c] * rstd;
        scale[c] = sc;
        shift[c] = be[c] - m * sc;
    }
}

// ---------------------------------------------------------------------------
// K2: gcn2 via bf16x3 MMA, v3. Block = 128 nodes (3200 blocks).
// h is recomputed inline in phase B from xeff (no HBE buffer): all
// out-of-range/cross-graph neighbors have stencil coefficient exactly 0.
// Dynamic smem (bytes): AHI@0 18432 | ALO@18432 | BHI@36864 9216 | BLO@46080
// total 55296 -> ~3 CTAs/SM.
// ---------------------------------------------------------------------------
#define G2S 72
#define G2_BYTES 55296

__global__ __launch_bounds__(256) void gcn2_mma(
    const float* __restrict__ x, const float* __restrict__ W1,
    const float* __restrict__ b1, const float* __restrict__ sc1,
    const float* __restrict__ sh1, const __nv_bfloat16* __restrict__ w2hb,
    const __nv_bfloat16* __restrict__ w2lb, const float* __restrict__ b2,
    float* __restrict__ part, float* __restrict__ z2b) {
    extern __shared__ __align__(16) char dynraw[];
    __nv_bfloat16* Ahi = reinterpret_cast<__nv_bfloat16*>(dynraw);
    __nv_bfloat16* Alo = reinterpret_cast<__nv_bfloat16*>(dynraw + 18432);
    __nv_bfloat16* Bhi = reinterpret_cast<__nv_bfloat16*>(dynraw + 36864);
    __nv_bfloat16* Blo = reinterpret_cast<__nv_bfloat16*>(dynraw + 46080);
    __shared__ __align__(16) float xs[396], xef[520];
    __shared__ __align__(16) float W1s[192], b1s[64], sc1s[64], sh1s[64], b2s[64];
    __shared__ float redS[256], redQ[256];

    int tid = threadIdx.x, lane = tid & 31, wid = tid >> 5;
    int n0 = blockIdx.x * 128;

    if (tid < 192) W1s[tid] = W1[tid];
    if (tid < 64) {
        b1s[tid] = b1[tid]; sc1s[tid] = sc1[tid];
        sh1s[tid] = sh1[tid]; b2s[tid] = b2[tid];
    }
    // 396 floats = 132 nodes: n0-2 .. n0+129 (l=129 xeff reads xs[393..395]).
    for (int i = tid; i < 396; i += 256) {
        int gi = (n0 - 2) * 3 + i;
        xs[i] = (gi >= 0 && gi < NNODES * 3) ? x[gi] : 0.f;
    }
    // B tiles: 64 rows x 64 k, bf16 pairs, stride 72
    for (int i = tid; i < 2048; i += 256) {
        int n = i >> 5, kk = i & 31;
        *reinterpret_cast<uint32_t*>(Bhi + n * G2S + kk * 2) =
            *reinterpret_cast<const uint32_t*>(w2hb + n * 64 + kk * 2);
        *reinterpret_cast<uint32_t*>(Blo + n * G2S + kk * 2) =
            *reinterpret_cast<const uint32_t*>(w2lb + n * 64 + kk * 2);
    }
    __syncthreads();

    // Phase 0: xeff[l] for l in 0..129 (node m = n0-1+l); xs row = l+1
    for (int i = tid; i < 130; i += 256) {
        int m = n0 - 1 + i;
        float e0 = 0.f, e1 = 0.f, e2 = 0.f;
        if (m >= 0 && m < NNODES) {
            int j = m % 25;
            float dj = dinvf(j);
            float cm = (j > 0) ? dinvf(j - 1) : 0.f;
            float cp = (j < 24) ? dinvf(j + 1) : 0.f;
            const float* xc = xs + (i + 1) * 3;
            e0 = dj * (dj * xc[0] + cm * xc[-3] + cp * xc[3]);
            e1 = dj * (dj * xc[1] + cm * xc[-2] + cp * xc[4]);
            e2 = dj * (dj * xc[2] + cm * xc[-1] + cp * xc[5]);
        }
        xef[i * 4] = e0; xef[i * 4 + 1] = e1; xef[i * 4 + 2] = e2;
    }
    __syncthreads();

    // Phase B: recompute h at (m-1, m, m+1) from xeff, stencil, split -> A.
    // xeff row for node m-1+d is (nl + d), d in {0,1,2}.
    // Invalid/cross-graph neighbors always carry coefficient 0 (j boundary).
    {
        const float4* W1s4 = reinterpret_cast<const float4*>(W1s);
        const float4* b4 = reinterpret_cast<const float4*>(b1s);
        const float4* sc4 = reinterpret_cast<const float4*>(sc1s);
        const float4* sh4 = reinterpret_cast<const float4*>(sh1s);
        for (int i = tid; i < 2048; i += 256) {
            int cg = i & 15, nl = i >> 4;
            int m = n0 + nl, j = m % 25;
            float dj = dinvf(j);
            float cm = (j > 0) ? dinvf(j - 1) : 0.f;
            float cp = (j < 24) ? dinvf(j + 1) : 0.f;
            float4 w0 = W1s4[cg], w1 = W1s4[16 + cg], w2 = W1s4[32 + cg];
            float4 bb = b4[cg], sv = sc4[cg], hs = sh4[cg];
            float4 h[3];
#pragma unroll
            for (int d = 0; d < 3; d++) {
                float e0 = xef[(nl + d) * 4], e1 = xef[(nl + d) * 4 + 1],
                      e2 = xef[(nl + d) * 4 + 2];
                float4 z;
                z.x = e0 * w0.x + e1 * w1.x + e2 * w2.x + bb.x;
                z.y = e0 * w0.y + e1 * w1.y + e2 * w2.y + bb.y;
                z.z = e0 * w0.z + e1 * w1.z + e2 * w2.z + bb.z;
                z.w = e0 * w0.w + e1 * w1.w + e2 * w2.w + bb.w;
                h[d].x = lrelu(fmaf(z.x, sv.x, hs.x));
                h[d].y = lrelu(fmaf(z.y, sv.y, hs.y));
                h[d].z = lrelu(fmaf(z.z, sv.z, hs.z));
                h[d].w = lrelu(fmaf(z.w, sv.w, hs.w));
            }
            float4 v;
            v.x = dj * (dj * h[1].x + cm * h[0].x + cp * h[2].x);
            v.y = dj * (dj * h[1].y + cm * h[0].y + cp * h[2].y);
            v.z = dj * (dj * h[1].z + cm * h[0].z + cp * h[2].z);
            v.w = dj * (dj * h[1].w + cm * h[0].w + cp * h[2].w);
            __nv_bfloat16 hx = __float2bfloat16(v.x), hy = __float2bfloat16(v.y);
            __nv_bfloat16 hz = __float2bfloat16(v.z), hw = __float2bfloat16(v.w);
            __nv_bfloat16 lx = __float2bfloat16(v.x - __bfloat162float(hx));
            __nv_bfloat16 ly = __float2bfloat16(v.y - __bfloat162float(hy));
            __nv_bfloat16 lz = __float2bfloat16(v.z - __bfloat162float(hz));
            __nv_bfloat16 lw = __float2bfloat16(v.w - __bfloat162float(hw));
            int di = nl * G2S + cg * 4;
            *reinterpret_cast<__nv_bfloat162*>(Ahi + di)     = __halves2bfloat162(hx, hy);
            *reinterpret_cast<__nv_bfloat162*>(Ahi + di + 2) = __halves2bfloat162(hz, hw);
            *reinterpret_cast<__nv_bfloat162*>(Alo + di)     = __halves2bfloat162(lx, ly);
            *reinterpret_cast<__nv_bfloat162*>(Alo + di + 2) = __halves2bfloat162(lz, lw);
        }
    }
    __syncthreads();

    // MMA: 8 warps = 4M x 2N; warp tile 32 rows x 32 cols; K=64 (4 kt).
    int wm = wid & 3, wn = wid >> 2;
    float acc[2][4][4];
#pragma unroll
    for (int mt = 0; mt < 2; mt++)
#pragma unroll
        for (int nt = 0; nt < 4; nt++)
#pragma unroll
            for (int u = 0; u < 4; u++) acc[mt][nt][u] = 0.f;

#pragma unroll
    for (int kt = 0; kt < 4; kt++) {
        uint32_t ahi[2][4], alo[2][4], bhi[4][2], blo[4][2];
        int abase = (wm * 32 + (lane >> 2)) * G2S + (lane & 3) * 2 + kt * 16;
#pragma unroll
        for (int mt = 0; mt < 2; mt++) {
            int o = abase + mt * 16 * G2S;
            ahi[mt][0] = *reinterpret_cast<const uint32_t*>(Ahi + o);
            ahi[mt][1] = *reinterpret_cast<const uint32_t*>(Ahi + o + 8 * G2S);
            ahi[mt][2] = *reinterpret_cast<const uint32_t*>(Ahi + o + 8);
            ahi[mt][3] = *reinterpret_cast<const uint32_t*>(Ahi + o + 8 * G2S + 8);
            alo[mt][0] = *reinterpret_cast<const uint32_t*>(Alo + o);
            alo[mt][1] = *reinterpret_cast<const uint32_t*>(Alo + o + 8 * G2S);
            alo[mt][2] = *reinterpret_cast<const uint32_t*>(Alo + o + 8);
            alo[mt][3] = *reinterpret_cast<const uint32_t*>(Alo + o + 8 * G2S + 8);
        }
        int bbase = (wn * 32 + (lane >> 2)) * G2S + (lane & 3) * 2 + kt * 16;
#pragma unroll
        for (int nt = 0; nt < 4; nt++) {
            int o = bbase + nt * 8 * G2S;
            bhi[nt][0] = *reinterpret_cast<const uint32_t*>(Bhi + o);
            bhi[nt][1] = *reinterpret_cast<const uint32_t*>(Bhi + o + 8);
            blo[nt][0] = *reinterpret_cast<const uint32_t*>(Blo + o);
            blo[nt][1] = *reinterpret_cast<const uint32_t*>(Blo + o + 8);
        }
#pragma unroll
        for (int nt = 0; nt < 4; nt++) {
            MMA_BF16(acc[0][nt], ahi[0], bhi[nt][0], bhi[nt][1]);
            MMA_BF16(acc[1][nt], ahi[1], bhi[nt][0], bhi[nt][1]);
        }
#pragma unroll
        for (int nt = 0; nt < 4; nt++) {
            MMA_BF16(acc[0][nt], ahi[0], blo[nt][0], blo[nt][1]);
            MMA_BF16(acc[1][nt], ahi[1], blo[nt][0], blo[nt][1]);
        }
#pragma unroll
        for (int nt = 0; nt < 4; nt++) {
            MMA_BF16(acc[0][nt], alo[0], bhi[nt][0], bhi[nt][1]);
            MMA_BF16(acc[1][nt], alo[1], bhi[nt][0], bhi[nt][1]);
        }
    }

    // Epilogue: bias + z2 store + per-channel partial stats
#pragma unroll
    for (int nt = 0; nt < 4; nt++) {
        int c0 = wn * 32 + nt * 8 + ((lane & 3) << 1);
        float bb0 = b2s[c0], bb1 = b2s[c0 + 1];
        float s0 = 0.f, q0 = 0.f, s1 = 0.f, q1 = 0.f;
#pragma unroll
        for (int mt = 0; mt < 2; mt++) {
            int row = n0 + wm * 32 + mt * 16 + (lane >> 2);
            float u0 = acc[mt][nt][0] + bb0, u1 = acc[mt][nt][1] + bb1;
            float u2 = acc[mt][nt][2] + bb0, u3 = acc[mt][nt][3] + bb1;
            *reinterpret_cast<float2*>(z2b + (size_t)row * 64 + c0) = make_float2(u0, u1);
            *reinterpret_cast<float2*>(z2b + (size_t)(row + 8) * 64 + c0) = make_float2(u2, u3);
            s0 += u0 + u2; q0 += u0 * u0 + u2 * u2;
            s1 += u1 + u3; q1 += u1 * u1 + u3 * u3;
        }
#pragma unroll
        for (int o = 4; o < 32; o <<= 1) {
            s0 += __shfl_xor_sync(0xffffffffu, s0, o);
            q0 += __shfl_xor_sync(0xffffffffu, q0, o);
            s1 += __shfl_xor_sync(0xffffffffu, s1, o);
            q1 += __shfl_xor_sync(0xffffffffu, q1, o);
        }
        if (lane < 4) {
            redS[c0 * 4 + wm] = s0; redS[(c0 + 1) * 4 + wm] = s1;
            redQ[c0 * 4 + wm] = q0; redQ[(c0 + 1) * 4 + wm] = q1;
        }
    }
    __syncthreads();
    if (tid < 64) {
        float S = redS[tid * 4] + redS[tid * 4 + 1] + redS[tid * 4 + 2] + redS[tid * 4 + 3];
        float Q = redQ[tid * 4] + redQ[tid * 4 + 1] + redQ[tid * 4 + 2] + redQ[tid * 4 + 3];
        part[tid * 3200 + blockIdx.x] = S;
        part[204800 + tid * 3200 + blockIdx.x] = Q;
    }
}

// ---------------------------------------------------------------------------
// K3: conv1 as bf16x3 mma.sync GEMM (m16n8k16). (unchanged, passing)
// ---------------------------------------------------------------------------
#define TILEB 5120                                   // 128*40 bf16
#define CM_BYTES (8 * TILEB * 2)                     // 81920

__global__ __launch_bounds__(256) void conv1_mma(
    const float* __restrict__ z2b, const __nv_bfloat16* __restrict__ wwhi,
    const __nv_bfloat16* __restrict__ wwlo, const float* __restrict__ sc,
    const float* __restrict__ sh, float* __restrict__ y) {
    extern __shared__ __align__(16) char dynraw[];
    __nv_bfloat16* sm = reinterpret_cast<__nv_bfloat16*>(dynraw);
    __shared__ float scs[64], shs[64];
    int tid = threadIdx.x, lane = tid & 31, wid = tid >> 5;
    int wm = wid & 3, wn = wid >> 2;
    int m0 = blockIdx.y * 128, n0 = blockIdx.x * 128;
    if (tid < 64) { scs[tid] = sc[tid]; shs[tid] = sh[tid]; }
    __syncthreads();

    float acc[2][8][4];
#pragma unroll
    for (int mt = 0; mt < 2; mt++)
#pragma unroll
        for (int nt = 0; nt < 8; nt++)
#pragma unroll
            for (int u = 0; u < 4; u++) acc[mt][nt][u] = 0.f;

    float4 aReg[4];

#define LOADA(step) do { \
        int ci0_ = (step) * 32; \
        _Pragma("unroll") \
        for (int u = 0; u < 4; u++) { \
            int fi = u * 256 + tid; \
            int row = fi >> 3, c4 = fi & 7; \
            aReg[u] = *reinterpret_cast<const float4*>( \
                z2b + (size_t)(m0 + row) * KCI + ci0_ + c4 * 4); \
        } \
    } while (0)

#define STOREA(bufi, step) do { \
        int ci0_ = (step) * 32; \
        __nv_bfloat16* Ah_ = sm + (bufi) * 4 * TILEB; \
        __nv_bfloat16* Al_ = Ah_ + TILEB; \
        _Pragma("unroll") \
        for (int u = 0; u < 4; u++) { \
            int fi = u * 256 + tid; \
            int row = fi >> 3, c4 = fi & 7; \
            int cb = (ci0_ + c4 * 4) & 63; \
            float4 v = aReg[u]; \
            v.x = lrelu(fmaf(v.x, scs[cb],     shs[cb])); \
            v.y = lrelu(fmaf(v.y, scs[cb + 1], shs[cb + 1])); \
            v.z = lrelu(fmaf(v.z, scs[cb + 2], shs[cb + 2])); \
            v.w = lrelu(fmaf(v.w, scs[cb + 3], shs[cb + 3])); \
            __nv_bfloat16 hx = __float2bfloat16(v.x); \
            __nv_bfloat16 hy = __float2bfloat16(v.y); \
            __nv_bfloat16 hz = __float2bfloat16(v.z); \
            __nv_bfloat16 hw = __float2bfloat16(v.w); \
            __nv_bfloat16 lx = __float2bfloat16(v.x - __bfloat162float(hx)); \
            __nv_bfloat16 ly = __float2bfloat16(v.y - __bfloat162float(hy)); \
            __nv_bfloat16 lz = __float2bfloat16(v.z - __bfloat162float(hz)); \
            __nv_bfloat16 lw = __float2bfloat16(v.w - __bfloat162float(hw)); \
            int di = row * 40 + c4 * 4; \
            *reinterpret_cast<__nv_bfloat162*>(Ah_ + di)     = __halves2bfloat162(hx, hy); \
            *reinterpret_cast<__nv_bfloat162*>(Ah_ + di + 2) = __halves2bfloat162(hz, hw); \
            *reinterpret_cast<__nv_bfloat162*>(Al_ + di)     = __halves2bfloat162(lx, ly); \
            *reinterpret_cast<__nv_bfloat162*>(Al_ + di + 2) = __halves2bfloat162(lz, lw); \
        } \
    } while (0)

#define LOADB(bufi, step) do { \
        int ci0_ = (step) * 32; \
        __nv_bfloat16* Bh_ = sm + (bufi) * 4 * TILEB + 2 * TILEB; \
        __nv_bfloat16* Bl_ = Bh_ + TILEB; \
        _Pragma("unroll") \
        for (int u = 0; u < 4; u++) { \
            int fi = u * 256 + tid; \
            int bsel = fi >> 9; \
            int rem = fi & 511; \
            int row = rem >> 2, gg = rem & 3; \
            const __nv_bfloat16* src = (bsel ? wwlo : wwhi) + \
                (size_t)(n0 + row) * KCI + ci0_ + gg * 8; \
            __nv_bfloat16* dstp = (bsel ? Bl_ : Bh_) + row * 40 + gg * 8; \
            cp_async16((uint32_t)__cvta_generic_to_shared(dstp), src); \
        } \
        asm volatile("cp.async.commit_group;" ::: "memory"); \
    } while (0)

    LOADA(0);
    STOREA(0, 0);
    LOADB(0, 0);

    for (int i = 0; i < 50; i++) {
        int buf = i & 1;
        if (i < 49) LOADA(i + 1);
        asm volatile("cp.async.wait_group 0;" ::: "memory");
        __syncthreads();
        if (i < 49) LOADB(buf ^ 1, i + 1);

        const __nv_bfloat16* Ahi = sm + buf * 4 * TILEB;
        const __nv_bfloat16* Alo = Ahi + TILEB;
        const __nv_bfloat16* Bhi = Ahi + 2 * TILEB;
        const __nv_bfloat16* Blo = Ahi + 3 * TILEB;
#pragma unroll
        for (int kt = 0; kt < 2; kt++) {
            uint32_t ahi[2][4], alo[2][4], bhi[8][2], blo[8][2];
            int abase = (wm * 32 + (lane >> 2)) * 40 + (lane & 3) * 2 + kt * 16;
#pragma unroll
            for (int mt = 0; mt < 2; mt++) {
                int o = abase + mt * 640;
                ahi[mt][0] = *reinterpret_cast<const uint32_t*>(Ahi + o);
                ahi[mt][1] = *reinterpret_cast<const uint32_t*>(Ahi + o + 320);
                ahi[mt][2] = *reinterpret_cast<const uint32_t*>(Ahi + o + 8);
                ahi[mt][3] = *reinterpret_cast<const uint32_t*>(Ahi + o + 328);
                alo[mt][0] = *reinterpret_cast<const uint32_t*>(Alo + o);
                alo[mt][1] = *reinterpret_cast<const uint32_t*>(Alo + o + 320);
                alo[mt][2] = *reinterpret_cast<const uint32_t*>(Alo + o + 8);
                alo[mt][3] = *reinterpret_cast<const uint32_t*>(Alo + o + 328);
            }
            int bbase = (wn * 64 + (lane >> 2)) * 40 + (lane & 3) * 2 + kt * 16;
#pragma unroll
            for (int nt = 0; nt < 8; nt++) {
                int o = bbase + nt * 320;
                bhi[nt][0] = *reinterpret_cast<const uint32_t*>(Bhi + o);
                bhi[nt][1] = *reinterpret_cast<const uint32_t*>(Bhi + o + 8);
                blo[nt][0] = *reinterpret_cast<const uint32_t*>(Blo + o);
                blo[nt][1] = *reinterpret_cast<const uint32_t*>(Blo + o + 8);
            }
#pragma unroll
            for (int nt = 0; nt < 8; nt++) {
                MMA_BF16(acc[0][nt], ahi[0], bhi[nt][0], bhi[nt][1]);
                MMA_BF16(acc[1][nt], ahi[1], bhi[nt][0], bhi[nt][1]);
            }
#pragma unroll
            for (int nt = 0; nt < 8; nt++) {
                MMA_BF16(acc[0][nt], ahi[0], blo[nt][0], blo[nt][1]);
                MMA_BF16(acc[1][nt], ahi[1], blo[nt][0], blo[nt][1]);
            }
#pragma unroll
            for (int nt = 0; nt < 8; nt++) {
                MMA_BF16(acc[0][nt], alo[0], bhi[nt][0], bhi[nt][1]);
                MMA_BF16(acc[1][nt], alo[1], bhi[nt][0], bhi[nt][1]);
            }
        }
        if (i < 49) STOREA(buf ^ 1, i + 1);
    }

#pragma unroll
    for (int mt = 0; mt < 2; mt++) {
#pragma unroll
        for (int nt = 0; nt < 8; nt++) {
            int row = m0 + wm * 32 + mt * 16 + (lane >> 2);
            int col = n0 + wn * 64 + nt * 8 + ((lane & 3) << 1);
            float2 v0 = make_float2(acc[mt][nt][0], acc[mt][nt][1]);
            float2 v1 = make_float2(acc[mt][nt][2], acc[mt][nt][3]);
            *reinterpret_cast<float2*>(y + (size_t)row * NW + col) = v0;
            *reinterpret_cast<float2*>(y + (size_t)(row + 8) * NW + col) = v1;
        }
    }
#undef LOADA
#undef STOREA
#undef LOADB
}

// ---------------------------------------------------------------------------
// K4: shift-add epilogue + fused per-channel stats.
// ---------------------------------------------------------------------------
__global__ __launch_bounds__(256) void shiftadd(
    const float* __restrict__ y, const float* __restrict__ cb1,
    float* __restrict__ w1o, float* __restrict__ part) {
    __shared__ float t[128 * 65];
    int tid = threadIdx.x;
    int b = blockIdx.y;
    int f0 = blockIdx.x * 64;
    for (int i = tid; i < 8192; i += 256) {
        int o = i & 127, ff = i >> 7;
        int f = f0 + ff, m = b * 256 + f;
        float val = __ldg(cb1 + o) + y[(size_t)m * NW + 128 + o];
        if (f > 0)   val += y[(size_t)(m - 1) * NW + o];
        if (f < 255) val += y[(size_t)(m + 1) * NW + 256 + o];
        t[o * 65 + ff] = val;
    }
    __syncthreads();
    for (int i = tid; i < 8192; i += 256) {
        int ff = i & 63, o = i >> 6;
        w1o[(size_t)(b * 128 + o) * 256 + f0 + ff] = t[o * 65 + ff];
    }
    if (tid < 128) {
        float S = 0.f, Q = 0.f;
#pragma unroll 8
        for (int k = 0; k < 64; k++) {
            float v = t[tid * 65 + k];
            S += v; Q += v * v;
        }
        int blk = blockIdx.y * 4 + blockIdx.x;
        part[tid * 256 + blk] = S;
        part[32768 + tid * 256 + blk] = Q;
    }
}

// ---------------------------------------------------------------------------
// K6: Conv2 (1x1, 128->64) with bnC1+lrelu fused at load + partial stats.
// ---------------------------------------------------------------------------
__global__ __launch_bounds__(256) void conv2_kernel(
    const float* __restrict__ w1o, const float* __restrict__ cw2,
    const float* __restrict__ cb2, const float* __restrict__ sc,
    const float* __restrict__ sh, float* __restrict__ vout,
    float* __restrict__ part) {
    __shared__ __align__(16) float Us[64 * 64];
    __shared__ __align__(16) float Ws2[64 * 64];
    int tid = threadIdx.x;
    int b = blockIdx.y;
    int f0 = blockIdx.x * 64;
    int fth = tid & 15, oth = tid >> 4;
    float acc[4][4] = {};

    for (int ci0 = 0; ci0 < 128; ci0 += 64) {
        for (int i = tid; i < 4096; i += 256) {
            int cc = i >> 6, ffi = i & 63;
            float raw = w1o[(size_t)(b * 128 + ci0 + cc) * 256 + f0 + ffi];
            float v = fmaf(raw, __ldg(sc + ci0 + cc), __ldg(sh + ci0 + cc));
            Us[i] = lrelu(v);
        }
        for (int i = tid; i < 4096; i += 256) {
            int o = i & 63, cc = i >> 6;
            Ws2[cc * 64 + o] = cw2[o * 128 + ci0 + cc];
        }
        __syncthreads();
#pragma unroll 8
        for (int cc = 0; cc < 64; cc++) {
            float4 iv = *reinterpret_cast<const float4*>(Us + cc * 64 + fth * 4);
            float4 wv = *reinterpret_cast<const float4*>(Ws2 + cc * 64 + oth * 4);
            acc[0][0] = fmaf(wv.x, iv.x, acc[0][0]); acc[0][1] = fmaf(wv.x, iv.y, acc[0][1]);
            acc[0][2] = fmaf(wv.x, iv.z, acc[0][2]); acc[0][3] = fmaf(wv.x, iv.w, acc[0][3]);
            acc[1][0] = fmaf(wv.y, iv.x, acc[1][0]); acc[1][1] = fmaf(wv.y, iv.y, acc[1][1]);
            acc[1][2] = fmaf(wv.y, iv.z, acc[1][2]); acc[1][3] = fmaf(wv.y, iv.w, acc[1][3]);
            acc[2][0] = fmaf(wv.z, iv.x, acc[2][0]); acc[2][1] = fmaf(wv.z, iv.y, acc[2][1]);
            acc[2][2] = fmaf(wv.z, iv.z, acc[2][2]); acc[2][3] = fmaf(wv.z, iv.w, acc[2][3]);
            acc[3][0] = fmaf(wv.w, iv.x, acc[3][0]); acc[3][1] = fmaf(wv.w, iv.y, acc[3][1]);
            acc[3][2] = fmaf(wv.w, iv.z, acc[3][2]); acc[3][3] = fmaf(wv.w, iv.w, acc[3][3]);
        }
        __syncthreads();
    }

    float* reds = Us;
    float* redq = Ws2;
#pragma unroll
    for (int i = 0; i < 4; i++) {
        int o = oth * 4 + i;
        float bias = __ldg(cb2 + o);
        float s = 0.f, q = 0.f;
#pragma unroll
        for (int j2 = 0; j2 < 4; j2++) {
            float r = acc[i][j2] + bias;
            vout[(size_t)(b * 64 + o) * 256 + f0 + fth * 4 + j2] = r;
            s += r; q += r * r;
        }
        reds[o * 17 + fth] = s;
        redq[o * 17 + fth] = q;
    }
    __syncthreads();
    if (tid < 64) {
        float S = 0.f, Q = 0.f;
#pragma unroll
        for (int t = 0; t < 16; t++) { S += reds[tid * 17 + t]; Q += redq[tid * 17 + t]; }
        int blk = blockIdx.y * 4 + blockIdx.x;
        part[tid * 256 + blk] = S;
        part[16384 + tid * 256 + blk] = Q;
    }
}

// ---------------------------------------------------------------------------
// K7: final BN + LReLU + transpose (B,64,256) -> (B,256,64)
// ---------------------------------------------------------------------------
__global__ __launch_bounds__(256) void final_kernel(
    const float* __restrict__ v, const float* __restrict__ sc,
    const float* __restrict__ sh, float* __restrict__ out) {
    __shared__ float s[64 * 65];
    int tid = threadIdx.x;
    int b = blockIdx.y;
    int f0 = blockIdx.x * 64;
    for (int i = tid; i < 4096; i += 256) {
        int o = i >> 6, ffi = i & 63;
        s[o * 65 + ffi] = v[(size_t)(b * 64 + o) * 256 + f0 + ffi];
    }
    __syncthreads();
    for (int i = tid; i < 4096; i += 256) {
        int ffi = i >> 6, o = i & 63;
        float val = fmaf(s[o * 65 + ffi], __ldg(sc + o), __ldg(sh + o));
        out[(size_t)(b * 256 + f0 + ffi) * 64 + o] = lrelu(val);
    }
}

// ---------------------------------------------------------------------------
// Launch
// ---------------------------------------------------------------------------
extern "C" void kernel_launch(void* const* d_in, const int* in_sizes, int n_in,
                              void* d_out, int out_size) {
    const float* x   = (const float*)d_in[0];
    const float* W1  = (const float*)d_in[4];
    const float* b1  = (const float*)d_in[5];
    const float* g1  = (const float*)d_in[6];
    const float* be1 = (const float*)d_in[7];
    const float* W2  = (const float*)d_in[8];
    const float* b2  = (const float*)d_in[9];
    const float* g2  = (const float*)d_in[10];
    const float* be2 = (const float*)d_in[11];
    const float* cw1 = (const float*)d_in[12];
    const float* cb1 = (const float*)d_in[13];
    const float* cg1 = (const float*)d_in[14];
    const float* cbe1= (const float*)d_in[15];
    const float* cw2 = (const float*)d_in[16];
    const float* cb2 = (const float*)d_in[17];
    const float* cg2 = (const float*)d_in[18];
    const float* cbe2= (const float*)d_in[19];
    float* out = (float*)d_out;

    float *z2, *y, *w1o, *v, *p1, *p2, *pC1, *pC2;
    __nv_bfloat16 *whi, *wlo, *w2h, *w2l;
    float *s1, *h1, *s2, *h2, *sC1, *hC1, *sC2, *hC2;
    cudaGetSymbolAddress((void**)&z2,  g_z2);
    cudaGetSymbolAddress((void**)&y,   g_y);
    cudaGetSymbolAddress((void**)&whi, g_wwhi);
    cudaGetSymbolAddress((void**)&wlo, g_wwlo);
    cudaGetSymbolAddress((void**)&w2h, g_w2hb);
    cudaGetSymbolAddress((void**)&w2l, g_w2lb);
    cudaGetSymbolAddress((void**)&w1o, g_w1out);
    cudaGetSymbolAddress((void**)&v,   g_v);
    cudaGetSymbolAddress((void**)&p1,  g_p1);
    cudaGetSymbolAddress((void**)&p2,  g_p2);
    cudaGetSymbolAddress((void**)&pC1, g_pC1);
    cudaGetSymbolAddress((void**)&pC2, g_pC2);
    cudaGetSymbolAddress((void**)&s1,  g_scale1);
    cudaGetSymbolAddress((void**)&h1,  g_shift1);
    cudaGetSymbolAddress((void**)&s2,  g_scale2);
    cudaGetSymbolAddress((void**)&h2,  g_shift2);
    cudaGetSymbolAddress((void**)&sC1, g_scaleC1);
    cudaGetSymbolAddress((void**)&hC1, g_shiftC1);
    cudaGetSymbolAddress((void**)&sC2, g_scaleC2);
    cudaGetSymbolAddress((void**)&hC2, g_shiftC2);

    cudaFuncSetAttribute(conv1_mma, cudaFuncAttributeMaxDynamicSharedMemorySize, CM_BYTES);
    cudaFuncSetAttribute(gcn2_mma,  cudaFuncAttributeMaxDynamicSharedMemorySize, G2_BYTES);

    const float invN_nodes = 1.f / (float)NNODES;
    const float invN_bf    = 1.f / (float)(BB * FF);

    prep_stats<<<3440, 256>>>(cw1, W2, x, W1, b1, whi, wlo, w2h, w2l, p1);     // 0
    bn_final<<<64, 256>>>(p1, 1024, 64, g1, be1, invN_nodes, s1, h1);          // 1
    gcn2_mma<<<3200, 256, G2_BYTES>>>(x, W1, b1, s1, h1, w2h, w2l, b2, p2, z2);// 2
    bn_final<<<64, 256>>>(p2, 3200, 64, g2, be2, invN_nodes, s2, h2);          // 3
    conv1_mma<<<dim3(3, 128), 256, CM_BYTES>>>(z2, whi, wlo, s2, h2, y);       // 4
    shiftadd<<<dim3(4, BB), 256>>>(y, cb1, w1o, pC1);                          // 5
    bn_final<<<128, 256>>>(pC1, 256, 128, cg1, cbe1, invN_bf, sC1, hC1);       // 6
    conv2_kernel<<<dim3(4, BB), 256>>>(w1o, cw2, cb2, sC1, hC1, v, pC2);       // 7
    bn_final<<<64, 256>>>(pC2, 256, 64, cg2, cbe2, invN_bf, sC2, hC2);         // 8
    final_kernel<<<dim3(4, BB), 256>>>(v, sC2, hC2, out);                      // 9
}

// round 14
// speedup vs baseline: 1.7991x; 1.0370x over previous
#include <cuda_runtime.h>
#include <cuda_bf16.h>
#include <cstdint>

#define BB 64
#define FF 256
#define JJ 25
#define FILT 64
#define C1 128
#define NNODES (BB * FF * JJ)              // 409600
#define NE (NNODES * FILT)                 // 26214400
#define MTOT (BB * FF)                     // 16384
#define NW 384
#define KCI 1600
#define EPSV 1e-5f

// ---------------------------------------------------------------------------
// Scratch
// ---------------------------------------------------------------------------
__device__ float g_z2[NE];                 // GCN2 pre-BN output [node][c]
__device__ __nv_bfloat16 g_zhi[NE];        // act(z2) bf16 hi
__device__ __nv_bfloat16 g_zlo[NE];        // act(z2) bf16 lo
__device__ float g_y[MTOT * NW];           // conv1 GEMM output (pre shift-add)
__device__ __nv_bfloat16 g_wwhi[NW * KCI]; // tap-split conv1 weights, bf16 hi
__device__ __nv_bfloat16 g_wwlo[NW * KCI]; // bf16 lo residual
__device__ __nv_bfloat16 g_w2hb[FILT * FILT]; // W2 split bf16, [n_out][k_in]
__device__ __nv_bfloat16 g_w2lb[FILT * FILT];
__device__ float g_w1out[BB * C1 * FF];    // conv1 raw output (pre-BN)
__device__ float g_v[BB * FILT * FF];      // conv2 raw output (pre-BN)
__device__ float g_p1[2 * 64 * 1024];
__device__ float g_p2[2 * 64 * 3200];
__device__ float g_pC1[2 * 128 * 512];
__device__ float g_pC2[2 * 64 * 256];
__device__ float g_scale1[64], g_shift1[64];
__device__ float g_scale2[64], g_shift2[64];
__device__ float g_scaleC1[128], g_shiftC1[128];
__device__ float g_scaleC2[64], g_shiftC2[64];

__device__ __forceinline__ float dinvf(int j) {
    return (j == 0 || j == JJ - 1) ? 0.70710678118654752f : 0.57735026918962576f;
}
__device__ __forceinline__ float lrelu(float v) { return v >= 0.f ? v : 0.2f * v; }

#define MMA_BF16(d, av, b0, b1) \
    asm volatile("mma.sync.aligned.m16n8k16.row.col.f32.bf16.bf16.f32 " \
        "{%0,%1,%2,%3}, {%4,%5,%6,%7}, {%8,%9}, {%0,%1,%2,%3};" \
        : "+f"((d)[0]), "+f"((d)[1]), "+f"((d)[2]), "+f"((d)[3]) \
        : "r"((av)[0]), "r"((av)[1]), "r"((av)[2]), "r"((av)[3]), \
          "r"(b0), "r"(b1))

__device__ __forceinline__ void cp_async16(uint32_t saddr, const void* g) {
    asm volatile("cp.async.cg.shared.global [%0], [%1], 16;" :: "r"(saddr), "l"(g) : "memory");
}

// ---------------------------------------------------------------------------
// K0: merged prep + gcn1 stats.
// ---------------------------------------------------------------------------
__global__ __launch_bounds__(256) void prep_stats(
    const float* __restrict__ cw1, const float* __restrict__ W2,
    const float* __restrict__ x, const float* __restrict__ W1,
    const float* __restrict__ b1,
    __nv_bfloat16* __restrict__ whi, __nv_bfloat16* __restrict__ wlo,
    __nv_bfloat16* __restrict__ w2h, __nv_bfloat16* __restrict__ w2l,
    float* __restrict__ part) {
    int bid = blockIdx.x;
    int tid = threadIdx.x;
    if (bid < 2400) {
        int idx = bid * 256 + tid;                // < 614400 exactly
        int n = idx / KCI, ci = idx - n * KCI;
        int k = n >> 7, o = n & 127;
        float w = cw1[(size_t)o * 4800 + ci * 3 + k];
        __nv_bfloat16 hb = __float2bfloat16(w);
        whi[idx] = hb;
        wlo[idx] = __float2bfloat16(w - __bfloat162float(hb));
        return;
    }
    if (bid < 2416) {
        int i = (bid - 2400) * 256 + tid;         // < 4096
        int n = i >> 6, k = i & 63;
        float w = W2[k * 64 + n];
        __nv_bfloat16 hb = __float2bfloat16(w);
        w2h[i] = hb;
        w2l[i] = __float2bfloat16(w - __bfloat162float(hb));
        return;
    }
    // ---- gcn1 stats ----
    int sb = bid - 2416;                          // 0..1023
    __shared__ float xs[1200], xef[1200], W1s[192], b1s[64], ss[256], qq[256];
    if (tid < 192) W1s[tid] = W1[tid];
    if (tid < 64) b1s[tid] = b1[tid];
    int base = sb * 1200;
    for (int i = tid; i < 1200; i += 256) xs[i] = x[base + i];
    __syncthreads();
    for (int i = tid; i < 400; i += 256) {
        int j = i % 25;
        float dj = dinvf(j);
        float cm = (j > 0) ? dinvf(j - 1) : 0.f;
        float cp = (j < 24) ? dinvf(j + 1) : 0.f;
        int im = (i > 0) ? i - 1 : 0, ip = (i < 399) ? i + 1 : 399;
#pragma unroll
        for (int d = 0; d < 3; d++)
            xef[i * 3 + d] = dj * (dj * xs[i * 3 + d] + cm * xs[im * 3 + d] + cp * xs[ip * 3 + d]);
    }
    __syncthreads();

    int c = tid & 63, sub = tid >> 6;
    float w0 = W1s[c], w1 = W1s[64 + c], w2 = W1s[128 + c], bb = b1s[c];
    float s = 0.f, q = 0.f;
    for (int it = 0; it < 100; it++) {
        int nl = it * 4 + sub;
        float z = xef[nl * 3] * w0 + xef[nl * 3 + 1] * w1 + xef[nl * 3 + 2] * w2 + bb;
        s += z; q += z * z;
    }
    ss[tid] = s; qq[tid] = q;
    __syncthreads();
    if (tid < 64) {
        s = ss[tid] + ss[tid + 64] + ss[tid + 128] + ss[tid + 192];
        q = qq[tid] + qq[tid + 64] + qq[tid + 128] + qq[tid + 192];
        part[tid * 1024 + sb] = s;
        part[65536 + tid * 1024 + sb] = q;
    }
}

// ---------------------------------------------------------------------------
// BN finalize: part layout S at [c*R + r], Q at [C*R + c*R + r].
// ---------------------------------------------------------------------------
__global__ __launch_bounds__(256) void bn_final(
    const float* __restrict__ part, int R, int C,
    const float* __restrict__ g, const float* __restrict__ be, float invN,
    float* __restrict__ scale, float* __restrict__ shift) {
    int c = blockIdx.x, tid = threadIdx.x;
    __shared__ float ss[256], qq[256];
    const float* pS = part + (size_t)c * R;
    const float* pQ = part + (size_t)C * R + (size_t)c * R;
    float s = 0.f, q = 0.f;
    for (int r = tid; r < R; r += 256) { s += pS[r]; q += pQ[r]; }
    ss[tid] = s; qq[tid] = q;
    __syncthreads();
    for (int o = 128; o > 0; o >>= 1) {
        if (tid < o) { ss[tid] += ss[tid + o]; qq[tid] += qq[tid + o]; }
        __syncthreads();
    }
    if (tid == 0) {
        float m = ss[0] * invN;
        float var = qq[0] * invN - m * m;
        float rstd = rsqrtf(var + EPSV);
        float sc = g[c] * rstd;
        scale[c] = sc;
        shift[c] = be[c] - m * sc;
    }
}

// ---------------------------------------------------------------------------
// K2: gcn2 via bf16x3 MMA (unchanged from passing round 13).
// ---------------------------------------------------------------------------
#define G2S 72
#define G2_BYTES 55296

__global__ __launch_bounds__(256) void gcn2_mma(
    const float* __restrict__ x, const float* __restrict__ W1,
    const float* __restrict__ b1, const float* __restrict__ sc1,
    const float* __restrict__ sh1, const __nv_bfloat16* __restrict__ w2hb,
    const __nv_bfloat16* __restrict__ w2lb, const float* __restrict__ b2,
    float* __restrict__ part, float* __restrict__ z2b) {
    extern __shared__ __align__(16) char dynraw[];
    __nv_bfloat16* Ahi = reinterpret_cast<__nv_bfloat16*>(dynraw);
    __nv_bfloat16* Alo = reinterpret_cast<__nv_bfloat16*>(dynraw + 18432);
    __nv_bfloat16* Bhi = reinterpret_cast<__nv_bfloat16*>(dynraw + 36864);
    __nv_bfloat16* Blo = reinterpret_cast<__nv_bfloat16*>(dynraw + 46080);
    __shared__ __align__(16) float xs[396], xef[520];
    __shared__ __align__(16) float W1s[192], b1s[64], sc1s[64], sh1s[64], b2s[64];
    __shared__ float redS[256], redQ[256];

    int tid = threadIdx.x, lane = tid & 31, wid = tid >> 5;
    int n0 = blockIdx.x * 128;

    if (tid < 192) W1s[tid] = W1[tid];
    if (tid < 64) {
        b1s[tid] = b1[tid]; sc1s[tid] = sc1[tid];
        sh1s[tid] = sh1[tid]; b2s[tid] = b2[tid];
    }
    for (int i = tid; i < 396; i += 256) {
        int gi = (n0 - 2) * 3 + i;
        xs[i] = (gi >= 0 && gi < NNODES * 3) ? x[gi] : 0.f;
    }
    for (int i = tid; i < 2048; i += 256) {
        int n = i >> 5, kk = i & 31;
        *reinterpret_cast<uint32_t*>(Bhi + n * G2S + kk * 2) =
            *reinterpret_cast<const uint32_t*>(w2hb + n * 64 + kk * 2);
        *reinterpret_cast<uint32_t*>(Blo + n * G2S + kk * 2) =
            *reinterpret_cast<const uint32_t*>(w2lb + n * 64 + kk * 2);
    }
    __syncthreads();

    for (int i = tid; i < 130; i += 256) {
        int m = n0 - 1 + i;
        float e0 = 0.f, e1 = 0.f, e2 = 0.f;
        if (m >= 0 && m < NNODES) {
            int j = m % 25;
            float dj = dinvf(j);
            float cm = (j > 0) ? dinvf(j - 1) : 0.f;
            float cp = (j < 24) ? dinvf(j + 1) : 0.f;
            const float* xc = xs + (i + 1) * 3;
            e0 = dj * (dj * xc[0] + cm * xc[-3] + cp * xc[3]);
            e1 = dj * (dj * xc[1] + cm * xc[-2] + cp * xc[4]);
            e2 = dj * (dj * xc[2] + cm * xc[-1] + cp * xc[5]);
        }
        xef[i * 4] = e0; xef[i * 4 + 1] = e1; xef[i * 4 + 2] = e2;
    }
    __syncthreads();

    {
        const float4* W1s4 = reinterpret_cast<const float4*>(W1s);
        const float4* b4 = reinterpret_cast<const float4*>(b1s);
        const float4* sc4 = reinterpret_cast<const float4*>(sc1s);
        const float4* sh4 = reinterpret_cast<const float4*>(sh1s);
        for (int i = tid; i < 2048; i += 256) {
            int cg = i & 15, nl = i >> 4;
            int m = n0 + nl, j = m % 25;
            float dj = dinvf(j);
            float cm = (j > 0) ? dinvf(j - 1) : 0.f;
            float cp = (j < 24) ? dinvf(j + 1) : 0.f;
            float4 w0 = W1s4[cg], w1 = W1s4[16 + cg], w2 = W1s4[32 + cg];
            float4 bb = b4[cg], sv = sc4[cg], hs = sh4[cg];
            float4 h[3];
#pragma unroll
            for (int d = 0; d < 3; d++) {
                float e0 = xef[(nl + d) * 4], e1 = xef[(nl + d) * 4 + 1],
                      e2 = xef[(nl + d) * 4 + 2];
                float4 z;
                z.x = e0 * w0.x + e1 * w1.x + e2 * w2.x + bb.x;
                z.y = e0 * w0.y + e1 * w1.y + e2 * w2.y + bb.y;
                z.z = e0 * w0.z + e1 * w1.z + e2 * w2.z + bb.z;
                z.w = e0 * w0.w + e1 * w1.w + e2 * w2.w + bb.w;
                h[d].x = lrelu(fmaf(z.x, sv.x, hs.x));
                h[d].y = lrelu(fmaf(z.y, sv.y, hs.y));
                h[d].z = lrelu(fmaf(z.z, sv.z, hs.z));
                h[d].w = lrelu(fmaf(z.w, sv.w, hs.w));
            }
            float4 v;
            v.x = dj * (dj * h[1].x + cm * h[0].x + cp * h[2].x);
            v.y = dj * (dj * h[1].y + cm * h[0].y + cp * h[2].y);
            v.z = dj * (dj * h[1].z + cm * h[0].z + cp * h[2].z);
            v.w = dj * (dj * h[1].w + cm * h[0].w + cp * h[2].w);
            __nv_bfloat16 hx = __float2bfloat16(v.x), hy = __float2bfloat16(v.y);
            __nv_bfloat16 hz = __float2bfloat16(v.z), hw = __float2bfloat16(v.w);
            __nv_bfloat16 lx = __float2bfloat16(v.x - __bfloat162float(hx));
            __nv_bfloat16 ly = __float2bfloat16(v.y - __bfloat162float(hy));
            __nv_bfloat16 lz = __float2bfloat16(v.z - __bfloat162float(hz));
            __nv_bfloat16 lw = __float2bfloat16(v.w - __bfloat162float(hw));
            int di = nl * G2S + cg * 4;
            *reinterpret_cast<__nv_bfloat162*>(Ahi + di)     = __halves2bfloat162(hx, hy);
            *reinterpret_cast<__nv_bfloat162*>(Ahi + di + 2) = __halves2bfloat162(hz, hw);
            *reinterpret_cast<__nv_bfloat162*>(Alo + di)     = __halves2bfloat162(lx, ly);
            *reinterpret_cast<__nv_bfloat162*>(Alo + di + 2) = __halves2bfloat162(lz, lw);
        }
    }
    __syncthreads();

    int wm = wid & 3, wn = wid >> 2;
    float acc[2][4][4];
#pragma unroll
    for (int mt = 0; mt < 2; mt++)
#pragma unroll
        for (int nt = 0; nt < 4; nt++)
#pragma unroll
            for (int u = 0; u < 4; u++) acc[mt][nt][u] = 0.f;

#pragma unroll
    for (int kt = 0; kt < 4; kt++) {
        uint32_t ahi[2][4], alo[2][4], bhi[4][2], blo[4][2];
        int abase = (wm * 32 + (lane >> 2)) * G2S + (lane & 3) * 2 + kt * 16;
#pragma unroll
        for (int mt = 0; mt < 2; mt++) {
            int o = abase + mt * 16 * G2S;
            ahi[mt][0] = *reinterpret_cast<const uint32_t*>(Ahi + o);
            ahi[mt][1] = *reinterpret_cast<const uint32_t*>(Ahi + o + 8 * G2S);
            ahi[mt][2] = *reinterpret_cast<const uint32_t*>(Ahi + o + 8);
            ahi[mt][3] = *reinterpret_cast<const uint32_t*>(Ahi + o + 8 * G2S + 8);
            alo[mt][0] = *reinterpret_cast<const uint32_t*>(Alo + o);
            alo[mt][1] = *reinterpret_cast<const uint32_t*>(Alo + o + 8 * G2S);
            alo[mt][2] = *reinterpret_cast<const uint32_t*>(Alo + o + 8);
            alo[mt][3] = *reinterpret_cast<const uint32_t*>(Alo + o + 8 * G2S + 8);
        }
        int bbase = (wn * 32 + (lane >> 2)) * G2S + (lane & 3) * 2 + kt * 16;
#pragma unroll
        for (int nt = 0; nt < 4; nt++) {
            int o = bbase + nt * 8 * G2S;
            bhi[nt][0] = *reinterpret_cast<const uint32_t*>(Bhi + o);
            bhi[nt][1] = *reinterpret_cast<const uint32_t*>(Bhi + o + 8);
            blo[nt][0] = *reinterpret_cast<const uint32_t*>(Blo + o);
            blo[nt][1] = *reinterpret_cast<const uint32_t*>(Blo + o + 8);
        }
#pragma unroll
        for (int nt = 0; nt < 4; nt++) {
            MMA_BF16(acc[0][nt], ahi[0], bhi[nt][0], bhi[nt][1]);
            MMA_BF16(acc[1][nt], ahi[1], bhi[nt][0], bhi[nt][1]);
        }
#pragma unroll
        for (int nt = 0; nt < 4; nt++) {
            MMA_BF16(acc[0][nt], ahi[0], blo[nt][0], blo[nt][1]);
            MMA_BF16(acc[1][nt], ahi[1], blo[nt][0], blo[nt][1]);
        }
#pragma unroll
        for (int nt = 0; nt < 4; nt++) {
            MMA_BF16(acc[0][nt], alo[0], bhi[nt][0], bhi[nt][1]);
            MMA_BF16(acc[1][nt], alo[1], bhi[nt][0], bhi[nt][1]);
        }
    }

#pragma unroll
    for (int nt = 0; nt < 4; nt++) {
        int c0 = wn * 32 + nt * 8 + ((lane & 3) << 1);
        float bb0 = b2s[c0], bb1 = b2s[c0 + 1];
        float s0 = 0.f, q0 = 0.f, s1 = 0.f, q1 = 0.f;
#pragma unroll
        for (int mt = 0; mt < 2; mt++) {
            int row = n0 + wm * 32 + mt * 16 + (lane >> 2);
            float u0 = acc[mt][nt][0] + bb0, u1 = acc[mt][nt][1] + bb1;
            float u2 = acc[mt][nt][2] + bb0, u3 = acc[mt][nt][3] + bb1;
            *reinterpret_cast<float2*>(z2b + (size_t)row * 64 + c0) = make_float2(u0, u1);
            *reinterpret_cast<float2*>(z2b + (size_t)(row + 8) * 64 + c0) = make_float2(u2, u3);
            s0 += u0 + u2; q0 += u0 * u0 + u2 * u2;
            s1 += u1 + u3; q1 += u1 * u1 + u3 * u3;
        }
#pragma unroll
        for (int o = 4; o < 32; o <<= 1) {
            s0 += __shfl_xor_sync(0xffffffffu, s0, o);
            q0 += __shfl_xor_sync(0xffffffffu, q0, o);
            s1 += __shfl_xor_sync(0xffffffffu, s1, o);
            q1 += __shfl_xor_sync(0xffffffffu, q1, o);
        }
        if (lane < 4) {
            redS[c0 * 4 + wm] = s0; redS[(c0 + 1) * 4 + wm] = s1;
            redQ[c0 * 4 + wm] = q0; redQ[(c0 + 1) * 4 + wm] = q1;
        }
    }
    __syncthreads();
    if (tid < 64) {
        float S = redS[tid * 4] + redS[tid * 4 + 1] + redS[tid * 4 + 2] + redS[tid * 4 + 3];
        float Q = redQ[tid * 4] + redQ[tid * 4 + 1] + redQ[tid * 4 + 2] + redQ[tid * 4 + 3];
        part[tid * 3200 + blockIdx.x] = S;
        part[204800 + tid * 3200 + blockIdx.x] = Q;
    }
}

// ---------------------------------------------------------------------------
// K2b: z2 convert — BN2+LReLU+bf16 split, streamed once. grid 25600.
// ---------------------------------------------------------------------------
__global__ __launch_bounds__(256) void z2convert(
    const float* __restrict__ z2, const float* __restrict__ sc,
    const float* __restrict__ sh, __nv_bfloat16* __restrict__ zhi,
    __nv_bfloat16* __restrict__ zlo) {
    __shared__ float scs[64], shs[64];
    int tid = threadIdx.x;
    if (tid < 64) { scs[tid] = sc[tid]; shs[tid] = sh[tid]; }
    __syncthreads();
    size_t base = (size_t)blockIdx.x * 1024 + tid * 4;   // 4 elems/thread
    int c = (tid * 4) & 63;
    float4 v = *reinterpret_cast<const float4*>(z2 + base);
    v.x = lrelu(fmaf(v.x, scs[c],     shs[c]));
    v.y = lrelu(fmaf(v.y, scs[c + 1], shs[c + 1]));
    v.z = lrelu(fmaf(v.z, scs[c + 2], shs[c + 2]));
    v.w = lrelu(fmaf(v.w, scs[c + 3], shs[c + 3]));
    __nv_bfloat16 hx = __float2bfloat16(v.x), hy = __float2bfloat16(v.y);
    __nv_bfloat16 hz = __float2bfloat16(v.z), hw = __float2bfloat16(v.w);
    __nv_bfloat16 lx = __float2bfloat16(v.x - __bfloat162float(hx));
    __nv_bfloat16 ly = __float2bfloat16(v.y - __bfloat162float(hy));
    __nv_bfloat16 lz = __float2bfloat16(v.z - __bfloat162float(hz));
    __nv_bfloat16 lw = __float2bfloat16(v.w - __bfloat162float(hw));
    *reinterpret_cast<__nv_bfloat162*>(zhi + base)     = __halves2bfloat162(hx, hy);
    *reinterpret_cast<__nv_bfloat162*>(zhi + base + 2) = __halves2bfloat162(hz, hw);
    *reinterpret_cast<__nv_bfloat162*>(zlo + base)     = __halves2bfloat162(lx, ly);
    *reinterpret_cast<__nv_bfloat162*>(zlo + base + 2) = __halves2bfloat162(lz, lw);
}

// ---------------------------------------------------------------------------
// K3: conv1 bf16x3 GEMM, v2 — A pre-split, all operands via cp.async.
// ---------------------------------------------------------------------------
#define TILEB 5120                                   // 128*40 bf16
#define CM_BYTES (8 * TILEB * 2)                     // 81920

__global__ __launch_bounds__(256) void conv1_mma(
    const __nv_bfloat16* __restrict__ zhi, const __nv_bfloat16* __restrict__ zlo,
    const __nv_bfloat16* __restrict__ wwhi, const __nv_bfloat16* __restrict__ wwlo,
    float* __restrict__ y) {
    extern __shared__ __align__(16) char dynraw[];
    __nv_bfloat16* sm = reinterpret_cast<__nv_bfloat16*>(dynraw);
    int tid = threadIdx.x, lane = tid & 31, wid = tid >> 5;
    int wm = wid & 3, wn = wid >> 2;
    int m0 = blockIdx.y * 128, n0 = blockIdx.x * 128;

    float acc[2][8][4];
#pragma unroll
    for (int mt = 0; mt < 2; mt++)
#pragma unroll
        for (int nt = 0; nt < 8; nt++)
#pragma unroll
            for (int u = 0; u < 4; u++) acc[mt][nt][u] = 0.f;

#define LOADAB(bufi, step) do { \
        int ci0_ = (step) * 32; \
        __nv_bfloat16* Ah_ = sm + (bufi) * 4 * TILEB; \
        __nv_bfloat16* Al_ = Ah_ + TILEB; \
        __nv_bfloat16* Bh_ = Ah_ + 2 * TILEB; \
        __nv_bfloat16* Bl_ = Ah_ + 3 * TILEB; \
        _Pragma("unroll") \
        for (int u = 0; u < 4; u++) { \
            int fi = u * 256 + tid; \
            int sel = fi >> 9, rem = fi & 511; \
            int row = rem >> 2, gg = rem & 3; \
            const __nv_bfloat16* src = (sel ? zlo : zhi) + \
                (size_t)(m0 + row) * KCI + ci0_ + gg * 8; \
            __nv_bfloat16* dst = (sel ? Al_ : Ah_) + row * 40 + gg * 8; \
            cp_async16((uint32_t)__cvta_generic_to_shared(dst), src); \
        } \
        _Pragma("unroll") \
        for (int u = 0; u < 4; u++) { \
            int fi = u * 256 + tid; \
            int sel = fi >> 9, rem = fi & 511; \
            int row = rem >> 2, gg = rem & 3; \
            const __nv_bfloat16* src = (sel ? wwlo : wwhi) + \
                (size_t)(n0 + row) * KCI + ci0_ + gg * 8; \
            __nv_bfloat16* dst = (sel ? Bl_ : Bh_) + row * 40 + gg * 8; \
            cp_async16((uint32_t)__cvta_generic_to_shared(dst), src); \
        } \
        asm volatile("cp.async.commit_group;" ::: "memory"); \
    } while (0)

    LOADAB(0, 0);

    for (int i = 0; i < 50; i++) {
        int buf = i & 1;
        asm volatile("cp.async.wait_group 0;" ::: "memory");
        __syncthreads();
        if (i < 49) LOADAB(buf ^ 1, i + 1);

        const __nv_bfloat16* Ahi = sm + buf * 4 * TILEB;
        const __nv_bfloat16* Alo = Ahi + TILEB;
        const __nv_bfloat16* Bhi = Ahi + 2 * TILEB;
        const __nv_bfloat16* Blo = Ahi + 3 * TILEB;
#pragma unroll
        for (int kt = 0; kt < 2; kt++) {
            uint32_t ahi[2][4], alo[2][4], bhi[8][2], blo[8][2];
            int abase = (wm * 32 + (lane >> 2)) * 40 + (lane & 3) * 2 + kt * 16;
#pragma unroll
            for (int mt = 0; mt < 2; mt++) {
                int o = abase + mt * 640;
                ahi[mt][0] = *reinterpret_cast<const uint32_t*>(Ahi + o);
                ahi[mt][1] = *reinterpret_cast<const uint32_t*>(Ahi + o + 320);
                ahi[mt][2] = *reinterpret_cast<const uint32_t*>(Ahi + o + 8);
                ahi[mt][3] = *reinterpret_cast<const uint32_t*>(Ahi + o + 328);
                alo[mt][0] = *reinterpret_cast<const uint32_t*>(Alo + o);
                alo[mt][1] = *reinterpret_cast<const uint32_t*>(Alo + o + 320);
                alo[mt][2] = *reinterpret_cast<const uint32_t*>(Alo + o + 8);
                alo[mt][3] = *reinterpret_cast<const uint32_t*>(Alo + o + 328);
            }
            int bbase = (wn * 64 + (lane >> 2)) * 40 + (lane & 3) * 2 + kt * 16;
#pragma unroll
            for (int nt = 0; nt < 8; nt++) {
                int o = bbase + nt * 320;
                bhi[nt][0] = *reinterpret_cast<const uint32_t*>(Bhi + o);
                bhi[nt][1] = *reinterpret_cast<const uint32_t*>(Bhi + o + 8);
                blo[nt][0] = *reinterpret_cast<const uint32_t*>(Blo + o);
                blo[nt][1] = *reinterpret_cast<const uint32_t*>(Blo + o + 8);
            }
#pragma unroll
            for (int nt = 0; nt < 8; nt++) {
                MMA_BF16(acc[0][nt], ahi[0], bhi[nt][0], bhi[nt][1]);
                MMA_BF16(acc[1][nt], ahi[1], bhi[nt][0], bhi[nt][1]);
            }
#pragma unroll
            for (int nt = 0; nt < 8; nt++) {
                MMA_BF16(acc[0][nt], ahi[0], blo[nt][0], blo[nt][1]);
                MMA_BF16(acc[1][nt], ahi[1], blo[nt][0], blo[nt][1]);
            }
#pragma unroll
            for (int nt = 0; nt < 8; nt++) {
                MMA_BF16(acc[0][nt], alo[0], bhi[nt][0], bhi[nt][1]);
                MMA_BF16(acc[1][nt], alo[1], bhi[nt][0], bhi[nt][1]);
            }
        }
    }

#pragma unroll
    for (int mt = 0; mt < 2; mt++) {
#pragma unroll
        for (int nt = 0; nt < 8; nt++) {
            int row = m0 + wm * 32 + mt * 16 + (lane >> 2);
            int col = n0 + wn * 64 + nt * 8 + ((lane & 3) << 1);
            float2 v0 = make_float2(acc[mt][nt][0], acc[mt][nt][1]);
            float2 v1 = make_float2(acc[mt][nt][2], acc[mt][nt][3]);
            *reinterpret_cast<float2*>(y + (size_t)row * NW + col) = v0;
            *reinterpret_cast<float2*>(y + (size_t)(row + 8) * NW + col) = v1;
        }
    }
#undef LOADAB
}

// ---------------------------------------------------------------------------
// K4: shift-add epilogue + fused per-channel stats. 32-frame tiles, grid (8,64).
// ---------------------------------------------------------------------------
__global__ __launch_bounds__(256) void shiftadd(
    const float* __restrict__ y, const float* __restrict__ cb1,
    float* __restrict__ w1o, float* __restrict__ part) {
    __shared__ float t[128 * 33];
    int tid = threadIdx.x;
    int b = blockIdx.y;
    int f0 = blockIdx.x * 32;
    for (int i = tid; i < 4096; i += 256) {
        int o = i & 127, ff = i >> 7;
        int f = f0 + ff, m = b * 256 + f;
        float val = __ldg(cb1 + o) + y[(size_t)m * NW + 128 + o];
        if (f > 0)   val += y[(size_t)(m - 1) * NW + o];
        if (f < 255) val += y[(size_t)(m + 1) * NW + 256 + o];
        t[o * 33 + ff] = val;
    }
    __syncthreads();
    for (int i = tid; i < 4096; i += 256) {
        int ff = i & 31, o = i >> 5;
        w1o[(size_t)(b * 128 + o) * 256 + f0 + ff] = t[o * 33 + ff];
    }
    if (tid < 128) {
        float S = 0.f, Q = 0.f;
#pragma unroll 8
        for (int k = 0; k < 32; k++) {
            float v = t[tid * 33 + k];
            S += v; Q += v * v;
        }
        int blk = blockIdx.y * 8 + blockIdx.x;
        part[tid * 512 + blk] = S;
        part[65536 + tid * 512 + blk] = Q;
    }
}

// ---------------------------------------------------------------------------
// K6: Conv2 (1x1, 128->64) with bnC1+lrelu fused at load + partial stats.
// ---------------------------------------------------------------------------
__global__ __launch_bounds__(256) void conv2_kernel(
    const float* __restrict__ w1o, const float* __restrict__ cw2,
    const float* __restrict__ cb2, const float* __restrict__ sc,
    const float* __restrict__ sh, float* __restrict__ vout,
    float* __restrict__ part) {
    __shared__ __align__(16) float Us[64 * 64];
    __shared__ __align__(16) float Ws2[64 * 64];
    int tid = threadIdx.x;
    int b = blockIdx.y;
    int f0 = blockIdx.x * 64;
    int fth = tid & 15, oth = tid >> 4;
    float acc[4][4] = {};

    for (int ci0 = 0; ci0 < 128; ci0 += 64) {
        for (int i = tid; i < 4096; i += 256) {
            int cc = i >> 6, ffi = i & 63;
            float raw = w1o[(size_t)(b * 128 + ci0 + cc) * 256 + f0 + ffi];
            float v = fmaf(raw, __ldg(sc + ci0 + cc), __ldg(sh + ci0 + cc));
            Us[i] = lrelu(v);
        }
        for (int i = tid; i < 4096; i += 256) {
            int o = i & 63, cc = i >> 6;
            Ws2[cc * 64 + o] = cw2[o * 128 + ci0 + cc];
        }
        __syncthreads();
#pragma unroll 8
        for (int cc = 0; cc < 64; cc++) {
            float4 iv = *reinterpret_cast<const float4*>(Us + cc * 64 + fth * 4);
            float4 wv = *reinterpret_cast<const float4*>(Ws2 + cc * 64 + oth * 4);
            acc[0][0] = fmaf(wv.x, iv.x, acc[0][0]); acc[0][1] = fmaf(wv.x, iv.y, acc[0][1]);
            acc[0][2] = fmaf(wv.x, iv.z, acc[0][2]); acc[0][3] = fmaf(wv.x, iv.w, acc[0][3]);
            acc[1][0] = fmaf(wv.y, iv.x, acc[1][0]); acc[1][1] = fmaf(wv.y, iv.y, acc[1][1]);
            acc[1][2] = fmaf(wv.y, iv.z, acc[1][2]); acc[1][3] = fmaf(wv.y, iv.w, acc[1][3]);
            acc[2][0] = fmaf(wv.z, iv.x, acc[2][0]); acc[2][1] = fmaf(wv.z, iv.y, acc[2][1]);
            acc[2][2] = fmaf(wv.z, iv.z, acc[2][2]); acc[2][3] = fmaf(wv.z, iv.w, acc[2][3]);
            acc[3][0] = fmaf(wv.w, iv.x, acc[3][0]); acc[3][1] = fmaf(wv.w, iv.y, acc[3][1]);
            acc[3][2] = fmaf(wv.w, iv.z, acc[3][2]); acc[3][3] = fmaf(wv.w, iv.w, acc[3][3]);
        }
        __syncthreads();
    }

    float* reds = Us;
    float* redq = Ws2;
#pragma unroll
    for (int i = 0; i < 4; i++) {
        int o = oth * 4 + i;
        float bias = __ldg(cb2 + o);
        float s = 0.f, q = 0.f;
#pragma unroll
        for (int j2 = 0; j2 < 4; j2++) {
            float r = acc[i][j2] + bias;
            vout[(size_t)(b * 64 + o) * 256 + f0 + fth * 4 + j2] = r;
            s += r; q += r * r;
        }
        reds[o * 17 + fth] = s;
        redq[o * 17 + fth] = q;
    }
    __syncthreads();
    if (tid < 64) {
        float S = 0.f, Q = 0.f;
#pragma unroll
        for (int t = 0; t < 16; t++) { S += reds[tid * 17 + t]; Q += redq[tid * 17 + t]; }
        int blk = blockIdx.y * 4 + blockIdx.x;
        part[tid * 256 + blk] = S;
        part[16384 + tid * 256 + blk] = Q;
    }
}

// ---------------------------------------------------------------------------
// K7: final BN + LReLU + transpose (B,64,256) -> (B,256,64)
// ---------------------------------------------------------------------------
__global__ __launch_bounds__(256) void final_kernel(
    const float* __restrict__ v, const float* __restrict__ sc,
    const float* __restrict__ sh, float* __restrict__ out) {
    __shared__ float s[64 * 65];
    int tid = threadIdx.x;
    int b = blockIdx.y;
    int f0 = blockIdx.x * 64;
    for (int i = tid; i < 4096; i += 256) {
        int o = i >> 6, ffi = i & 63;
        s[o * 65 + ffi] = v[(size_t)(b * 64 + o) * 256 + f0 + ffi];
    }
    __syncthreads();
    for (int i = tid; i < 4096; i += 256) {
        int ffi = i >> 6, o = i & 63;
        float val = fmaf(s[o * 65 + ffi], __ldg(sc + o), __ldg(sh + o));
        out[(size_t)(b * 256 + f0 + ffi) * 64 + o] = lrelu(val);
    }
}

// ---------------------------------------------------------------------------
// Launch
// ---------------------------------------------------------------------------
extern "C" void kernel_launch(void* const* d_in, const int* in_sizes, int n_in,
                              void* d_out, int out_size) {
    const float* x   = (const float*)d_in[0];
    const float* W1  = (const float*)d_in[4];
    const float* b1  = (const float*)d_in[5];
    const float* g1  = (const float*)d_in[6];
    const float* be1 = (const float*)d_in[7];
    const float* W2  = (const float*)d_in[8];
    const float* b2  = (const float*)d_in[9];
    const float* g2  = (const float*)d_in[10];
    const float* be2 = (const float*)d_in[11];
    const float* cw1 = (const float*)d_in[12];
    const float* cb1 = (const float*)d_in[13];
    const float* cg1 = (const float*)d_in[14];
    const float* cbe1= (const float*)d_in[15];
    const float* cw2 = (const float*)d_in[16];
    const float* cb2 = (const float*)d_in[17];
    const float* cg2 = (const float*)d_in[18];
    const float* cbe2= (const float*)d_in[19];
    float* out = (float*)d_out;

    float *z2, *y, *w1o, *v, *p1, *p2, *pC1, *pC2;
    __nv_bfloat16 *zhi, *zlo, *whi, *wlo, *w2h, *w2l;
    float *s1, *h1, *s2, *h2, *sC1, *hC1, *sC2, *hC2;
    cudaGetSymbolAddress((void**)&z2,  g_z2);
    cudaGetSymbolAddress((void**)&zhi, g_zhi);
    cudaGetSymbolAddress((void**)&zlo, g_zlo);
    cudaGetSymbolAddress((void**)&y,   g_y);
    cudaGetSymbolAddress((void**)&whi, g_wwhi);
    cudaGetSymbolAddress((void**)&wlo, g_wwlo);
    cudaGetSymbolAddress((void**)&w2h, g_w2hb);
    cudaGetSymbolAddress((void**)&w2l, g_w2lb);
    cudaGetSymbolAddress((void**)&w1o, g_w1out);
    cudaGetSymbolAddress((void**)&v,   g_v);
    cudaGetSymbolAddress((void**)&p1,  g_p1);
    cudaGetSymbolAddress((void**)&p2,  g_p2);
    cudaGetSymbolAddress((void**)&pC1, g_pC1);
    cudaGetSymbolAddress((void**)&pC2, g_pC2);
    cudaGetSymbolAddress((void**)&s1,  g_scale1);
    cudaGetSymbolAddress((void**)&h1,  g_shift1);
    cudaGetSymbolAddress((void**)&s2,  g_scale2);
    cudaGetSymbolAddress((void**)&h2,  g_shift2);
    cudaGetSymbolAddress((void**)&sC1, g_scaleC1);
    cudaGetSymbolAddress((void**)&hC1, g_shiftC1);
    cudaGetSymbolAddress((void**)&sC2, g_scaleC2);
    cudaGetSymbolAddress((void**)&hC2, g_shiftC2);

    cudaFuncSetAttribute(conv1_mma, cudaFuncAttributeMaxDynamicSharedMemorySize, CM_BYTES);
    cudaFuncSetAttribute(gcn2_mma,  cudaFuncAttributeMaxDynamicSharedMemorySize, G2_BYTES);

    const float invN_nodes = 1.f / (float)NNODES;
    const float invN_bf    = 1.f / (float)(BB * FF);

    prep_stats<<<3440, 256>>>(cw1, W2, x, W1, b1, whi, wlo, w2h, w2l, p1);     // 0
    bn_final<<<64, 256>>>(p1, 1024, 64, g1, be1, invN_nodes, s1, h1);          // 1
    gcn2_mma<<<3200, 256, G2_BYTES>>>(x, W1, b1, s1, h1, w2h, w2l, b2, p2, z2);// 2
    bn_final<<<64, 256>>>(p2, 3200, 64, g2, be2, invN_nodes, s2, h2);          // 3
    z2convert<<<25600, 256>>>(z2, s2, h2, zhi, zlo);                           // 4
    conv1_mma<<<dim3(3, 128), 256, CM_BYTES>>>(zhi, zlo, whi, wlo, y);         // 5
    shiftadd<<<dim3(8, BB), 256>>>(y, cb1, w1o, pC1);                          // 6
    bn_final<<<128, 256>>>(pC1, 512, 128, cg1, cbe1, invN_bf, sC1, hC1);       // 7
    conv2_kernel<<<dim3(4, BB), 256>>>(w1o, cw2, cb2, sC1, hC1, v, pC2);       // 8
    bn_final<<<64, 256>>>(pC2, 256, 64, cg2, cbe2, invN_bf, sC2, hC2);         // 9
    final_kernel<<<dim3(4, BB), 256>>>(v, sC2, hC2, out);                      // 10
}

// round 15
// speedup vs baseline: 2.0208x; 1.1232x over previous
#include <cuda_runtime.h>
#include <cuda_bf16.h>
#include <cstdint>

#define BB 64
#define FF 256
#define JJ 25
#define FILT 64
#define C1 128
#define NNODES (BB * FF * JJ)              // 409600
#define NE (NNODES * FILT)                 // 26214400
#define MTOT (BB * FF)                     // 16384
#define KCI 1600
#define EPSV 1e-5f

// ---------------------------------------------------------------------------
// Scratch
// ---------------------------------------------------------------------------
__device__ float g_z2[NE];                 // GCN2 pre-BN output [node][c]
__device__ __nv_bfloat16 g_zhi[NE];        // act(z2) bf16 hi
__device__ __nv_bfloat16 g_zlo[NE];        // act(z2) bf16 lo
__device__ __nv_bfloat16 g_wwhi[384 * KCI];// tap-split conv1 weights, bf16 hi
__device__ __nv_bfloat16 g_wwlo[384 * KCI];// bf16 lo residual
__device__ __nv_bfloat16 g_w2hb[FILT * FILT];
__device__ __nv_bfloat16 g_w2lb[FILT * FILT];
__device__ float g_w1out[BB * C1 * FF];    // conv1 raw output (pre-BN)
__device__ float g_v[BB * FILT * FF];      // conv2 raw output (pre-BN)
__device__ float g_p1[2 * 64 * 1024];
__device__ float g_p2[2 * 64 * 3200];
__device__ float g_pC1[2 * 128 * 128];
__device__ float g_pC2[2 * 64 * 256];
__device__ float g_scale1[64], g_shift1[64];
__device__ float g_scale2[64], g_shift2[64];
__device__ float g_scaleC1[128], g_shiftC1[128];
__device__ float g_scaleC2[64], g_shiftC2[64];

__device__ __forceinline__ float dinvf(int j) {
    return (j == 0 || j == JJ - 1) ? 0.70710678118654752f : 0.57735026918962576f;
}
__device__ __forceinline__ float lrelu(float v) { return v >= 0.f ? v : 0.2f * v; }

#define MMA_BF16(d, av, b0, b1) \
    asm volatile("mma.sync.aligned.m16n8k16.row.col.f32.bf16.bf16.f32 " \
        "{%0,%1,%2,%3}, {%4,%5,%6,%7}, {%8,%9}, {%0,%1,%2,%3};" \
        : "+f"((d)[0]), "+f"((d)[1]), "+f"((d)[2]), "+f"((d)[3]) \
        : "r"((av)[0]), "r"((av)[1]), "r"((av)[2]), "r"((av)[3]), \
          "r"(b0), "r"(b1))

__device__ __forceinline__ void cp_async16(uint32_t saddr, const void* g) {
    asm volatile("cp.async.cg.shared.global [%0], [%1], 16;" :: "r"(saddr), "l"(g) : "memory");
}

// ---------------------------------------------------------------------------
// K0: merged prep + gcn1 stats. (unchanged, passing)
// ---------------------------------------------------------------------------
__global__ __launch_bounds__(256) void prep_stats(
    const float* __restrict__ cw1, const float* __restrict__ W2,
    const float* __restrict__ x, const float* __restrict__ W1,
    const float* __restrict__ b1,
    __nv_bfloat16* __restrict__ whi, __nv_bfloat16* __restrict__ wlo,
    __nv_bfloat16* __restrict__ w2h, __nv_bfloat16* __restrict__ w2l,
    float* __restrict__ part) {
    int bid = blockIdx.x;
    int tid = threadIdx.x;
    if (bid < 2400) {
        int idx = bid * 256 + tid;                // < 614400 exactly
        int n = idx / KCI, ci = idx - n * KCI;
        int k = n >> 7, o = n & 127;
        float w = cw1[(size_t)o * 4800 + ci * 3 + k];
        __nv_bfloat16 hb = __float2bfloat16(w);
        whi[idx] = hb;
        wlo[idx] = __float2bfloat16(w - __bfloat162float(hb));
        return;
    }
    if (bid < 2416) {
        int i = (bid - 2400) * 256 + tid;         // < 4096
        int n = i >> 6, k = i & 63;
        float w = W2[k * 64 + n];
        __nv_bfloat16 hb = __float2bfloat16(w);
        w2h[i] = hb;
        w2l[i] = __float2bfloat16(w - __bfloat162float(hb));
        return;
    }
    int sb = bid - 2416;                          // 0..1023
    __shared__ float xs[1200], xef[1200], W1s[192], b1s[64], ss[256], qq[256];
    if (tid < 192) W1s[tid] = W1[tid];
    if (tid < 64) b1s[tid] = b1[tid];
    int base = sb * 1200;
    for (int i = tid; i < 1200; i += 256) xs[i] = x[base + i];
    __syncthreads();
    for (int i = tid; i < 400; i += 256) {
        int j = i % 25;
        float dj = dinvf(j);
        float cm = (j > 0) ? dinvf(j - 1) : 0.f;
        float cp = (j < 24) ? dinvf(j + 1) : 0.f;
        int im = (i > 0) ? i - 1 : 0, ip = (i < 399) ? i + 1 : 399;
#pragma unroll
        for (int d = 0; d < 3; d++)
            xef[i * 3 + d] = dj * (dj * xs[i * 3 + d] + cm * xs[im * 3 + d] + cp * xs[ip * 3 + d]);
    }
    __syncthreads();

    int c = tid & 63, sub = tid >> 6;
    float w0 = W1s[c], w1 = W1s[64 + c], w2 = W1s[128 + c], bb = b1s[c];
    float s = 0.f, q = 0.f;
    for (int it = 0; it < 100; it++) {
        int nl = it * 4 + sub;
        float z = xef[nl * 3] * w0 + xef[nl * 3 + 1] * w1 + xef[nl * 3 + 2] * w2 + bb;
        s += z; q += z * z;
    }
    ss[tid] = s; qq[tid] = q;
    __syncthreads();
    if (tid < 64) {
        s = ss[tid] + ss[tid + 64] + ss[tid + 128] + ss[tid + 192];
        q = qq[tid] + qq[tid + 64] + qq[tid + 128] + qq[tid + 192];
        part[tid * 1024 + sb] = s;
        part[65536 + tid * 1024 + sb] = q;
    }
}

// ---------------------------------------------------------------------------
// BN finalize: part layout S at [c*R + r], Q at [C*R + c*R + r].
// ---------------------------------------------------------------------------
__global__ __launch_bounds__(256) void bn_final(
    const float* __restrict__ part, int R, int C,
    const float* __restrict__ g, const float* __restrict__ be, float invN,
    float* __restrict__ scale, float* __restrict__ shift) {
    int c = blockIdx.x, tid = threadIdx.x;
    __shared__ float ss[256], qq[256];
    const float* pS = part + (size_t)c * R;
    const float* pQ = part + (size_t)C * R + (size_t)c * R;
    float s = 0.f, q = 0.f;
    for (int r = tid; r < R; r += 256) { s += pS[r]; q += pQ[r]; }
    ss[tid] = s; qq[tid] = q;
    __syncthreads();
    for (int o = 128; o > 0; o >>= 1) {
        if (tid < o) { ss[tid] += ss[tid + o]; qq[tid] += qq[tid + o]; }
        __syncthreads();
    }
    if (tid == 0) {
        float m = ss[0] * invN;
        float var = qq[0] * invN - m * m;
        float rstd = rsqrtf(var + EPSV);
        float sc = g[c] * rstd;
        scale[c] = sc;
        shift[c] = be[c] - m * sc;
    }
}

// ---------------------------------------------------------------------------
// K2: gcn2 via bf16x3 MMA (unchanged, passing).
// ---------------------------------------------------------------------------
#define G2S 72
#define G2_BYTES 55296

__global__ __launch_bounds__(256) void gcn2_mma(
    const float* __restrict__ x, const float* __restrict__ W1,
    const float* __restrict__ b1, const float* __restrict__ sc1,
    const float* __restrict__ sh1, const __nv_bfloat16* __restrict__ w2hb,
    const __nv_bfloat16* __restrict__ w2lb, const float* __restrict__ b2,
    float* __restrict__ part, float* __restrict__ z2b) {
    extern __shared__ __align__(16) char dynraw[];
    __nv_bfloat16* Ahi = reinterpret_cast<__nv_bfloat16*>(dynraw);
    __nv_bfloat16* Alo = reinterpret_cast<__nv_bfloat16*>(dynraw + 18432);
    __nv_bfloat16* Bhi = reinterpret_cast<__nv_bfloat16*>(dynraw + 36864);
    __nv_bfloat16* Blo = reinterpret_cast<__nv_bfloat16*>(dynraw + 46080);
    __shared__ __align__(16) float xs[396], xef[520];
    __shared__ __align__(16) float W1s[192], b1s[64], sc1s[64], sh1s[64], b2s[64];
    __shared__ float redS[256], redQ[256];

    int tid = threadIdx.x, lane = tid & 31, wid = tid >> 5;
    int n0 = blockIdx.x * 128;

    if (tid < 192) W1s[tid] = W1[tid];
    if (tid < 64) {
        b1s[tid] = b1[tid]; sc1s[tid] = sc1[tid];
        sh1s[tid] = sh1[tid]; b2s[tid] = b2[tid];
    }
    for (int i = tid; i < 396; i += 256) {
        int gi = (n0 - 2) * 3 + i;
        xs[i] = (gi >= 0 && gi < NNODES * 3) ? x[gi] : 0.f;
    }
    for (int i = tid; i < 2048; i += 256) {
        int n = i >> 5, kk = i & 31;
        *reinterpret_cast<uint32_t*>(Bhi + n * G2S + kk * 2) =
            *reinterpret_cast<const uint32_t*>(w2hb + n * 64 + kk * 2);
        *reinterpret_cast<uint32_t*>(Blo + n * G2S + kk * 2) =
            *reinterpret_cast<const uint32_t*>(w2lb + n * 64 + kk * 2);
    }
    __syncthreads();

    for (int i = tid; i < 130; i += 256) {
        int m = n0 - 1 + i;
        float e0 = 0.f, e1 = 0.f, e2 = 0.f;
        if (m >= 0 && m < NNODES) {
            int j = m % 25;
            float dj = dinvf(j);
            float cm = (j > 0) ? dinvf(j - 1) : 0.f;
            float cp = (j < 24) ? dinvf(j + 1) : 0.f;
            const float* xc = xs + (i + 1) * 3;
            e0 = dj * (dj * xc[0] + cm * xc[-3] + cp * xc[3]);
            e1 = dj * (dj * xc[1] + cm * xc[-2] + cp * xc[4]);
            e2 = dj * (dj * xc[2] + cm * xc[-1] + cp * xc[5]);
        }
        xef[i * 4] = e0; xef[i * 4 + 1] = e1; xef[i * 4 + 2] = e2;
    }
    __syncthreads();

    {
        const float4* W1s4 = reinterpret_cast<const float4*>(W1s);
        const float4* b4 = reinterpret_cast<const float4*>(b1s);
        const float4* sc4 = reinterpret_cast<const float4*>(sc1s);
        const float4* sh4 = reinterpret_cast<const float4*>(sh1s);
        for (int i = tid; i < 2048; i += 256) {
            int cg = i & 15, nl = i >> 4;
            int m = n0 + nl, j = m % 25;
            float dj = dinvf(j);
            float cm = (j > 0) ? dinvf(j - 1) : 0.f;
            float cp = (j < 24) ? dinvf(j + 1) : 0.f;
            float4 w0 = W1s4[cg], w1 = W1s4[16 + cg], w2 = W1s4[32 + cg];
            float4 bb = b4[cg], sv = sc4[cg], hs = sh4[cg];
            float4 h[3];
#pragma unroll
            for (int d = 0; d < 3; d++) {
                float e0 = xef[(nl + d) * 4], e1 = xef[(nl + d) * 4 + 1],
                      e2 = xef[(nl + d) * 4 + 2];
                float4 z;
                z.x = e0 * w0.x + e1 * w1.x + e2 * w2.x + bb.x;
                z.y = e0 * w0.y + e1 * w1.y + e2 * w2.y + bb.y;
                z.z = e0 * w0.z + e1 * w1.z + e2 * w2.z + bb.z;
                z.w = e0 * w0.w + e1 * w1.w + e2 * w2.w + bb.w;
                h[d].x = lrelu(fmaf(z.x, sv.x, hs.x));
                h[d].y = lrelu(fmaf(z.y, sv.y, hs.y));
                h[d].z = lrelu(fmaf(z.z, sv.z, hs.z));
                h[d].w = lrelu(fmaf(z.w, sv.w, hs.w));
            }
            float4 v;
            v.x = dj * (dj * h[1].x + cm * h[0].x + cp * h[2].x);
            v.y = dj * (dj * h[1].y + cm * h[0].y + cp * h[2].y);
            v.z = dj * (dj * h[1].z + cm * h[0].z + cp * h[2].z);
            v.w = dj * (dj * h[1].w + cm * h[0].w + cp * h[2].w);
            __nv_bfloat16 hx = __float2bfloat16(v.x), hy = __float2bfloat16(v.y);
            __nv_bfloat16 hz = __float2bfloat16(v.z), hw = __float2bfloat16(v.w);
            __nv_bfloat16 lx = __float2bfloat16(v.x - __bfloat162float(hx));
            __nv_bfloat16 ly = __float2bfloat16(v.y - __bfloat162float(hy));
            __nv_bfloat16 lz = __float2bfloat16(v.z - __bfloat162float(hz));
            __nv_bfloat16 lw = __float2bfloat16(v.w - __bfloat162float(hw));
            int di = nl * G2S + cg * 4;
            *reinterpret_cast<__nv_bfloat162*>(Ahi + di)     = __halves2bfloat162(hx, hy);
            *reinterpret_cast<__nv_bfloat162*>(Ahi + di + 2) = __halves2bfloat162(hz, hw);
            *reinterpret_cast<__nv_bfloat162*>(Alo + di)     = __halves2bfloat162(lx, ly);
            *reinterpret_cast<__nv_bfloat162*>(Alo + di + 2) = __halves2bfloat162(lz, lw);
        }
    }
    __syncthreads();

    int wm = wid & 3, wn = wid >> 2;
    float acc[2][4][4];
#pragma unroll
    for (int mt = 0; mt < 2; mt++)
#pragma unroll
        for (int nt = 0; nt < 4; nt++)
#pragma unroll
            for (int u = 0; u < 4; u++) acc[mt][nt][u] = 0.f;

#pragma unroll
    for (int kt = 0; kt < 4; kt++) {
        uint32_t ahi[2][4], alo[2][4], bhi[4][2], blo[4][2];
        int abase = (wm * 32 + (lane >> 2)) * G2S + (lane & 3) * 2 + kt * 16;
#pragma unroll
        for (int mt = 0; mt < 2; mt++) {
            int o = abase + mt * 16 * G2S;
            ahi[mt][0] = *reinterpret_cast<const uint32_t*>(Ahi + o);
            ahi[mt][1] = *reinterpret_cast<const uint32_t*>(Ahi + o + 8 * G2S);
            ahi[mt][2] = *reinterpret_cast<const uint32_t*>(Ahi + o + 8);
            ahi[mt][3] = *reinterpret_cast<const uint32_t*>(Ahi + o + 8 * G2S + 8);
            alo[mt][0] = *reinterpret_cast<const uint32_t*>(Alo + o);
            alo[mt][1] = *reinterpret_cast<const uint32_t*>(Alo + o + 8 * G2S);
            alo[mt][2] = *reinterpret_cast<const uint32_t*>(Alo + o + 8);
            alo[mt][3] = *reinterpret_cast<const uint32_t*>(Alo + o + 8 * G2S + 8);
        }
        int bbase = (wn * 32 + (lane >> 2)) * G2S + (lane & 3) * 2 + kt * 16;
#pragma unroll
        for (int nt = 0; nt < 4; nt++) {
            int o = bbase + nt * 8 * G2S;
            bhi[nt][0] = *reinterpret_cast<const uint32_t*>(Bhi + o);
            bhi[nt][1] = *reinterpret_cast<const uint32_t*>(Bhi + o + 8);
            blo[nt][0] = *reinterpret_cast<const uint32_t*>(Blo + o);
            blo[nt][1] = *reinterpret_cast<const uint32_t*>(Blo + o + 8);
        }
#pragma unroll
        for (int nt = 0; nt < 4; nt++) {
            MMA_BF16(acc[0][nt], ahi[0], bhi[nt][0], bhi[nt][1]);
            MMA_BF16(acc[1][nt], ahi[1], bhi[nt][0], bhi[nt][1]);
        }
#pragma unroll
        for (int nt = 0; nt < 4; nt++) {
            MMA_BF16(acc[0][nt], ahi[0], blo[nt][0], blo[nt][1]);
            MMA_BF16(acc[1][nt], ahi[1], blo[nt][0], blo[nt][1]);
        }
#pragma unroll
        for (int nt = 0; nt < 4; nt++) {
            MMA_BF16(acc[0][nt], alo[0], bhi[nt][0], bhi[nt][1]);
            MMA_BF16(acc[1][nt], alo[1], bhi[nt][0], bhi[nt][1]);
        }
    }

#pragma unroll
    for (int nt = 0; nt < 4; nt++) {
        int c0 = wn * 32 + nt * 8 + ((lane & 3) << 1);
        float bb0 = b2s[c0], bb1 = b2s[c0 + 1];
        float s0 = 0.f, q0 = 0.f, s1 = 0.f, q1 = 0.f;
#pragma unroll
        for (int mt = 0; mt < 2; mt++) {
            int row = n0 + wm * 32 + mt * 16 + (lane >> 2);
            float u0 = acc[mt][nt][0] + bb0, u1 = acc[mt][nt][1] + bb1;
            float u2 = acc[mt][nt][2] + bb0, u3 = acc[mt][nt][3] + bb1;
            *reinterpret_cast<float2*>(z2b + (size_t)row * 64 + c0) = make_float2(u0, u1);
            *reinterpret_cast<float2*>(z2b + (size_t)(row + 8) * 64 + c0) = make_float2(u2, u3);
            s0 += u0 + u2; q0 += u0 * u0 + u2 * u2;
            s1 += u1 + u3; q1 += u1 * u1 + u3 * u3;
        }
#pragma unroll
        for (int o = 4; o < 32; o <<= 1) {
            s0 += __shfl_xor_sync(0xffffffffu, s0, o);
            q0 += __shfl_xor_sync(0xffffffffu, q0, o);
            s1 += __shfl_xor_sync(0xffffffffu, s1, o);
            q1 += __shfl_xor_sync(0xffffffffu, q1, o);
        }
        if (lane < 4) {
            redS[c0 * 4 + wm] = s0; redS[(c0 + 1) * 4 + wm] = s1;
            redQ[c0 * 4 + wm] = q0; redQ[(c0 + 1) * 4 + wm] = q1;
        }
    }
    __syncthreads();
    if (tid < 64) {
        float S = redS[tid * 4] + redS[tid * 4 + 1] + redS[tid * 4 + 2] + redS[tid * 4 + 3];
        float Q = redQ[tid * 4] + redQ[tid * 4 + 1] + redQ[tid * 4 + 2] + redQ[tid * 4 + 3];
        part[tid * 3200 + blockIdx.x] = S;
        part[204800 + tid * 3200 + blockIdx.x] = Q;
    }
}

// ---------------------------------------------------------------------------
// K2b: z2 convert — BN2+LReLU+bf16 split. (unchanged)
// ---------------------------------------------------------------------------
__global__ __launch_bounds__(256) void z2convert(
    const float* __restrict__ z2, const float* __restrict__ sc,
    const float* __restrict__ sh, __nv_bfloat16* __restrict__ zhi,
    __nv_bfloat16* __restrict__ zlo) {
    __shared__ float scs[64], shs[64];
    int tid = threadIdx.x;
    if (tid < 64) { scs[tid] = sc[tid]; shs[tid] = sh[tid]; }
    __syncthreads();
    size_t base = (size_t)blockIdx.x * 1024 + tid * 4;
    int c = (tid * 4) & 63;
    float4 v = *reinterpret_cast<const float4*>(z2 + base);
    v.x = lrelu(fmaf(v.x, scs[c],     shs[c]));
    v.y = lrelu(fmaf(v.y, scs[c + 1], shs[c + 1]));
    v.z = lrelu(fmaf(v.z, scs[c + 2], shs[c + 2]));
    v.w = lrelu(fmaf(v.w, scs[c + 3], shs[c + 3]));
    __nv_bfloat16 hx = __float2bfloat16(v.x), hy = __float2bfloat16(v.y);
    __nv_bfloat16 hz = __float2bfloat16(v.z), hw = __float2bfloat16(v.w);
    __nv_bfloat16 lx = __float2bfloat16(v.x - __bfloat162float(hx));
    __nv_bfloat16 ly = __float2bfloat16(v.y - __bfloat162float(hy));
    __nv_bfloat16 lz = __float2bfloat16(v.z - __bfloat162float(hz));
    __nv_bfloat16 lw = __float2bfloat16(v.w - __bfloat162float(hw));
    *reinterpret_cast<__nv_bfloat162*>(zhi + base)     = __halves2bfloat162(hx, hy);
    *reinterpret_cast<__nv_bfloat162*>(zhi + base + 2) = __halves2bfloat162(hz, hw);
    *reinterpret_cast<__nv_bfloat162*>(zlo + base)     = __halves2bfloat162(lx, ly);
    *reinterpret_cast<__nv_bfloat162*>(zlo + base + 2) = __halves2bfloat162(lz, lw);
}

// ---------------------------------------------------------------------------
// K3: conv1 fused with shift-add. Grid 128; block = 128 frames (half batch).
// A tile = 130 rows (halo +-1; invalid edge row zero-filled), taps = A-row
// shifts accumulating into one 128x128 output; direct w1out + fused stats.
// Smem per stage: A 2*5200 + B 2*15360 bf16 = 82240 B; 2 stages = 164480 B.
// ---------------------------------------------------------------------------
#define AROWS 5200                                  // 130*40 bf16
#define BROWS 15360                                 // 384*40 bf16
#define STAGEE (2 * AROWS + 2 * BROWS)              // bf16 elems per stage
#define CF_BYTES (2 * STAGEE * 2)                   // 164480

__global__ __launch_bounds__(256) void conv1_fused(
    const __nv_bfloat16* __restrict__ zhi, const __nv_bfloat16* __restrict__ zlo,
    const __nv_bfloat16* __restrict__ wwhi, const __nv_bfloat16* __restrict__ wwlo,
    const float* __restrict__ cb1, float* __restrict__ w1o,
    float* __restrict__ part) {
    extern __shared__ __align__(16) char dynraw[];
    __nv_bfloat16* sm = reinterpret_cast<__nv_bfloat16*>(dynraw);
    int tid = threadIdx.x, lane = tid & 31, wid = tid >> 5;
    int wm = wid & 3, wn = wid >> 2;
    int m0 = blockIdx.x * 128;                       // first output frame-node
    int bidx = m0 >> 8;                              // batch
    int f0g = m0 & 255;                              // 0 or 128
    int zr = (f0g == 0) ? 0 : 129;                   // invalid halo row
    int mA0 = m0 - 1;                                // global row of tile row 0

    float acc[2][8][4];
#pragma unroll
    for (int mt = 0; mt < 2; mt++)
#pragma unroll
        for (int nt = 0; nt < 8; nt++)
#pragma unroll
            for (int u = 0; u < 4; u++) acc[mt][nt][u] = 0.f;

#define LOADAB(bufi, step) do { \
        int ci0_ = (step) * 32; \
        __nv_bfloat16* Ah_ = sm + (bufi) * STAGEE; \
        __nv_bfloat16* Al_ = Ah_ + AROWS; \
        __nv_bfloat16* Bh_ = Al_ + AROWS; \
        __nv_bfloat16* Bl_ = Bh_ + BROWS; \
        if (tid < 16) { \
            __nv_bfloat16* zd = (tid < 8 ? Ah_ : Al_) + zr * 40 + (tid & 7) * 4; \
            *reinterpret_cast<float2*>(zd) = make_float2(0.f, 0.f); \
        } \
        _Pragma("unroll") \
        for (int u = 0; u < 5; u++) { \
            int fi = u * 256 + tid; \
            if (fi < 1040) { \
                int sel = fi >= 520; \
                int rem = sel ? fi - 520 : fi; \
                int row = rem >> 2, gg = rem & 3; \
                if (row != zr) { \
                    const __nv_bfloat16* src = (sel ? zlo : zhi) + \
                        (size_t)(mA0 + row) * KCI + ci0_ + gg * 8; \
                    __nv_bfloat16* dst = (sel ? Al_ : Ah_) + row * 40 + gg * 8; \
                    cp_async16((uint32_t)__cvta_generic_to_shared(dst), src); \
                } \
            } \
        } \
        _Pragma("unroll") \
        for (int u = 0; u < 12; u++) { \
            int fi = u * 256 + tid; \
            int sel = fi >= 1536; \
            int rem = sel ? fi - 1536 : fi; \
            int row = rem >> 2, gg = rem & 3; \
            const __nv_bfloat16* src = (sel ? wwlo : wwhi) + \
                (size_t)row * KCI + ci0_ + gg * 8; \
            __nv_bfloat16* dst = (sel ? Bl_ : Bh_) + row * 40 + gg * 8; \
            cp_async16((uint32_t)__cvta_generic_to_shared(dst), src); \
        } \
        asm volatile("cp.async.commit_group;" ::: "memory"); \
    } while (0)

    LOADAB(0, 0);

    for (int i = 0; i < 50; i++) {
        int buf = i & 1;
        asm volatile("cp.async.wait_group 0;" ::: "memory");
        __syncthreads();
        if (i < 49) LOADAB(buf ^ 1, i + 1);

        const __nv_bfloat16* Ah = sm + buf * STAGEE;
        const __nv_bfloat16* Al = Ah + AROWS;
        const __nv_bfloat16* Bh = Al + AROWS;
        const __nv_bfloat16* Bl = Bh + BROWS;
#pragma unroll
        for (int kt = 0; kt < 2; kt++) {
#pragma unroll
            for (int tap = 0; tap < 3; tap++) {
                uint32_t ahi[2][4], alo[2][4], bhi[8][2], blo[8][2];
                int abase = (wm * 32 + tap + (lane >> 2)) * 40 + (lane & 3) * 2 + kt * 16;
#pragma unroll
                for (int mt = 0; mt < 2; mt++) {
                    int o = abase + mt * 640;
                    ahi[mt][0] = *reinterpret_cast<const uint32_t*>(Ah + o);
                    ahi[mt][1] = *reinterpret_cast<const uint32_t*>(Ah + o + 320);
                    ahi[mt][2] = *reinterpret_cast<const uint32_t*>(Ah + o + 8);
                    ahi[mt][3] = *reinterpret_cast<const uint32_t*>(Ah + o + 328);
                    alo[mt][0] = *reinterpret_cast<const uint32_t*>(Al + o);
                    alo[mt][1] = *reinterpret_cast<const uint32_t*>(Al + o + 320);
                    alo[mt][2] = *reinterpret_cast<const uint32_t*>(Al + o + 8);
                    alo[mt][3] = *reinterpret_cast<const uint32_t*>(Al + o + 328);
                }
                int bbase = (tap * 128 + wn * 64 + (lane >> 2)) * 40 + (lane & 3) * 2 + kt * 16;
#pragma unroll
                for (int nt = 0; nt < 8; nt++) {
                    int o = bbase + nt * 320;
                    bhi[nt][0] = *reinterpret_cast<const uint32_t*>(Bh + o);
                    bhi[nt][1] = *reinterpret_cast<const uint32_t*>(Bh + o + 8);
                    blo[nt][0] = *reinterpret_cast<const uint32_t*>(Bl + o);
                    blo[nt][1] = *reinterpret_cast<const uint32_t*>(Bl + o + 8);
                }
#pragma unroll
                for (int nt = 0; nt < 8; nt++) {
                    MMA_BF16(acc[0][nt], ahi[0], bhi[nt][0], bhi[nt][1]);
                    MMA_BF16(acc[1][nt], ahi[1], bhi[nt][0], bhi[nt][1]);
                }
#pragma unroll
                for (int nt = 0; nt < 8; nt++) {
                    MMA_BF16(acc[0][nt], ahi[0], blo[nt][0], blo[nt][1]);
                    MMA_BF16(acc[1][nt], ahi[1], blo[nt][0], blo[nt][1]);
                }
#pragma unroll
                for (int nt = 0; nt < 8; nt++) {
                    MMA_BF16(acc[0][nt], alo[0], bhi[nt][0], bhi[nt][1]);
                    MMA_BF16(acc[1][nt], alo[1], bhi[nt][0], bhi[nt][1]);
                }
            }
        }
    }

    // Epilogue: bias, stage transposed tile T[o][fo], coalesced write + stats.
    __syncthreads();
    float* T = reinterpret_cast<float*>(sm);         // 128 x 132
#pragma unroll
    for (int mt = 0; mt < 2; mt++)
#pragma unroll
        for (int nt = 0; nt < 8; nt++)
#pragma unroll
            for (int u = 0; u < 4; u++) {
                int fo = wm * 32 + mt * 16 + (lane >> 2) + ((u >> 1) ? 8 : 0);
                int o = wn * 64 + nt * 8 + ((lane & 3) << 1) + (u & 1);
                T[o * 132 + fo] = acc[mt][nt][u] + __ldg(cb1 + o);
            }
    __syncthreads();
    for (int i = tid; i < 4096; i += 256) {
        int o = i >> 5, f4 = i & 31;
        float4 v = *reinterpret_cast<const float4*>(T + o * 132 + f4 * 4);
        *reinterpret_cast<float4*>(
            w1o + (size_t)(bidx * 128 + o) * 256 + f0g + f4 * 4) = v;
    }
    if (tid < 128) {
        float S = 0.f, Q = 0.f;
#pragma unroll 8
        for (int k = 0; k < 128; k++) {
            float v = T[tid * 132 + k];
            S += v; Q += v * v;
        }
        part[tid * 128 + blockIdx.x] = S;
        part[16384 + tid * 128 + blockIdx.x] = Q;
    }
#undef LOADAB
}

// ---------------------------------------------------------------------------
// K6: Conv2 (1x1, 128->64) with bnC1+lrelu fused at load + partial stats.
// ---------------------------------------------------------------------------
__global__ __launch_bounds__(256) void conv2_kernel(
    const float* __restrict__ w1o, const float* __restrict__ cw2,
    const float* __restrict__ cb2, const float* __restrict__ sc,
    const float* __restrict__ sh, float* __restrict__ vout,
    float* __restrict__ part) {
    __shared__ __align__(16) float Us[64 * 64];
    __shared__ __align__(16) float Ws2[64 * 64];
    int tid = threadIdx.x;
    int b = blockIdx.y;
    int f0 = blockIdx.x * 64;
    int fth = tid & 15, oth = tid >> 4;
    float acc[4][4] = {};

    for (int ci0 = 0; ci0 < 128; ci0 += 64) {
        for (int i = tid; i < 4096; i += 256) {
            int cc = i >> 6, ffi = i & 63;
            float raw = w1o[(size_t)(b * 128 + ci0 + cc) * 256 + f0 + ffi];
            float v = fmaf(raw, __ldg(sc + ci0 + cc), __ldg(sh + ci0 + cc));
            Us[i] = lrelu(v);
        }
        for (int i = tid; i < 4096; i += 256) {
            int o = i & 63, cc = i >> 6;
            Ws2[cc * 64 + o] = cw2[o * 128 + ci0 + cc];
        }
        __syncthreads();
#pragma unroll 8
        for (int cc = 0; cc < 64; cc++) {
            float4 iv = *reinterpret_cast<const float4*>(Us + cc * 64 + fth * 4);
            float4 wv = *reinterpret_cast<const float4*>(Ws2 + cc * 64 + oth * 4);
            acc[0][0] = fmaf(wv.x, iv.x, acc[0][0]); acc[0][1] = fmaf(wv.x, iv.y, acc[0][1]);
            acc[0][2] = fmaf(wv.x, iv.z, acc[0][2]); acc[0][3] = fmaf(wv.x, iv.w, acc[0][3]);
            acc[1][0] = fmaf(wv.y, iv.x, acc[1][0]); acc[1][1] = fmaf(wv.y, iv.y, acc[1][1]);
            acc[1][2] = fmaf(wv.y, iv.z, acc[1][2]); acc[1][3] = fmaf(wv.y, iv.w, acc[1][3]);
            acc[2][0] = fmaf(wv.z, iv.x, acc[2][0]); acc[2][1] = fmaf(wv.z, iv.y, acc[2][1]);
            acc[2][2] = fmaf(wv.z, iv.z, acc[2][2]); acc[2][3] = fmaf(wv.z, iv.w, acc[2][3]);
            acc[3][0] = fmaf(wv.w, iv.x, acc[3][0]); acc[3][1] = fmaf(wv.w, iv.y, acc[3][1]);
            acc[3][2] = fmaf(wv.w, iv.z, acc[3][2]); acc[3][3] = fmaf(wv.w, iv.w, acc[3][3]);
        }
        __syncthreads();
    }

    float* reds = Us;
    float* redq = Ws2;
#pragma unroll
    for (int i = 0; i < 4; i++) {
        int o = oth * 4 + i;
        float bias = __ldg(cb2 + o);
        float s = 0.f, q = 0.f;
#pragma unroll
        for (int j2 = 0; j2 < 4; j2++) {
            float r = acc[i][j2] + bias;
            vout[(size_t)(b * 64 + o) * 256 + f0 + fth * 4 + j2] = r;
            s += r; q += r * r;
        }
        reds[o * 17 + fth] = s;
        redq[o * 17 + fth] = q;
    }
    __syncthreads();
    if (tid < 64) {
        float S = 0.f, Q = 0.f;
#pragma unroll
        for (int t = 0; t < 16; t++) { S += reds[tid * 17 + t]; Q += redq[tid * 17 + t]; }
        int blk = blockIdx.y * 4 + blockIdx.x;
        part[tid * 256 + blk] = S;
        part[16384 + tid * 256 + blk] = Q;
    }
}

// ---------------------------------------------------------------------------
// K7: final BN + LReLU + transpose (B,64,256) -> (B,256,64)
// ---------------------------------------------------------------------------
__global__ __launch_bounds__(256) void final_kernel(
    const float* __restrict__ v, const float* __restrict__ sc,
    const float* __restrict__ sh, float* __restrict__ out) {
    __shared__ float s[64 * 65];
    int tid = threadIdx.x;
    int b = blockIdx.y;
    int f0 = blockIdx.x * 64;
    for (int i = tid; i < 4096; i += 256) {
        int o = i >> 6, ffi = i & 63;
        s[o * 65 + ffi] = v[(size_t)(b * 64 + o) * 256 + f0 + ffi];
    }
    __syncthreads();
    for (int i = tid; i < 4096; i += 256) {
        int ffi = i >> 6, o = i & 63;
        float val = fmaf(s[o * 65 + ffi], __ldg(sc + o), __ldg(sh + o));
        out[(size_t)(b * 256 + f0 + ffi) * 64 + o] = lrelu(val);
    }
}

// ---------------------------------------------------------------------------
// Launch
// ---------------------------------------------------------------------------
extern "C" void kernel_launch(void* const* d_in, const int* in_sizes, int n_in,
                              void* d_out, int out_size) {
    const float* x   = (const float*)d_in[0];
    const float* W1  = (const float*)d_in[4];
    const float* b1  = (const float*)d_in[5];
    const float* g1  = (const float*)d_in[6];
    const float* be1 = (const float*)d_in[7];
    const float* W2  = (const float*)d_in[8];
    const float* b2  = (const float*)d_in[9];
    const float* g2  = (const float*)d_in[10];
    const float* be2 = (const float*)d_in[11];
    const float* cw1 = (const float*)d_in[12];
    const float* cb1 = (const float*)d_in[13];
    const float* cg1 = (const float*)d_in[14];
    const float* cbe1= (const float*)d_in[15];
    const float* cw2 = (const float*)d_in[16];
    const float* cb2 = (const float*)d_in[17];
    const float* cg2 = (const float*)d_in[18];
    const float* cbe2= (const float*)d_in[19];
    float* out = (float*)d_out;

    float *z2, *w1o, *v, *p1, *p2, *pC1, *pC2;
    __nv_bfloat16 *zhi, *zlo, *whi, *wlo, *w2h, *w2l;
    float *s1, *h1, *s2, *h2, *sC1, *hC1, *sC2, *hC2;
    cudaGetSymbolAddress((void**)&z2,  g_z2);
    cudaGetSymbolAddress((void**)&zhi, g_zhi);
    cudaGetSymbolAddress((void**)&zlo, g_zlo);
    cudaGetSymbolAddress((void**)&whi, g_wwhi);
    cudaGetSymbolAddress((void**)&wlo, g_wwlo);
    cudaGetSymbolAddress((void**)&w2h, g_w2hb);
    cudaGetSymbolAddress((void**)&w2l, g_w2lb);
    cudaGetSymbolAddress((void**)&w1o, g_w1out);
    cudaGetSymbolAddress((void**)&v,   g_v);
    cudaGetSymbolAddress((void**)&p1,  g_p1);
    cudaGetSymbolAddress((void**)&p2,  g_p2);
    cudaGetSymbolAddress((void**)&pC1, g_pC1);
    cudaGetSymbolAddress((void**)&pC2, g_pC2);
    cudaGetSymbolAddress((void**)&s1,  g_scale1);
    cudaGetSymbolAddress((void**)&h1,  g_shift1);
    cudaGetSymbolAddress((void**)&s2,  g_scale2);
    cudaGetSymbolAddress((void**)&h2,  g_shift2);
    cudaGetSymbolAddress((void**)&sC1, g_scaleC1);
    cudaGetSymbolAddress((void**)&hC1, g_shiftC1);
    cudaGetSymbolAddress((void**)&sC2, g_scaleC2);
    cudaGetSymbolAddress((void**)&hC2, g_shiftC2);

    cudaFuncSetAttribute(conv1_fused, cudaFuncAttributeMaxDynamicSharedMemorySize, CF_BYTES);
    cudaFuncSetAttribute(gcn2_mma,   cudaFuncAttributeMaxDynamicSharedMemorySize, G2_BYTES);

    const float invN_nodes = 1.f / (float)NNODES;
    const float invN_bf    = 1.f / (float)(BB * FF);

    prep_stats<<<3440, 256>>>(cw1, W2, x, W1, b1, whi, wlo, w2h, w2l, p1);     // 0
    bn_final<<<64, 256>>>(p1, 1024, 64, g1, be1, invN_nodes, s1, h1);          // 1
    gcn2_mma<<<3200, 256, G2_BYTES>>>(x, W1, b1, s1, h1, w2h, w2l, b2, p2, z2);// 2
    bn_final<<<64, 256>>>(p2, 3200, 64, g2, be2, invN_nodes, s2, h2);          // 3
    z2convert<<<25600, 256>>>(z2, s2, h2, zhi, zlo);                           // 4
    conv1_fused<<<128, 256, CF_BYTES>>>(zhi, zlo, whi, wlo, cb1, w1o, pC1);    // 5
    bn_final<<<128, 256>>>(pC1, 128, 128, cg1, cbe1, invN_bf, sC1, hC1);       // 6
    conv2_kernel<<<dim3(4, BB), 256>>>(w1o, cw2, cb2, sC1, hC1, v, pC2);       // 7
    bn_final<<<64, 256>>>(pC2, 256, 64, cg2, cbe2, invN_bf, sC2, hC2);         // 8
    final_kernel<<<dim3(4, BB), 256>>>(v, sC2, hC2, out);                      // 9
}